// round 1
// baseline (speedup 1.0000x reference)
#include <cuda_runtime.h>

#define NN   100000
#define EE   1600000
#define RR   500
#define DDIM 128
#define HH   8
#define DHH  16
#define DFFN 512
#define HOPS 5
#define ALPHA 0.15f
#define SLOPE 0.2f
#define LNEPS 1e-5f

// ---------------- scratch (static device globals; no allocation) -------------
__device__ float g_h[NN * DDIM];        // LN1 output
__device__ float g_feat0[NN * DDIM];    // h @ W_ent
__device__ float g_fA[NN * DDIM];       // ping
__device__ float g_fB[NN * DDIM];       // pong
__device__ float g_eh[NN * HH];
__device__ float g_et[NN * HH];
__device__ float g_er[RR * HH];
__device__ float g_a[EE * HH];          // normalized attention, dst-sorted edge order
__device__ int   g_deg[NN];
__device__ int   g_rowptr[NN + 1];
__device__ int   g_cursor[NN];
__device__ int   g_srcs[EE];            // src, sorted by dst
__device__ int   g_ets[EE];             // e_type, sorted by dst

// ---------------- K1: LN1 + feat = h@W_ent + eh/et --------------------------
__global__ void __launch_bounds__(256) k_ln1_feat(
    const float* __restrict__ ent, const float* __restrict__ g1,
    const float* __restrict__ b1, const float* __restrict__ Went,
    const float* __restrict__ ah, const float* __restrict__ at)
{
    __shared__ float sh[32 * 132];   // x -> h tile
    __shared__ float sf[32 * 132];   // feat tile
    const int n0 = blockIdx.x * 32;
    const int tid = threadIdx.x;

    for (int i = tid; i < 32 * 128; i += 256) {
        int r = i >> 7, c = i & 127;
        sh[r * 132 + c] = ent[(n0 + r) * 128 + c];
    }
    __syncthreads();

    // LN per row: warp w handles rows 4w..4w+3
    {
        int w = tid >> 5, lane = tid & 31;
        #pragma unroll
        for (int rr = 0; rr < 4; rr++) {
            int r = w * 4 + rr;
            float s = 0.f, s2 = 0.f;
            #pragma unroll
            for (int k = 0; k < 4; k++) {
                float v = sh[r * 132 + lane + 32 * k];
                s += v; s2 += v * v;
            }
            #pragma unroll
            for (int o = 16; o; o >>= 1) {
                s  += __shfl_xor_sync(0xffffffffu, s, o);
                s2 += __shfl_xor_sync(0xffffffffu, s2, o);
            }
            float mu  = s * (1.f / 128.f);
            float inv = rsqrtf(s2 * (1.f / 128.f) - mu * mu + LNEPS);
            #pragma unroll
            for (int k = 0; k < 4; k++) {
                int c = lane + 32 * k;
                sh[r * 132 + c] = (sh[r * 132 + c] - mu) * inv * g1[c] + b1[c];
            }
        }
    }
    __syncthreads();

    for (int i = tid; i < 32 * 128; i += 256) {
        int r = i >> 7, c = i & 127;
        g_h[(n0 + r) * 128 + c] = sh[r * 132 + c];
    }

    // GEMM 32x128 @ 128x128: thread = 2 rows x 8 cols
    {
        const int ty = tid >> 4;   // 0..15 -> rows 2*ty, 2*ty+1
        const int tx = tid & 15;   // cols tx + 16m
        float acc[2][8];
        #pragma unroll
        for (int a = 0; a < 2; a++)
            #pragma unroll
            for (int m = 0; m < 8; m++) acc[a][m] = 0.f;

        for (int j = 0; j < 128; j++) {
            float y0 = sh[(ty * 2 + 0) * 132 + j];
            float y1 = sh[(ty * 2 + 1) * 132 + j];
            #pragma unroll
            for (int m = 0; m < 8; m++) {
                float wv = Went[j * 128 + tx + 16 * m];
                acc[0][m] += y0 * wv;
                acc[1][m] += y1 * wv;
            }
        }
        #pragma unroll
        for (int rr = 0; rr < 2; rr++)
            #pragma unroll
            for (int m = 0; m < 8; m++) {
                int r = ty * 2 + rr, c = tx + 16 * m;
                sf[r * 132 + c] = acc[rr][m];
                g_feat0[(n0 + r) * 128 + c] = acc[rr][m];
            }
    }
    __syncthreads();

    // eh / et: thread -> (row = tid/8, head = tid%8)
    {
        int r = tid >> 3, hh = tid & 7;
        float se = 0.f, st = 0.f;
        #pragma unroll
        for (int d = 0; d < 16; d++) {
            float f = sf[r * 132 + hh * 16 + d];
            se += f * ah[hh * 16 + d];
            st += f * at[hh * 16 + d];
        }
        g_eh[(n0 + r) * 8 + hh] = se;
        g_et[(n0 + r) * 8 + hh] = st;
    }
}

// ---------------- K2: er per relation ---------------------------------------
__global__ void k_rel(const float* __restrict__ rel,
                      const float* __restrict__ Wrel,
                      const float* __restrict__ ar)
{
    __shared__ float srow[128];
    const int r = blockIdx.x, k = threadIdx.x;
    srow[k] = rel[r * 128 + k];
    __syncthreads();
    float acc = 0.f;
    for (int j = 0; j < 128; j++) acc += srow[j] * Wrel[j * 128 + k];
    float v = acc * ar[k];
    #pragma unroll
    for (int o = 8; o; o >>= 1) v += __shfl_xor_sync(0xffffffffu, v, o);
    if ((k & 15) == 0) g_er[r * 8 + (k >> 4)] = v;
}

// ---------------- CSR build -------------------------------------------------
__global__ void k_zero() {
    int i = blockIdx.x * blockDim.x + threadIdx.x;
    if (i < NN) g_deg[i] = 0;
}

__global__ void k_hist(const int* __restrict__ dst) {
    int e = blockIdx.x * blockDim.x + threadIdx.x;
    if (e < EE) atomicAdd(&g_deg[dst[e]], 1);
}

__global__ void k_scan() {
    __shared__ int sp[1024];
    const int t = threadIdx.x;
    const int beg = t * 98;
    const int end = min(beg + 98, NN);
    int s = 0;
    for (int i = beg; i < end; i++) s += g_deg[i];
    sp[t] = s;
    __syncthreads();
    for (int off = 1; off < 1024; off <<= 1) {
        int v = (t >= off) ? sp[t - off] : 0;
        __syncthreads();
        sp[t] += v;
        __syncthreads();
    }
    int run = sp[t] - s;   // exclusive prefix
    for (int i = beg; i < end; i++) {
        g_rowptr[i] = run;
        g_cursor[i] = run;
        run += g_deg[i];
    }
    if (t == 0) g_rowptr[NN] = EE;
}

__global__ void k_scatter(const int* __restrict__ src,
                          const int* __restrict__ dst,
                          const int* __restrict__ etp)
{
    int e = blockIdx.x * blockDim.x + threadIdx.x;
    if (e < EE) {
        int p = atomicAdd(&g_cursor[dst[e]], 1);
        g_srcs[p] = src[e];
        g_ets[p]  = etp[e];
    }
}

// ---------------- K4: edge softmax (warp per node) --------------------------
__global__ void __launch_bounds__(256) k_soft()
{
    const int wid  = (blockIdx.x * blockDim.x + threadIdx.x) >> 5;
    const int lane = threadIdx.x & 31;
    if (wid >= NN) return;
    const int beg = g_rowptr[wid], end = g_rowptr[wid + 1];

    float etn[8];
    {
        const float4* p = (const float4*)&g_et[wid * 8];
        float4 a0 = p[0], a1 = p[1];
        etn[0]=a0.x; etn[1]=a0.y; etn[2]=a0.z; etn[3]=a0.w;
        etn[4]=a1.x; etn[5]=a1.y; etn[6]=a1.z; etn[7]=a1.w;
    }

    float mx[8];
    #pragma unroll
    for (int h = 0; h < 8; h++) mx[h] = -1e30f;

    for (int p = beg + lane; p < end; p += 32) {
        int s = g_srcs[p], t = g_ets[p];
        float eh8[8], er8[8];
        *(float4*)&eh8[0] = ((const float4*)&g_eh[s * 8])[0];
        *(float4*)&eh8[4] = ((const float4*)&g_eh[s * 8])[1];
        *(float4*)&er8[0] = ((const float4*)&g_er[t * 8])[0];
        *(float4*)&er8[4] = ((const float4*)&g_er[t * 8])[1];
        #pragma unroll
        for (int h = 0; h < 8; h++) {
            float sc = eh8[h] + etn[h] + er8[h];
            sc = sc > 0.f ? sc : SLOPE * sc;
            mx[h] = fmaxf(mx[h], sc);
        }
    }
    #pragma unroll
    for (int o = 16; o; o >>= 1)
        #pragma unroll
        for (int h = 0; h < 8; h++)
            mx[h] = fmaxf(mx[h], __shfl_xor_sync(0xffffffffu, mx[h], o));

    float sm[8];
    #pragma unroll
    for (int h = 0; h < 8; h++) sm[h] = 0.f;

    for (int p = beg + lane; p < end; p += 32) {
        int s = g_srcs[p], t = g_ets[p];
        float eh8[8], er8[8], ex[8];
        *(float4*)&eh8[0] = ((const float4*)&g_eh[s * 8])[0];
        *(float4*)&eh8[4] = ((const float4*)&g_eh[s * 8])[1];
        *(float4*)&er8[0] = ((const float4*)&g_er[t * 8])[0];
        *(float4*)&er8[4] = ((const float4*)&g_er[t * 8])[1];
        #pragma unroll
        for (int h = 0; h < 8; h++) {
            float sc = eh8[h] + etn[h] + er8[h];
            sc = sc > 0.f ? sc : SLOPE * sc;
            ex[h] = __expf(sc - mx[h]);
            sm[h] += ex[h];
        }
        float4 o0 = {ex[0], ex[1], ex[2], ex[3]};
        float4 o1 = {ex[4], ex[5], ex[6], ex[7]};
        ((float4*)&g_a[p * 8])[0] = o0;
        ((float4*)&g_a[p * 8])[1] = o1;
    }
    #pragma unroll
    for (int o = 16; o; o >>= 1)
        #pragma unroll
        for (int h = 0; h < 8; h++)
            sm[h] += __shfl_xor_sync(0xffffffffu, sm[h], o);

    float inv[8];
    #pragma unroll
    for (int h = 0; h < 8; h++) inv[h] = 1.f / sm[h];

    for (int p = beg + lane; p < end; p += 32) {
        float4 a0 = ((float4*)&g_a[p * 8])[0];
        float4 a1 = ((float4*)&g_a[p * 8])[1];
        a0.x *= inv[0]; a0.y *= inv[1]; a0.z *= inv[2]; a0.w *= inv[3];
        a1.x *= inv[4]; a1.y *= inv[5]; a1.z *= inv[6]; a1.w *= inv[7];
        ((float4*)&g_a[p * 8])[0] = a0;
        ((float4*)&g_a[p * 8])[1] = a1;
    }
}

// ---------------- K5: one diffusion hop (warp per node) ---------------------
__global__ void __launch_bounds__(256) k_hop(int hop)
{
    const float4* fin  = (hop == 0) ? (const float4*)g_feat0
                        : ((hop & 1) ? (const float4*)g_fA : (const float4*)g_fB);
    float4* fout = (hop & 1) ? (float4*)g_fB : (float4*)g_fA;

    const int wid  = (blockIdx.x * blockDim.x + threadIdx.x) >> 5;
    const int lane = threadIdx.x & 31;
    if (wid >= NN) return;
    const int beg = g_rowptr[wid], end = g_rowptr[wid + 1];
    const int h = lane >> 2;

    float4 acc = {0.f, 0.f, 0.f, 0.f};
    for (int pb = beg; pb < end; pb += 32) {
        int cnt = min(32, end - pb);
        int sl = (pb + lane < end) ? g_srcs[pb + lane] : 0;
        for (int q = 0; q < cnt; q++) {
            int s = __shfl_sync(0xffffffffu, sl, q);
            float av = __ldg(&g_a[(pb + q) * 8 + h]);
            float4 v = fin[s * 32 + lane];
            acc.x += av * v.x; acc.y += av * v.y;
            acc.z += av * v.z; acc.w += av * v.w;
        }
    }
    float4 f0 = ((const float4*)g_feat0)[wid * 32 + lane];
    float4 o;
    o.x = (1.f - ALPHA) * acc.x + ALPHA * f0.x;
    o.y = (1.f - ALPHA) * acc.y + ALPHA * f0.y;
    o.z = (1.f - ALPHA) * acc.z + ALPHA * f0.z;
    o.w = (1.f - ALPHA) * acc.w + ALPHA * f0.w;
    fout[wid * 32 + lane] = o;
}

// ---------------- K6: residual + LN2 + FFN + residual -----------------------
__global__ void __launch_bounds__(256, 2) k_ffn(
    const float* __restrict__ g2, const float* __restrict__ be2,
    const float* __restrict__ W1, const float* __restrict__ bb1,
    const float* __restrict__ W2, const float* __restrict__ bb2,
    float* __restrict__ out)
{
    extern __shared__ float smem_[];
    float* rst = smem_;               // 32*132
    float* yln = smem_ + 32 * 132;    // 32*132
    float* zbf = smem_ + 2 * 32 * 132;// 32*520
    const int n0 = blockIdx.x * 32;
    const int tid = threadIdx.x;

    for (int i = tid; i < 32 * 128; i += 256) {
        int r = i >> 7, c = i & 127;
        rst[r * 132 + c] = g_fA[(n0 + r) * 128 + c] + g_h[(n0 + r) * 128 + c];
    }
    __syncthreads();

    {
        int w = tid >> 5, lane = tid & 31;
        #pragma unroll
        for (int rr = 0; rr < 4; rr++) {
            int r = w * 4 + rr;
            float s = 0.f, s2 = 0.f;
            #pragma unroll
            for (int k = 0; k < 4; k++) {
                float v = rst[r * 132 + lane + 32 * k];
                s += v; s2 += v * v;
            }
            #pragma unroll
            for (int o = 16; o; o >>= 1) {
                s  += __shfl_xor_sync(0xffffffffu, s, o);
                s2 += __shfl_xor_sync(0xffffffffu, s2, o);
            }
            float mu  = s * (1.f / 128.f);
            float inv = rsqrtf(s2 * (1.f / 128.f) - mu * mu + LNEPS);
            #pragma unroll
            for (int k = 0; k < 4; k++) {
                int c = lane + 32 * k;
                yln[r * 132 + c] = (rst[r * 132 + c] - mu) * inv * g2[c] + be2[c];
            }
        }
    }
    __syncthreads();

    // GEMM1: z[32][512] = relu(y @ W1 + b1), thread = 8 rows x 8 cols
    {
        const int ty = tid >> 6;   // 0..3 -> rows ty*8..+7
        const int tx = tid & 63;   // cols tx + 64m
        float acc[8][8];
        #pragma unroll
        for (int a = 0; a < 8; a++)
            #pragma unroll
            for (int b = 0; b < 8; b++) acc[a][b] = 0.f;

        for (int j = 0; j < 128; j++) {
            float yv[8], wv[8];
            #pragma unroll
            for (int rr = 0; rr < 8; rr++) yv[rr] = yln[(ty * 8 + rr) * 132 + j];
            #pragma unroll
            for (int m = 0; m < 8; m++) wv[m] = W1[j * 512 + tx + 64 * m];
            #pragma unroll
            for (int rr = 0; rr < 8; rr++)
                #pragma unroll
                for (int m = 0; m < 8; m++) acc[rr][m] += yv[rr] * wv[m];
        }
        #pragma unroll
        for (int rr = 0; rr < 8; rr++)
            #pragma unroll
            for (int m = 0; m < 8; m++) {
                int c = tx + 64 * m;
                zbf[(ty * 8 + rr) * 520 + c] = fmaxf(acc[rr][m] + bb1[c], 0.f);
            }
    }
    __syncthreads();

    // GEMM2: out[32][128] = z @ W2 + b2 + rst, thread = 4 rows x 4 cols
    {
        const int ry = tid >> 5;   // 0..7 -> rows ry*4..+3
        const int cx = tid & 31;   // cols cx + 32m
        float acc[4][4];
        #pragma unroll
        for (int a = 0; a < 4; a++)
            #pragma unroll
            for (int b = 0; b < 4; b++) acc[a][b] = 0.f;

        for (int j = 0; j < 512; j++) {
            float zv[4], wv[4];
            #pragma unroll
            for (int rr = 0; rr < 4; rr++) zv[rr] = zbf[(ry * 4 + rr) * 520 + j];
            #pragma unroll
            for (int m = 0; m < 4; m++) wv[m] = W2[j * 128 + cx + 32 * m];
            #pragma unroll
            for (int rr = 0; rr < 4; rr++)
                #pragma unroll
                for (int m = 0; m < 4; m++) acc[rr][m] += zv[rr] * wv[m];
        }
        #pragma unroll
        for (int rr = 0; rr < 4; rr++)
            #pragma unroll
            for (int m = 0; m < 4; m++) {
                int r = ry * 4 + rr, c = cx + 32 * m;
                out[(n0 + r) * 128 + c] = acc[rr][m] + bb2[c] + rst[r * 132 + c];
            }
    }
}

// ---------------- launch ----------------------------------------------------
extern "C" void kernel_launch(void* const* d_in, const int* in_sizes, int n_in,
                              void* d_out, int out_size)
{
    const float* ent   = (const float*)d_in[0];
    const float* rel   = (const float*)d_in[1];
    const int*   src   = (const int*)  d_in[2];
    const int*   dst   = (const int*)  d_in[3];
    const int*   etp   = (const int*)  d_in[4];
    const float* ln1g  = (const float*)d_in[5];
    const float* ln1b  = (const float*)d_in[6];
    const float* Went  = (const float*)d_in[7];
    const float* Wrel  = (const float*)d_in[8];
    const float* ah    = (const float*)d_in[9];
    const float* at    = (const float*)d_in[10];
    const float* ar    = (const float*)d_in[11];
    const float* ln2g  = (const float*)d_in[12];
    const float* ln2b  = (const float*)d_in[13];
    const float* W1    = (const float*)d_in[14];
    const float* b1    = (const float*)d_in[15];
    const float* W2    = (const float*)d_in[16];
    const float* b2    = (const float*)d_in[17];
    float* out = (float*)d_out;

    static const size_t FFN_SMEM = (2 * 32 * 132 + 32 * 520) * sizeof(float); // 100352
    cudaFuncSetAttribute(k_ffn, cudaFuncAttributeMaxDynamicSharedMemorySize, (int)FFN_SMEM);

    // CSR build
    k_zero<<<(NN + 255) / 256, 256>>>();
    k_hist<<<EE / 256, 256>>>(dst);
    k_scan<<<1, 1024>>>();
    k_scatter<<<EE / 256, 256>>>(src, dst, etp);

    // node/relation projections + attention logit pieces
    k_ln1_feat<<<NN / 32, 256>>>(ent, ln1g, ln1b, Went, ah, at);
    k_rel<<<RR, 128>>>(rel, Wrel, ar);

    // edge softmax
    k_soft<<<NN / 8, 256>>>();

    // diffusion
    for (int hop = 0; hop < HOPS; hop++)
        k_hop<<<NN / 8, 256>>>(hop);

    // FFN + residuals
    k_ffn<<<NN / 32, 256, FFN_SMEM>>>(ln2g, ln2b, W1, b1, W2, b2, out);
}

// round 3
// speedup vs baseline: 1.5710x; 1.5710x over previous
#include <cuda_runtime.h>

#define NN   100000
#define EE   1600000
#define RR   500
#define DDIM 128
#define HH   8
#define DHH  16
#define DFFN 512
#define HOPS 5
#define ALPHA 0.15f
#define SLOPE 0.2f
#define LNEPS 1e-5f

// ---------------- scratch (static device globals; no allocation) -------------
__device__ float g_h[NN * DDIM];        // LN1 output
__device__ float g_feat0[NN * DDIM];    // h @ W_ent
__device__ float g_fA[NN * DDIM];       // ping
__device__ float g_fB[NN * DDIM];       // pong
__device__ float g_eh[NN * HH];
__device__ float g_et[NN * HH];
__device__ float g_er[RR * HH];
__device__ float g_a[EE * HH];          // normalized attention, dst-sorted edge order
__device__ int   g_deg[NN];
__device__ int   g_rowptr[NN + 1];
__device__ int   g_cursor[NN];
__device__ int   g_srcs[EE];            // src, sorted by dst
__device__ int   g_ets[EE];             // e_type, sorted by dst
// TF32-prerounded weights
__device__ float g_Wentr[DDIM * DDIM];
__device__ float g_W1r[DDIM * DFFN];
__device__ float g_W2r[DFFN * DDIM];

// ---------------- mma helpers ------------------------------------------------
__device__ __forceinline__ unsigned f2tf(float f) {
    unsigned u;
    asm("cvt.rna.tf32.f32 %0, %1;" : "=r"(u) : "f"(f));
    return u;
}

__device__ __forceinline__ void mma_tf32(float c[4],
    unsigned a0, unsigned a1, unsigned a2, unsigned a3,
    unsigned b0, unsigned b1)
{
    asm volatile(
        "mma.sync.aligned.m16n8k8.row.col.f32.tf32.tf32.f32 "
        "{%0,%1,%2,%3}, {%4,%5,%6,%7}, {%8,%9}, {%0,%1,%2,%3};"
        : "+f"(c[0]), "+f"(c[1]), "+f"(c[2]), "+f"(c[3])
        : "r"(a0), "r"(a1), "r"(a2), "r"(a3), "r"(b0), "r"(b1));
}

// ---------------- K0: preround all weights to tf32 (writes device globals) ---
#define RND_TOTAL (DDIM * DDIM + DDIM * DFFN + DFFN * DDIM)  // 147456
__global__ void k_rnd3(const float* __restrict__ Went,
                       const float* __restrict__ W1,
                       const float* __restrict__ W2)
{
    int i = blockIdx.x * blockDim.x + threadIdx.x;
    if (i < DDIM * DDIM) {
        g_Wentr[i] = __uint_as_float(f2tf(Went[i]));
    } else if (i < DDIM * DDIM + DDIM * DFFN) {
        int j = i - DDIM * DDIM;
        g_W1r[j] = __uint_as_float(f2tf(W1[j]));
    } else if (i < RND_TOTAL) {
        int j = i - DDIM * DDIM - DDIM * DFFN;
        g_W2r[j] = __uint_as_float(f2tf(W2[j]));
    }
}

// ---------------- K1: LN1 + feat = h@W_ent + eh/et (tensor core) -------------
// 64-node tile, 256 threads (8 warps). dyn smem: sh[64*132] + sf[64*132]
__global__ void __launch_bounds__(256) k_ln1_feat(
    const float* __restrict__ ent, const float* __restrict__ g1,
    const float* __restrict__ b1,
    const float* __restrict__ ah, const float* __restrict__ at)
{
    extern __shared__ float smem_[];
    float* sh = smem_;               // 64*132 LN output
    float* sf = smem_ + 64 * 132;    // 64*132 feat tile
    const int n0 = blockIdx.x * 64;
    const int tid = threadIdx.x;
    const int wid = tid >> 5, lane = tid & 31;
    const int group = lane >> 2, tig = lane & 3;

    // load ent tile (clamped rows)
    for (int i = tid; i < 64 * 128; i += 256) {
        int r = i >> 7, c = i & 127;
        int gr = min(n0 + r, NN - 1);
        sh[r * 132 + c] = ent[gr * 128 + c];
    }
    __syncthreads();

    // LN per row: warp w handles rows 8w..8w+7
    #pragma unroll
    for (int rr = 0; rr < 8; rr++) {
        int r = wid * 8 + rr;
        float s = 0.f, s2 = 0.f;
        #pragma unroll
        for (int k = 0; k < 4; k++) {
            float v = sh[r * 132 + lane + 32 * k];
            s += v; s2 += v * v;
        }
        #pragma unroll
        for (int o = 16; o; o >>= 1) {
            s  += __shfl_xor_sync(0xffffffffu, s, o);
            s2 += __shfl_xor_sync(0xffffffffu, s2, o);
        }
        float mu  = s * (1.f / 128.f);
        float inv = rsqrtf(s2 * (1.f / 128.f) - mu * mu + LNEPS);
        #pragma unroll
        for (int k = 0; k < 4; k++) {
            int c = lane + 32 * k;
            sh[r * 132 + c] = (sh[r * 132 + c] - mu) * inv * g1[c] + b1[c];
        }
    }
    __syncthreads();

    // store g_h
    for (int i = tid; i < 64 * 128; i += 256) {
        int r = i >> 7, c = i & 127;
        if (n0 + r < NN) g_h[(n0 + r) * 128 + c] = sh[r * 132 + c];
    }

    // GEMM 64x128 = sh(64x128) @ Went(128x128). warp tile 16x64: m-grid 4, n-grid 2
    {
        const float* Wu = g_Wentr;
        const int m0 = (wid >> 1) * 16;
        const int nw = (wid & 1) * 64;
        float acc[8][4];
        #pragma unroll
        for (int t = 0; t < 8; t++)
            #pragma unroll
            for (int q = 0; q < 4; q++) acc[t][q] = 0.f;

        #pragma unroll
        for (int ks = 0; ks < 16; ks++) {
            int k0 = ks * 8;
            unsigned a0 = f2tf(sh[(m0 + group) * 132 + k0 + tig]);
            unsigned a1 = f2tf(sh[(m0 + group + 8) * 132 + k0 + tig]);
            unsigned a2 = f2tf(sh[(m0 + group) * 132 + k0 + tig + 4]);
            unsigned a3 = f2tf(sh[(m0 + group + 8) * 132 + k0 + tig + 4]);
            #pragma unroll
            for (int nt = 0; nt < 8; nt++) {
                int c = nw + nt * 8 + group;
                unsigned b0 = __float_as_uint(Wu[(k0 + tig) * 128 + c]);
                unsigned b1 = __float_as_uint(Wu[(k0 + tig + 4) * 128 + c]);
                mma_tf32(acc[nt], a0, a1, a2, a3, b0, b1);
            }
        }
        // epilogue -> sf + g_feat0
        #pragma unroll
        for (int nt = 0; nt < 8; nt++) {
            int r = m0 + group;
            int cc = nw + nt * 8 + 2 * tig;
            sf[r * 132 + cc]           = acc[nt][0];
            sf[r * 132 + cc + 1]       = acc[nt][1];
            sf[(r + 8) * 132 + cc]     = acc[nt][2];
            sf[(r + 8) * 132 + cc + 1] = acc[nt][3];
            if (n0 + r < NN) {
                g_feat0[(n0 + r) * 128 + cc]     = acc[nt][0];
                g_feat0[(n0 + r) * 128 + cc + 1] = acc[nt][1];
            }
            if (n0 + r + 8 < NN) {
                g_feat0[(n0 + r + 8) * 128 + cc]     = acc[nt][2];
                g_feat0[(n0 + r + 8) * 128 + cc + 1] = acc[nt][3];
            }
        }
    }
    __syncthreads();

    // eh / et: 64 rows x 8 heads = 512 slots, 2 per thread
    #pragma unroll
    for (int rep = 0; rep < 2; rep++) {
        int i = tid + rep * 256;
        int r = i >> 3, hh = i & 7;
        float se = 0.f, st = 0.f;
        #pragma unroll
        for (int d = 0; d < 16; d++) {
            float f = sf[r * 132 + hh * 16 + d];
            se += f * ah[hh * 16 + d];
            st += f * at[hh * 16 + d];
        }
        if (n0 + r < NN) {
            g_eh[(n0 + r) * 8 + hh] = se;
            g_et[(n0 + r) * 8 + hh] = st;
        }
    }
}

// ---------------- K2: er per relation ---------------------------------------
__global__ void k_rel(const float* __restrict__ rel,
                      const float* __restrict__ Wrel,
                      const float* __restrict__ ar)
{
    __shared__ float srow[128];
    const int r = blockIdx.x, k = threadIdx.x;
    srow[k] = rel[r * 128 + k];
    __syncthreads();
    float acc = 0.f;
    for (int j = 0; j < 128; j++) acc += srow[j] * Wrel[j * 128 + k];
    float v = acc * ar[k];
    #pragma unroll
    for (int o = 8; o; o >>= 1) v += __shfl_xor_sync(0xffffffffu, v, o);
    if ((k & 15) == 0) g_er[r * 8 + (k >> 4)] = v;
}

// ---------------- CSR build -------------------------------------------------
__global__ void k_zero() {
    int i = blockIdx.x * blockDim.x + threadIdx.x;
    if (i < NN) g_deg[i] = 0;
}

__global__ void k_hist(const int* __restrict__ dst) {
    int e = blockIdx.x * blockDim.x + threadIdx.x;
    if (e < EE) atomicAdd(&g_deg[dst[e]], 1);
}

__global__ void k_scan() {
    __shared__ int sp[1024];
    const int t = threadIdx.x;
    const int beg = t * 98;
    const int end = min(beg + 98, NN);
    int s = 0;
    for (int i = beg; i < end; i++) s += g_deg[i];
    sp[t] = s;
    __syncthreads();
    for (int off = 1; off < 1024; off <<= 1) {
        int v = (t >= off) ? sp[t - off] : 0;
        __syncthreads();
        sp[t] += v;
        __syncthreads();
    }
    int run = sp[t] - s;   // exclusive prefix
    for (int i = beg; i < end; i++) {
        g_rowptr[i] = run;
        g_cursor[i] = run;
        run += g_deg[i];
    }
    if (t == 0) g_rowptr[NN] = EE;
}

__global__ void k_scatter(const int* __restrict__ src,
                          const int* __restrict__ dst,
                          const int* __restrict__ etp)
{
    int e = blockIdx.x * blockDim.x + threadIdx.x;
    if (e < EE) {
        int p = atomicAdd(&g_cursor[dst[e]], 1);
        g_srcs[p] = src[e];
        g_ets[p]  = etp[e];
    }
}

// ---------------- K4: edge softmax (warp per node) --------------------------
__global__ void __launch_bounds__(256) k_soft()
{
    const int wid  = (blockIdx.x * blockDim.x + threadIdx.x) >> 5;
    const int lane = threadIdx.x & 31;
    if (wid >= NN) return;
    const int beg = g_rowptr[wid], end = g_rowptr[wid + 1];

    float etn[8];
    {
        const float4* p = (const float4*)&g_et[wid * 8];
        float4 a0 = p[0], a1 = p[1];
        etn[0]=a0.x; etn[1]=a0.y; etn[2]=a0.z; etn[3]=a0.w;
        etn[4]=a1.x; etn[5]=a1.y; etn[6]=a1.z; etn[7]=a1.w;
    }

    float mx[8];
    #pragma unroll
    for (int h = 0; h < 8; h++) mx[h] = -1e30f;

    for (int p = beg + lane; p < end; p += 32) {
        int s = g_srcs[p], t = g_ets[p];
        float eh8[8], er8[8];
        *(float4*)&eh8[0] = ((const float4*)&g_eh[s * 8])[0];
        *(float4*)&eh8[4] = ((const float4*)&g_eh[s * 8])[1];
        *(float4*)&er8[0] = ((const float4*)&g_er[t * 8])[0];
        *(float4*)&er8[4] = ((const float4*)&g_er[t * 8])[1];
        #pragma unroll
        for (int h = 0; h < 8; h++) {
            float sc = eh8[h] + etn[h] + er8[h];
            sc = sc > 0.f ? sc : SLOPE * sc;
            mx[h] = fmaxf(mx[h], sc);
        }
    }
    #pragma unroll
    for (int o = 16; o; o >>= 1)
        #pragma unroll
        for (int h = 0; h < 8; h++)
            mx[h] = fmaxf(mx[h], __shfl_xor_sync(0xffffffffu, mx[h], o));

    float sm[8];
    #pragma unroll
    for (int h = 0; h < 8; h++) sm[h] = 0.f;

    for (int p = beg + lane; p < end; p += 32) {
        int s = g_srcs[p], t = g_ets[p];
        float eh8[8], er8[8], ex[8];
        *(float4*)&eh8[0] = ((const float4*)&g_eh[s * 8])[0];
        *(float4*)&eh8[4] = ((const float4*)&g_eh[s * 8])[1];
        *(float4*)&er8[0] = ((const float4*)&g_er[t * 8])[0];
        *(float4*)&er8[4] = ((const float4*)&g_er[t * 8])[1];
        #pragma unroll
        for (int h = 0; h < 8; h++) {
            float sc = eh8[h] + etn[h] + er8[h];
            sc = sc > 0.f ? sc : SLOPE * sc;
            ex[h] = __expf(sc - mx[h]);
            sm[h] += ex[h];
        }
        float4 o0 = {ex[0], ex[1], ex[2], ex[3]};
        float4 o1 = {ex[4], ex[5], ex[6], ex[7]};
        ((float4*)&g_a[p * 8])[0] = o0;
        ((float4*)&g_a[p * 8])[1] = o1;
    }
    #pragma unroll
    for (int o = 16; o; o >>= 1)
        #pragma unroll
        for (int h = 0; h < 8; h++)
            sm[h] += __shfl_xor_sync(0xffffffffu, sm[h], o);

    float inv[8];
    #pragma unroll
    for (int h = 0; h < 8; h++) inv[h] = 1.f / sm[h];

    for (int p = beg + lane; p < end; p += 32) {
        float4 a0 = ((float4*)&g_a[p * 8])[0];
        float4 a1 = ((float4*)&g_a[p * 8])[1];
        a0.x *= inv[0]; a0.y *= inv[1]; a0.z *= inv[2]; a0.w *= inv[3];
        a1.x *= inv[4]; a1.y *= inv[5]; a1.z *= inv[6]; a1.w *= inv[7];
        ((float4*)&g_a[p * 8])[0] = a0;
        ((float4*)&g_a[p * 8])[1] = a1;
    }
}

// ---------------- K5: one diffusion hop (warp per node) ---------------------
__global__ void __launch_bounds__(256) k_hop(int hop)
{
    const float4* fin  = (hop == 0) ? (const float4*)g_feat0
                        : ((hop & 1) ? (const float4*)g_fA : (const float4*)g_fB);
    float4* fout = (hop & 1) ? (float4*)g_fB : (float4*)g_fA;

    const int wid  = (blockIdx.x * blockDim.x + threadIdx.x) >> 5;
    const int lane = threadIdx.x & 31;
    if (wid >= NN) return;
    const int beg = g_rowptr[wid], end = g_rowptr[wid + 1];
    const int h = lane >> 2;

    float4 acc = {0.f, 0.f, 0.f, 0.f};
    for (int pb = beg; pb < end; pb += 32) {
        int cnt = min(32, end - pb);
        int sl = (pb + lane < end) ? g_srcs[pb + lane] : 0;
        for (int q = 0; q < cnt; q++) {
            int s = __shfl_sync(0xffffffffu, sl, q);
            float av = __ldg(&g_a[(pb + q) * 8 + h]);
            float4 v = fin[s * 32 + lane];
            acc.x += av * v.x; acc.y += av * v.y;
            acc.z += av * v.z; acc.w += av * v.w;
        }
    }
    float4 f0 = ((const float4*)g_feat0)[wid * 32 + lane];
    float4 o;
    o.x = (1.f - ALPHA) * acc.x + ALPHA * f0.x;
    o.y = (1.f - ALPHA) * acc.y + ALPHA * f0.y;
    o.z = (1.f - ALPHA) * acc.z + ALPHA * f0.z;
    o.w = (1.f - ALPHA) * acc.w + ALPHA * f0.w;
    fout[wid * 32 + lane] = o;
}

// ---------------- K6: residual + LN2 + FFN + residual (tensor core) ---------
// 64-node tile, 256 threads (8 warps)
// dyn smem: rst[64*132] + yln[64*132] + z[64*520] = 200704 B
__global__ void __launch_bounds__(256) k_ffn(
    const float* __restrict__ g2, const float* __restrict__ be2,
    const float* __restrict__ bb1, const float* __restrict__ bb2,
    float* __restrict__ out)
{
    extern __shared__ float smem_[];
    float* rst = smem_;                    // 64*132
    float* yln = smem_ + 64 * 132;         // 64*132
    float* z   = smem_ + 2 * 64 * 132;     // 64*520
    const int n0 = blockIdx.x * 64;
    const int tid = threadIdx.x;
    const int wid = tid >> 5, lane = tid & 31;
    const int group = lane >> 2, tig = lane & 3;

    for (int i = tid; i < 64 * 128; i += 256) {
        int r = i >> 7, c = i & 127;
        int gr = min(n0 + r, NN - 1);
        rst[r * 132 + c] = g_fA[gr * 128 + c] + g_h[gr * 128 + c];
    }
    __syncthreads();

    // LN2 (store tf32-rounded y for mma A-operand)
    #pragma unroll
    for (int rr = 0; rr < 8; rr++) {
        int r = wid * 8 + rr;
        float s = 0.f, s2 = 0.f;
        #pragma unroll
        for (int k = 0; k < 4; k++) {
            float v = rst[r * 132 + lane + 32 * k];
            s += v; s2 += v * v;
        }
        #pragma unroll
        for (int o = 16; o; o >>= 1) {
            s  += __shfl_xor_sync(0xffffffffu, s, o);
            s2 += __shfl_xor_sync(0xffffffffu, s2, o);
        }
        float mu  = s * (1.f / 128.f);
        float inv = rsqrtf(s2 * (1.f / 128.f) - mu * mu + LNEPS);
        #pragma unroll
        for (int k = 0; k < 4; k++) {
            int c = lane + 32 * k;
            float y = (rst[r * 132 + c] - mu) * inv * g2[c] + be2[c];
            yln[r * 132 + c] = __uint_as_float(f2tf(y));
        }
    }
    __syncthreads();

    // GEMM1: z(64x512) = relu(y @ W1 + b1). warp tile 32x128: m-grid 2, n-grid 4
    {
        const float* Wu = g_W1r;
        const int m0 = (wid >> 2) * 32;
        const int nw = (wid & 3) * 128;
        float acc[2][16][4];
        #pragma unroll
        for (int mt = 0; mt < 2; mt++)
            #pragma unroll
            for (int nt = 0; nt < 16; nt++)
                #pragma unroll
                for (int q = 0; q < 4; q++) acc[mt][nt][q] = 0.f;

        #pragma unroll
        for (int ks = 0; ks < 16; ks++) {
            int k0 = ks * 8;
            unsigned a[2][4];
            #pragma unroll
            for (int mt = 0; mt < 2; mt++) {
                int rb = m0 + mt * 16 + group;
                a[mt][0] = __float_as_uint(yln[rb * 132 + k0 + tig]);
                a[mt][1] = __float_as_uint(yln[(rb + 8) * 132 + k0 + tig]);
                a[mt][2] = __float_as_uint(yln[rb * 132 + k0 + tig + 4]);
                a[mt][3] = __float_as_uint(yln[(rb + 8) * 132 + k0 + tig + 4]);
            }
            #pragma unroll
            for (int nt = 0; nt < 16; nt++) {
                int c = nw + nt * 8 + group;
                unsigned b0 = __float_as_uint(Wu[(k0 + tig) * 512 + c]);
                unsigned b1 = __float_as_uint(Wu[(k0 + tig + 4) * 512 + c]);
                mma_tf32(acc[0][nt], a[0][0], a[0][1], a[0][2], a[0][3], b0, b1);
                mma_tf32(acc[1][nt], a[1][0], a[1][1], a[1][2], a[1][3], b0, b1);
            }
        }
        #pragma unroll
        for (int mt = 0; mt < 2; mt++)
            #pragma unroll
            for (int nt = 0; nt < 16; nt++) {
                int r  = m0 + mt * 16 + group;
                int cc = nw + nt * 8 + 2 * tig;
                float v0 = fmaxf(acc[mt][nt][0] + bb1[cc], 0.f);
                float v1 = fmaxf(acc[mt][nt][1] + bb1[cc + 1], 0.f);
                float v2 = fmaxf(acc[mt][nt][2] + bb1[cc], 0.f);
                float v3 = fmaxf(acc[mt][nt][3] + bb1[cc + 1], 0.f);
                z[r * 520 + cc]           = __uint_as_float(f2tf(v0));
                z[r * 520 + cc + 1]       = __uint_as_float(f2tf(v1));
                z[(r + 8) * 520 + cc]     = __uint_as_float(f2tf(v2));
                z[(r + 8) * 520 + cc + 1] = __uint_as_float(f2tf(v3));
            }
    }
    __syncthreads();

    // GEMM2: out(64x128) = z @ W2 + b2 + rst. warp tile 16x64: m-grid 4, n-grid 2
    {
        const float* Wu = g_W2r;
        const int m0 = (wid >> 1) * 16;
        const int nw = (wid & 1) * 64;
        float acc[8][4];
        #pragma unroll
        for (int nt = 0; nt < 8; nt++)
            #pragma unroll
            for (int q = 0; q < 4; q++) acc[nt][q] = 0.f;

        #pragma unroll 8
        for (int ks = 0; ks < 64; ks++) {
            int k0 = ks * 8;
            unsigned a0 = __float_as_uint(z[(m0 + group) * 520 + k0 + tig]);
            unsigned a1 = __float_as_uint(z[(m0 + group + 8) * 520 + k0 + tig]);
            unsigned a2 = __float_as_uint(z[(m0 + group) * 520 + k0 + tig + 4]);
            unsigned a3 = __float_as_uint(z[(m0 + group + 8) * 520 + k0 + tig + 4]);
            #pragma unroll
            for (int nt = 0; nt < 8; nt++) {
                int c = nw + nt * 8 + group;
                unsigned b0 = __float_as_uint(Wu[(k0 + tig) * 128 + c]);
                unsigned b1 = __float_as_uint(Wu[(k0 + tig + 4) * 128 + c]);
                mma_tf32(acc[nt], a0, a1, a2, a3, b0, b1);
            }
        }
        #pragma unroll
        for (int nt = 0; nt < 8; nt++) {
            int r  = m0 + group;
            int cc = nw + nt * 8 + 2 * tig;
            if (n0 + r < NN) {
                out[(n0 + r) * 128 + cc]     = acc[nt][0] + bb2[cc]     + rst[r * 132 + cc];
                out[(n0 + r) * 128 + cc + 1] = acc[nt][1] + bb2[cc + 1] + rst[r * 132 + cc + 1];
            }
            if (n0 + r + 8 < NN) {
                out[(n0 + r + 8) * 128 + cc]     = acc[nt][2] + bb2[cc]     + rst[(r + 8) * 132 + cc];
                out[(n0 + r + 8) * 128 + cc + 1] = acc[nt][3] + bb2[cc + 1] + rst[(r + 8) * 132 + cc + 1];
            }
        }
    }
}

// ---------------- launch ----------------------------------------------------
extern "C" void kernel_launch(void* const* d_in, const int* in_sizes, int n_in,
                              void* d_out, int out_size)
{
    const float* ent   = (const float*)d_in[0];
    const float* rel   = (const float*)d_in[1];
    const int*   src   = (const int*)  d_in[2];
    const int*   dst   = (const int*)  d_in[3];
    const int*   etp   = (const int*)  d_in[4];
    const float* ln1g  = (const float*)d_in[5];
    const float* ln1b  = (const float*)d_in[6];
    const float* Went  = (const float*)d_in[7];
    const float* Wrel  = (const float*)d_in[8];
    const float* ah    = (const float*)d_in[9];
    const float* at    = (const float*)d_in[10];
    const float* ar    = (const float*)d_in[11];
    const float* ln2g  = (const float*)d_in[12];
    const float* ln2b  = (const float*)d_in[13];
    const float* W1    = (const float*)d_in[14];
    const float* b1    = (const float*)d_in[15];
    const float* W2    = (const float*)d_in[16];
    const float* b2    = (const float*)d_in[17];
    float* out = (float*)d_out;

    static const size_t LN1_SMEM = (2 * 64 * 132) * sizeof(float);              // 67584
    static const size_t FFN_SMEM = (2 * 64 * 132 + 64 * 520) * sizeof(float);   // 200704
    cudaFuncSetAttribute(k_ln1_feat, cudaFuncAttributeMaxDynamicSharedMemorySize, (int)LN1_SMEM);
    cudaFuncSetAttribute(k_ffn, cudaFuncAttributeMaxDynamicSharedMemorySize, (int)FFN_SMEM);

    // pre-round weights to tf32 (single kernel, writes device globals directly)
    k_rnd3<<<(RND_TOTAL + 255) / 256, 256>>>(Went, W1, W2);

    // CSR build
    k_zero<<<(NN + 255) / 256, 256>>>();
    k_hist<<<EE / 256, 256>>>(dst);
    k_scan<<<1, 1024>>>();
    k_scatter<<<EE / 256, 256>>>(src, dst, etp);

    // node/relation projections + attention logit pieces
    k_ln1_feat<<<(NN + 63) / 64, 256, LN1_SMEM>>>(ent, ln1g, ln1b, ah, at);
    k_rel<<<RR, 128>>>(rel, Wrel, ar);

    // edge softmax
    k_soft<<<NN / 8, 256>>>();

    // diffusion
    for (int hop = 0; hop < HOPS; hop++)
        k_hop<<<NN / 8, 256>>>(hop);

    // FFN + residuals
    k_ffn<<<(NN + 63) / 64, 256, FFN_SMEM>>>(ln2g, ln2b, b1, b2, out);
}

// round 4
// speedup vs baseline: 1.7851x; 1.1363x over previous
#include <cuda_runtime.h>

#define NN   100000
#define EE   1600000
#define RR   500
#define DDIM 128
#define HH   8
#define DHH  16
#define DFFN 512
#define HOPS 5
#define ALPHA 0.15f
#define SLOPE 0.2f
#define LNEPS 1e-5f

#define SCAN_B 256
#define NBLK ((NN + SCAN_B - 1) / SCAN_B)   // 391

// ---------------- scratch (static device globals; no allocation) -------------
__device__ float g_h[NN * DDIM];        // LN1 output
__device__ float g_feat0[NN * DDIM];    // h @ W_ent
__device__ float g_fA[NN * DDIM];       // ping
__device__ float g_fB[NN * DDIM];       // pong
__device__ float g_eh[NN * HH];
__device__ float g_et[NN * HH];
__device__ float g_er[RR * HH];
__device__ float g_a[EE * HH];          // UNnormalized exp scores, dst-sorted order
__device__ float g_inv[NN * HH];        // 1/softmax-sum per (node, head)
__device__ int   g_deg[NN];
__device__ int   g_rowptr[NN + 1];
__device__ int   g_cursor[NN];
__device__ int   g_part[512];           // scan partials
__device__ int   g_srcs[EE];            // src, sorted by dst
__device__ int   g_ets[EE];             // e_type, sorted by dst
// TF32-prerounded weights
__device__ float g_Wentr[DDIM * DDIM];
__device__ float g_W1r[DDIM * DFFN];
__device__ float g_W2r[DFFN * DDIM];

// ---------------- mma helpers ------------------------------------------------
__device__ __forceinline__ unsigned f2tf(float f) {
    unsigned u;
    asm("cvt.rna.tf32.f32 %0, %1;" : "=r"(u) : "f"(f));
    return u;
}

__device__ __forceinline__ void mma_tf32(float c[4],
    unsigned a0, unsigned a1, unsigned a2, unsigned a3,
    unsigned b0, unsigned b1)
{
    asm volatile(
        "mma.sync.aligned.m16n8k8.row.col.f32.tf32.tf32.f32 "
        "{%0,%1,%2,%3}, {%4,%5,%6,%7}, {%8,%9}, {%0,%1,%2,%3};"
        : "+f"(c[0]), "+f"(c[1]), "+f"(c[2]), "+f"(c[3])
        : "r"(a0), "r"(a1), "r"(a2), "r"(a3), "r"(b0), "r"(b1));
}

// ---------------- K0: preround all weights to tf32 ---------------------------
#define RND_TOTAL (DDIM * DDIM + DDIM * DFFN + DFFN * DDIM)  // 147456
__global__ void k_rnd3(const float* __restrict__ Went,
                       const float* __restrict__ W1,
                       const float* __restrict__ W2)
{
    int i = blockIdx.x * blockDim.x + threadIdx.x;
    if (i < DDIM * DDIM) {
        g_Wentr[i] = __uint_as_float(f2tf(Went[i]));
    } else if (i < DDIM * DDIM + DDIM * DFFN) {
        int j = i - DDIM * DDIM;
        g_W1r[j] = __uint_as_float(f2tf(W1[j]));
    } else if (i < RND_TOTAL) {
        int j = i - DDIM * DDIM - DDIM * DFFN;
        g_W2r[j] = __uint_as_float(f2tf(W2[j]));
    }
}

// ---------------- K1: LN1 + feat = h@W_ent + eh/et (tensor core) -------------
__global__ void __launch_bounds__(256) k_ln1_feat(
    const float* __restrict__ ent, const float* __restrict__ g1,
    const float* __restrict__ b1,
    const float* __restrict__ ah, const float* __restrict__ at)
{
    extern __shared__ float smem_[];
    float* sh = smem_;               // 64*132 LN output
    float* sf = smem_ + 64 * 132;    // 64*132 feat tile
    const int n0 = blockIdx.x * 64;
    const int tid = threadIdx.x;
    const int wid = tid >> 5, lane = tid & 31;
    const int group = lane >> 2, tig = lane & 3;

    for (int i = tid; i < 64 * 128; i += 256) {
        int r = i >> 7, c = i & 127;
        int gr = min(n0 + r, NN - 1);
        sh[r * 132 + c] = ent[gr * 128 + c];
    }
    __syncthreads();

    #pragma unroll
    for (int rr = 0; rr < 8; rr++) {
        int r = wid * 8 + rr;
        float s = 0.f, s2 = 0.f;
        #pragma unroll
        for (int k = 0; k < 4; k++) {
            float v = sh[r * 132 + lane + 32 * k];
            s += v; s2 += v * v;
        }
        #pragma unroll
        for (int o = 16; o; o >>= 1) {
            s  += __shfl_xor_sync(0xffffffffu, s, o);
            s2 += __shfl_xor_sync(0xffffffffu, s2, o);
        }
        float mu  = s * (1.f / 128.f);
        float inv = rsqrtf(s2 * (1.f / 128.f) - mu * mu + LNEPS);
        #pragma unroll
        for (int k = 0; k < 4; k++) {
            int c = lane + 32 * k;
            sh[r * 132 + c] = (sh[r * 132 + c] - mu) * inv * g1[c] + b1[c];
        }
    }
    __syncthreads();

    for (int i = tid; i < 64 * 128; i += 256) {
        int r = i >> 7, c = i & 127;
        if (n0 + r < NN) g_h[(n0 + r) * 128 + c] = sh[r * 132 + c];
    }

    // GEMM 64x128 = sh(64x128) @ Went(128x128). warp tile 16x64
    {
        const float* Wu = g_Wentr;
        const int m0 = (wid >> 1) * 16;
        const int nw = (wid & 1) * 64;
        float acc[8][4];
        #pragma unroll
        for (int t = 0; t < 8; t++)
            #pragma unroll
            for (int q = 0; q < 4; q++) acc[t][q] = 0.f;

        #pragma unroll
        for (int ks = 0; ks < 16; ks++) {
            int k0 = ks * 8;
            unsigned a0 = f2tf(sh[(m0 + group) * 132 + k0 + tig]);
            unsigned a1 = f2tf(sh[(m0 + group + 8) * 132 + k0 + tig]);
            unsigned a2 = f2tf(sh[(m0 + group) * 132 + k0 + tig + 4]);
            unsigned a3 = f2tf(sh[(m0 + group + 8) * 132 + k0 + tig + 4]);
            #pragma unroll
            for (int nt = 0; nt < 8; nt++) {
                int c = nw + nt * 8 + group;
                unsigned b0 = __float_as_uint(Wu[(k0 + tig) * 128 + c]);
                unsigned b1 = __float_as_uint(Wu[(k0 + tig + 4) * 128 + c]);
                mma_tf32(acc[nt], a0, a1, a2, a3, b0, b1);
            }
        }
        #pragma unroll
        for (int nt = 0; nt < 8; nt++) {
            int r = m0 + group;
            int cc = nw + nt * 8 + 2 * tig;
            sf[r * 132 + cc]           = acc[nt][0];
            sf[r * 132 + cc + 1]       = acc[nt][1];
            sf[(r + 8) * 132 + cc]     = acc[nt][2];
            sf[(r + 8) * 132 + cc + 1] = acc[nt][3];
            if (n0 + r < NN) {
                g_feat0[(n0 + r) * 128 + cc]     = acc[nt][0];
                g_feat0[(n0 + r) * 128 + cc + 1] = acc[nt][1];
            }
            if (n0 + r + 8 < NN) {
                g_feat0[(n0 + r + 8) * 128 + cc]     = acc[nt][2];
                g_feat0[(n0 + r + 8) * 128 + cc + 1] = acc[nt][3];
            }
        }
    }
    __syncthreads();

    #pragma unroll
    for (int rep = 0; rep < 2; rep++) {
        int i = tid + rep * 256;
        int r = i >> 3, hh = i & 7;
        float se = 0.f, st = 0.f;
        #pragma unroll
        for (int d = 0; d < 16; d++) {
            float f = sf[r * 132 + hh * 16 + d];
            se += f * ah[hh * 16 + d];
            st += f * at[hh * 16 + d];
        }
        if (n0 + r < NN) {
            g_eh[(n0 + r) * 8 + hh] = se;
            g_et[(n0 + r) * 8 + hh] = st;
        }
    }
}

// ---------------- K2: er per relation ---------------------------------------
__global__ void k_rel(const float* __restrict__ rel,
                      const float* __restrict__ Wrel,
                      const float* __restrict__ ar)
{
    __shared__ float srow[128];
    const int r = blockIdx.x, k = threadIdx.x;
    srow[k] = rel[r * 128 + k];
    __syncthreads();
    float acc = 0.f;
    for (int j = 0; j < 128; j++) acc += srow[j] * Wrel[j * 128 + k];
    float v = acc * ar[k];
    #pragma unroll
    for (int o = 8; o; o >>= 1) v += __shfl_xor_sync(0xffffffffu, v, o);
    if ((k & 15) == 0) g_er[r * 8 + (k >> 4)] = v;
}

// ---------------- CSR build -------------------------------------------------
__global__ void k_zero() {
    int i = blockIdx.x * blockDim.x + threadIdx.x;
    if (i < NN) g_deg[i] = 0;
}

__global__ void k_hist(const int* __restrict__ dst) {
    int e = blockIdx.x * blockDim.x + threadIdx.x;
    if (e < EE) atomicAdd(&g_deg[dst[e]], 1);
}

// phase A: per-block sums of deg
__global__ void __launch_bounds__(SCAN_B) k_scanA() {
    __shared__ int red[SCAN_B / 32];
    const int t = threadIdx.x;
    const int i = blockIdx.x * SCAN_B + t;
    int v = (i < NN) ? g_deg[i] : 0;
    int s = v;
    #pragma unroll
    for (int o = 16; o; o >>= 1) s += __shfl_xor_sync(0xffffffffu, s, o);
    if ((t & 31) == 0) red[t >> 5] = s;
    __syncthreads();
    if (t < 32) {
        int x = (t < SCAN_B / 32) ? red[t] : 0;
        #pragma unroll
        for (int o = 16; o; o >>= 1) x += __shfl_xor_sync(0xffffffffu, x, o);
        if (t == 0) g_part[blockIdx.x] = x;
    }
}

// phase B: exclusive scan of NBLK partials (single block)
__global__ void __launch_bounds__(512) k_scanB() {
    __shared__ int sp[512];
    const int t = threadIdx.x;
    int v = (t < NBLK) ? g_part[t] : 0;
    sp[t] = v;
    __syncthreads();
    for (int off = 1; off < 512; off <<= 1) {
        int x = (t >= off) ? sp[t - off] : 0;
        __syncthreads();
        sp[t] += x;
        __syncthreads();
    }
    if (t < NBLK) g_part[t] = sp[t] - v;   // exclusive
}

// phase C: local exclusive scan + base -> rowptr/cursor
__global__ void __launch_bounds__(SCAN_B) k_scanC() {
    __shared__ int sp[SCAN_B];
    const int t = threadIdx.x;
    const int i = blockIdx.x * SCAN_B + t;
    const int base = g_part[blockIdx.x];
    int v = (i < NN) ? g_deg[i] : 0;
    sp[t] = v;
    __syncthreads();
    for (int off = 1; off < SCAN_B; off <<= 1) {
        int x = (t >= off) ? sp[t - off] : 0;
        __syncthreads();
        sp[t] += x;
        __syncthreads();
    }
    if (i < NN) {
        int excl = base + sp[t] - v;
        g_rowptr[i] = excl;
        g_cursor[i] = excl;
    }
    if (i == NN - 1) g_rowptr[NN] = EE;
}

__global__ void k_scatter(const int* __restrict__ src,
                          const int* __restrict__ dst,
                          const int* __restrict__ etp)
{
    int e = blockIdx.x * blockDim.x + threadIdx.x;
    if (e < EE) {
        int p = atomicAdd(&g_cursor[dst[e]], 1);
        g_srcs[p] = src[e];
        g_ets[p]  = etp[e];
    }
}

// ---------------- K4: edge softmax (warp per node, 2 passes) ----------------
// writes UNnormalized exp into g_a and 1/sum into g_inv
__global__ void __launch_bounds__(256) k_soft()
{
    const int wid  = (blockIdx.x * blockDim.x + threadIdx.x) >> 5;
    const int lane = threadIdx.x & 31;
    if (wid >= NN) return;
    const int beg = g_rowptr[wid], end = g_rowptr[wid + 1];

    float etn[8];
    {
        const float4* p = (const float4*)&g_et[wid * 8];
        float4 a0 = p[0], a1 = p[1];
        etn[0]=a0.x; etn[1]=a0.y; etn[2]=a0.z; etn[3]=a0.w;
        etn[4]=a1.x; etn[5]=a1.y; etn[6]=a1.z; etn[7]=a1.w;
    }

    float mx[8];
    #pragma unroll
    for (int h = 0; h < 8; h++) mx[h] = -1e30f;

    for (int p = beg + lane; p < end; p += 32) {
        int s = g_srcs[p], t = g_ets[p];
        float eh8[8], er8[8];
        *(float4*)&eh8[0] = ((const float4*)&g_eh[s * 8])[0];
        *(float4*)&eh8[4] = ((const float4*)&g_eh[s * 8])[1];
        *(float4*)&er8[0] = ((const float4*)&g_er[t * 8])[0];
        *(float4*)&er8[4] = ((const float4*)&g_er[t * 8])[1];
        #pragma unroll
        for (int h = 0; h < 8; h++) {
            float sc = eh8[h] + etn[h] + er8[h];
            sc = sc > 0.f ? sc : SLOPE * sc;
            mx[h] = fmaxf(mx[h], sc);
        }
    }
    #pragma unroll
    for (int o = 16; o; o >>= 1)
        #pragma unroll
        for (int h = 0; h < 8; h++)
            mx[h] = fmaxf(mx[h], __shfl_xor_sync(0xffffffffu, mx[h], o));

    float sm[8];
    #pragma unroll
    for (int h = 0; h < 8; h++) sm[h] = 0.f;

    for (int p = beg + lane; p < end; p += 32) {
        int s = g_srcs[p], t = g_ets[p];
        float eh8[8], er8[8], ex[8];
        *(float4*)&eh8[0] = ((const float4*)&g_eh[s * 8])[0];
        *(float4*)&eh8[4] = ((const float4*)&g_eh[s * 8])[1];
        *(float4*)&er8[0] = ((const float4*)&g_er[t * 8])[0];
        *(float4*)&er8[4] = ((const float4*)&g_er[t * 8])[1];
        #pragma unroll
        for (int h = 0; h < 8; h++) {
            float sc = eh8[h] + etn[h] + er8[h];
            sc = sc > 0.f ? sc : SLOPE * sc;
            ex[h] = __expf(sc - mx[h]);
            sm[h] += ex[h];
        }
        float4 o0 = {ex[0], ex[1], ex[2], ex[3]};
        float4 o1 = {ex[4], ex[5], ex[6], ex[7]};
        ((float4*)&g_a[p * 8])[0] = o0;
        ((float4*)&g_a[p * 8])[1] = o1;
    }
    #pragma unroll
    for (int o = 16; o; o >>= 1)
        #pragma unroll
        for (int h = 0; h < 8; h++)
            sm[h] += __shfl_xor_sync(0xffffffffu, sm[h], o);

    if (lane == 0) {
        float inv[8];
        #pragma unroll
        for (int h = 0; h < 8; h++) inv[h] = (sm[h] > 0.f) ? (1.f / sm[h]) : 0.f;
        float4 i0 = {inv[0], inv[1], inv[2], inv[3]};
        float4 i1 = {inv[4], inv[5], inv[6], inv[7]};
        ((float4*)&g_inv[wid * 8])[0] = i0;
        ((float4*)&g_inv[wid * 8])[1] = i1;
    }
}

// ---------------- K5: one diffusion hop (warp per node) ---------------------
// normalization folded in: acc * g_inv[node, head]
__global__ void __launch_bounds__(256) k_hop(int hop)
{
    const float4* fin  = (hop == 0) ? (const float4*)g_feat0
                        : ((hop & 1) ? (const float4*)g_fA : (const float4*)g_fB);
    float4* fout = (hop & 1) ? (float4*)g_fB : (float4*)g_fA;

    const int wid  = (blockIdx.x * blockDim.x + threadIdx.x) >> 5;
    const int lane = threadIdx.x & 31;
    if (wid >= NN) return;
    const int beg = g_rowptr[wid], end = g_rowptr[wid + 1];
    const int h = lane >> 2;

    const float invh = g_inv[wid * 8 + h];

    float4 acc = {0.f, 0.f, 0.f, 0.f};
    for (int pb = beg; pb < end; pb += 32) {
        int cnt = min(32, end - pb);
        int sl = (pb + lane < end) ? g_srcs[pb + lane] : 0;
        for (int q = 0; q < cnt; q++) {
            int s = __shfl_sync(0xffffffffu, sl, q);
            float av = __ldg(&g_a[(pb + q) * 8 + h]);
            float4 v = fin[s * 32 + lane];
            acc.x += av * v.x; acc.y += av * v.y;
            acc.z += av * v.z; acc.w += av * v.w;
        }
    }
    const float w = (1.f - ALPHA) * invh;
    float4 f0 = ((const float4*)g_feat0)[wid * 32 + lane];
    float4 o;
    o.x = w * acc.x + ALPHA * f0.x;
    o.y = w * acc.y + ALPHA * f0.y;
    o.z = w * acc.z + ALPHA * f0.z;
    o.w = w * acc.w + ALPHA * f0.w;
    fout[wid * 32 + lane] = o;
}

// ---------------- K6: residual + LN2 + FFN + residual (tensor core) ---------
__global__ void __launch_bounds__(256) k_ffn(
    const float* __restrict__ g2, const float* __restrict__ be2,
    const float* __restrict__ bb1, const float* __restrict__ bb2,
    float* __restrict__ out)
{
    extern __shared__ float smem_[];
    float* rst = smem_;                    // 64*132
    float* yln = smem_ + 64 * 132;         // 64*132
    float* z   = smem_ + 2 * 64 * 132;     // 64*520
    const int n0 = blockIdx.x * 64;
    const int tid = threadIdx.x;
    const int wid = tid >> 5, lane = tid & 31;
    const int group = lane >> 2, tig = lane & 3;

    for (int i = tid; i < 64 * 128; i += 256) {
        int r = i >> 7, c = i & 127;
        int gr = min(n0 + r, NN - 1);
        rst[r * 132 + c] = g_fA[gr * 128 + c] + g_h[gr * 128 + c];
    }
    __syncthreads();

    #pragma unroll
    for (int rr = 0; rr < 8; rr++) {
        int r = wid * 8 + rr;
        float s = 0.f, s2 = 0.f;
        #pragma unroll
        for (int k = 0; k < 4; k++) {
            float v = rst[r * 132 + lane + 32 * k];
            s += v; s2 += v * v;
        }
        #pragma unroll
        for (int o = 16; o; o >>= 1) {
            s  += __shfl_xor_sync(0xffffffffu, s, o);
            s2 += __shfl_xor_sync(0xffffffffu, s2, o);
        }
        float mu  = s * (1.f / 128.f);
        float inv = rsqrtf(s2 * (1.f / 128.f) - mu * mu + LNEPS);
        #pragma unroll
        for (int k = 0; k < 4; k++) {
            int c = lane + 32 * k;
            float y = (rst[r * 132 + c] - mu) * inv * g2[c] + be2[c];
            yln[r * 132 + c] = __uint_as_float(f2tf(y));
        }
    }
    __syncthreads();

    // GEMM1: z(64x512) = relu(y @ W1 + b1). warp tile 32x128
    {
        const float* Wu = g_W1r;
        const int m0 = (wid >> 2) * 32;
        const int nw = (wid & 3) * 128;
        float acc[2][16][4];
        #pragma unroll
        for (int mt = 0; mt < 2; mt++)
            #pragma unroll
            for (int nt = 0; nt < 16; nt++)
                #pragma unroll
                for (int q = 0; q < 4; q++) acc[mt][nt][q] = 0.f;

        #pragma unroll
        for (int ks = 0; ks < 16; ks++) {
            int k0 = ks * 8;
            unsigned a[2][4];
            #pragma unroll
            for (int mt = 0; mt < 2; mt++) {
                int rb = m0 + mt * 16 + group;
                a[mt][0] = __float_as_uint(yln[rb * 132 + k0 + tig]);
                a[mt][1] = __float_as_uint(yln[(rb + 8) * 132 + k0 + tig]);
                a[mt][2] = __float_as_uint(yln[rb * 132 + k0 + tig + 4]);
                a[mt][3] = __float_as_uint(yln[(rb + 8) * 132 + k0 + tig + 4]);
            }
            #pragma unroll
            for (int nt = 0; nt < 16; nt++) {
                int c = nw + nt * 8 + group;
                unsigned b0 = __float_as_uint(Wu[(k0 + tig) * 512 + c]);
                unsigned b1 = __float_as_uint(Wu[(k0 + tig + 4) * 512 + c]);
                mma_tf32(acc[0][nt], a[0][0], a[0][1], a[0][2], a[0][3], b0, b1);
                mma_tf32(acc[1][nt], a[1][0], a[1][1], a[1][2], a[1][3], b0, b1);
            }
        }
        #pragma unroll
        for (int mt = 0; mt < 2; mt++)
            #pragma unroll
            for (int nt = 0; nt < 16; nt++) {
                int r  = m0 + mt * 16 + group;
                int cc = nw + nt * 8 + 2 * tig;
                float v0 = fmaxf(acc[mt][nt][0] + bb1[cc], 0.f);
                float v1 = fmaxf(acc[mt][nt][1] + bb1[cc + 1], 0.f);
                float v2 = fmaxf(acc[mt][nt][2] + bb1[cc], 0.f);
                float v3 = fmaxf(acc[mt][nt][3] + bb1[cc + 1], 0.f);
                z[r * 520 + cc]           = __uint_as_float(f2tf(v0));
                z[r * 520 + cc + 1]       = __uint_as_float(f2tf(v1));
                z[(r + 8) * 520 + cc]     = __uint_as_float(f2tf(v2));
                z[(r + 8) * 520 + cc + 1] = __uint_as_float(f2tf(v3));
            }
    }
    __syncthreads();

    // GEMM2: out(64x128) = z @ W2 + b2 + rst. warp tile 16x64
    {
        const float* Wu = g_W2r;
        const int m0 = (wid >> 1) * 16;
        const int nw = (wid & 1) * 64;
        float acc[8][4];
        #pragma unroll
        for (int nt = 0; nt < 8; nt++)
            #pragma unroll
            for (int q = 0; q < 4; q++) acc[nt][q] = 0.f;

        #pragma unroll 8
        for (int ks = 0; ks < 64; ks++) {
            int k0 = ks * 8;
            unsigned a0 = __float_as_uint(z[(m0 + group) * 520 + k0 + tig]);
            unsigned a1 = __float_as_uint(z[(m0 + group + 8) * 520 + k0 + tig]);
            unsigned a2 = __float_as_uint(z[(m0 + group) * 520 + k0 + tig + 4]);
            unsigned a3 = __float_as_uint(z[(m0 + group + 8) * 520 + k0 + tig + 4]);
            #pragma unroll
            for (int nt = 0; nt < 8; nt++) {
                int c = nw + nt * 8 + group;
                unsigned b0 = __float_as_uint(Wu[(k0 + tig) * 128 + c]);
                unsigned b1 = __float_as_uint(Wu[(k0 + tig + 4) * 128 + c]);
                mma_tf32(acc[nt], a0, a1, a2, a3, b0, b1);
            }
        }
        #pragma unroll
        for (int nt = 0; nt < 8; nt++) {
            int r  = m0 + group;
            int cc = nw + nt * 8 + 2 * tig;
            if (n0 + r < NN) {
                out[(n0 + r) * 128 + cc]     = acc[nt][0] + bb2[cc]     + rst[r * 132 + cc];
                out[(n0 + r) * 128 + cc + 1] = acc[nt][1] + bb2[cc + 1] + rst[r * 132 + cc + 1];
            }
            if (n0 + r + 8 < NN) {
                out[(n0 + r + 8) * 128 + cc]     = acc[nt][2] + bb2[cc]     + rst[(r + 8) * 132 + cc];
                out[(n0 + r + 8) * 128 + cc + 1] = acc[nt][3] + bb2[cc + 1] + rst[(r + 8) * 132 + cc + 1];
            }
        }
    }
}

// ---------------- launch ----------------------------------------------------
extern "C" void kernel_launch(void* const* d_in, const int* in_sizes, int n_in,
                              void* d_out, int out_size)
{
    const float* ent   = (const float*)d_in[0];
    const float* rel   = (const float*)d_in[1];
    const int*   src   = (const int*)  d_in[2];
    const int*   dst   = (const int*)  d_in[3];
    const int*   etp   = (const int*)  d_in[4];
    const float* ln1g  = (const float*)d_in[5];
    const float* ln1b  = (const float*)d_in[6];
    const float* Went  = (const float*)d_in[7];
    const float* Wrel  = (const float*)d_in[8];
    const float* ah    = (const float*)d_in[9];
    const float* at    = (const float*)d_in[10];
    const float* ar    = (const float*)d_in[11];
    const float* ln2g  = (const float*)d_in[12];
    const float* ln2b  = (const float*)d_in[13];
    const float* W1    = (const float*)d_in[14];
    const float* b1    = (const float*)d_in[15];
    const float* W2    = (const float*)d_in[16];
    const float* b2    = (const float*)d_in[17];
    float* out = (float*)d_out;

    static const size_t LN1_SMEM = (2 * 64 * 132) * sizeof(float);              // 67584
    static const size_t FFN_SMEM = (2 * 64 * 132 + 64 * 520) * sizeof(float);   // 200704
    cudaFuncSetAttribute(k_ln1_feat, cudaFuncAttributeMaxDynamicSharedMemorySize, (int)LN1_SMEM);
    cudaFuncSetAttribute(k_ffn, cudaFuncAttributeMaxDynamicSharedMemorySize, (int)FFN_SMEM);

    // pre-round weights to tf32
    k_rnd3<<<(RND_TOTAL + 255) / 256, 256>>>(Went, W1, W2);

    // CSR build (parallel scan)
    k_zero<<<(NN + 255) / 256, 256>>>();
    k_hist<<<EE / 256, 256>>>(dst);
    k_scanA<<<NBLK, SCAN_B>>>();
    k_scanB<<<1, 512>>>();
    k_scanC<<<NBLK, SCAN_B>>>();
    k_scatter<<<EE / 256, 256>>>(src, dst, etp);

    // node/relation projections + attention logit pieces
    k_ln1_feat<<<(NN + 63) / 64, 256, LN1_SMEM>>>(ent, ln1g, ln1b, ah, at);
    k_rel<<<RR, 128>>>(rel, Wrel, ar);

    // edge softmax (unnormalized + inv table)
    k_soft<<<NN / 8, 256>>>();

    // diffusion
    for (int hop = 0; hop < HOPS; hop++)
        k_hop<<<NN / 8, 256>>>(hop);

    // FFN + residuals
    k_ffn<<<(NN + 63) / 64, 256, FFN_SMEM>>>(ln2g, ln2b, b1, b2, out);
}

// round 5
// speedup vs baseline: 1.8032x; 1.0102x over previous
#include <cuda_runtime.h>
#include <cuda_bf16.h>

#define NN   100000
#define EE   1600000
#define RR   500
#define DDIM 128
#define HH   8
#define DHH  16
#define DFFN 512
#define HOPS 5
#define ALPHA 0.15f
#define SLOPE 0.2f
#define LNEPS 1e-5f

#define SCAN_B 256
#define NBLK ((NN + SCAN_B - 1) / SCAN_B)   // 391

// ---------------- scratch (static device globals; no allocation) -------------
__device__ float g_h[NN * DDIM];        // LN1 output
__device__ float g_feat0[NN * DDIM];    // h @ W_ent (fp32 anchor)
__device__ float g_fA[NN * DDIM];       // final hop output (fp32)
__device__ __nv_bfloat16 g_f0h[NN * DDIM];  // feat0 in bf16 (hop-0 input)
__device__ __nv_bfloat16 g_hA[NN * DDIM];   // bf16 ping
__device__ __nv_bfloat16 g_hB[NN * DDIM];   // bf16 pong
__device__ float g_eh[NN * HH];
__device__ float g_et[NN * HH];
__device__ float g_er[RR * HH];
__device__ float g_a[EE * HH];          // UNnormalized exp scores, dst-sorted order
__device__ float g_inv[NN * HH];        // 1/softmax-sum per (node, head)
__device__ int   g_deg[NN];
__device__ int   g_rowptr[NN + 1];
__device__ int   g_cursor[NN];
__device__ int   g_part[512];           // scan partials
__device__ int   g_srcs[EE];            // src, sorted by dst
__device__ int   g_ets[EE];             // e_type, sorted by dst
// TF32-prerounded weights
__device__ float g_Wentr[DDIM * DDIM];
__device__ float g_W1r[DDIM * DFFN];
__device__ float g_W2r[DFFN * DDIM];

// ---------------- mma helpers ------------------------------------------------
__device__ __forceinline__ unsigned f2tf(float f) {
    unsigned u;
    asm("cvt.rna.tf32.f32 %0, %1;" : "=r"(u) : "f"(f));
    return u;
}

__device__ __forceinline__ void mma_tf32(float c[4],
    unsigned a0, unsigned a1, unsigned a2, unsigned a3,
    unsigned b0, unsigned b1)
{
    asm volatile(
        "mma.sync.aligned.m16n8k8.row.col.f32.tf32.tf32.f32 "
        "{%0,%1,%2,%3}, {%4,%5,%6,%7}, {%8,%9}, {%0,%1,%2,%3};"
        : "+f"(c[0]), "+f"(c[1]), "+f"(c[2]), "+f"(c[3])
        : "r"(a0), "r"(a1), "r"(a2), "r"(a3), "r"(b0), "r"(b1));
}

// ---------------- K0: preround all weights to tf32 ---------------------------
#define RND_TOTAL (DDIM * DDIM + DDIM * DFFN + DFFN * DDIM)  // 147456
__global__ void k_rnd3(const float* __restrict__ Went,
                       const float* __restrict__ W1,
                       const float* __restrict__ W2)
{
    int i = blockIdx.x * blockDim.x + threadIdx.x;
    if (i < DDIM * DDIM) {
        g_Wentr[i] = __uint_as_float(f2tf(Went[i]));
    } else if (i < DDIM * DDIM + DDIM * DFFN) {
        int j = i - DDIM * DDIM;
        g_W1r[j] = __uint_as_float(f2tf(W1[j]));
    } else if (i < RND_TOTAL) {
        int j = i - DDIM * DDIM - DDIM * DFFN;
        g_W2r[j] = __uint_as_float(f2tf(W2[j]));
    }
}

// ---------------- K1: LN1 + feat = h@W_ent + eh/et (tensor core) -------------
__global__ void __launch_bounds__(256) k_ln1_feat(
    const float* __restrict__ ent, const float* __restrict__ g1,
    const float* __restrict__ b1,
    const float* __restrict__ ah, const float* __restrict__ at)
{
    extern __shared__ float smem_[];
    float* sh = smem_;               // 64*132 LN output
    float* sf = smem_ + 64 * 132;    // 64*132 feat tile
    const int n0 = blockIdx.x * 64;
    const int tid = threadIdx.x;
    const int wid = tid >> 5, lane = tid & 31;
    const int group = lane >> 2, tig = lane & 3;

    for (int i = tid; i < 64 * 128; i += 256) {
        int r = i >> 7, c = i & 127;
        int gr = min(n0 + r, NN - 1);
        sh[r * 132 + c] = ent[gr * 128 + c];
    }
    __syncthreads();

    #pragma unroll
    for (int rr = 0; rr < 8; rr++) {
        int r = wid * 8 + rr;
        float s = 0.f, s2 = 0.f;
        #pragma unroll
        for (int k = 0; k < 4; k++) {
            float v = sh[r * 132 + lane + 32 * k];
            s += v; s2 += v * v;
        }
        #pragma unroll
        for (int o = 16; o; o >>= 1) {
            s  += __shfl_xor_sync(0xffffffffu, s, o);
            s2 += __shfl_xor_sync(0xffffffffu, s2, o);
        }
        float mu  = s * (1.f / 128.f);
        float inv = rsqrtf(s2 * (1.f / 128.f) - mu * mu + LNEPS);
        #pragma unroll
        for (int k = 0; k < 4; k++) {
            int c = lane + 32 * k;
            sh[r * 132 + c] = (sh[r * 132 + c] - mu) * inv * g1[c] + b1[c];
        }
    }
    __syncthreads();

    for (int i = tid; i < 64 * 128; i += 256) {
        int r = i >> 7, c = i & 127;
        if (n0 + r < NN) g_h[(n0 + r) * 128 + c] = sh[r * 132 + c];
    }

    // GEMM 64x128 = sh(64x128) @ Went(128x128). warp tile 16x64
    {
        const float* Wu = g_Wentr;
        const int m0 = (wid >> 1) * 16;
        const int nw = (wid & 1) * 64;
        float acc[8][4];
        #pragma unroll
        for (int t = 0; t < 8; t++)
            #pragma unroll
            for (int q = 0; q < 4; q++) acc[t][q] = 0.f;

        #pragma unroll
        for (int ks = 0; ks < 16; ks++) {
            int k0 = ks * 8;
            unsigned a0 = f2tf(sh[(m0 + group) * 132 + k0 + tig]);
            unsigned a1 = f2tf(sh[(m0 + group + 8) * 132 + k0 + tig]);
            unsigned a2 = f2tf(sh[(m0 + group) * 132 + k0 + tig + 4]);
            unsigned a3 = f2tf(sh[(m0 + group + 8) * 132 + k0 + tig + 4]);
            #pragma unroll
            for (int nt = 0; nt < 8; nt++) {
                int c = nw + nt * 8 + group;
                unsigned b0 = __float_as_uint(Wu[(k0 + tig) * 128 + c]);
                unsigned b1 = __float_as_uint(Wu[(k0 + tig + 4) * 128 + c]);
                mma_tf32(acc[nt], a0, a1, a2, a3, b0, b1);
            }
        }
        #pragma unroll
        for (int nt = 0; nt < 8; nt++) {
            int r = m0 + group;
            int cc = nw + nt * 8 + 2 * tig;
            sf[r * 132 + cc]           = acc[nt][0];
            sf[r * 132 + cc + 1]       = acc[nt][1];
            sf[(r + 8) * 132 + cc]     = acc[nt][2];
            sf[(r + 8) * 132 + cc + 1] = acc[nt][3];
            if (n0 + r < NN) {
                g_feat0[(n0 + r) * 128 + cc]     = acc[nt][0];
                g_feat0[(n0 + r) * 128 + cc + 1] = acc[nt][1];
                *(__nv_bfloat162*)&g_f0h[(n0 + r) * 128 + cc] =
                    __float22bfloat162_rn(make_float2(acc[nt][0], acc[nt][1]));
            }
            if (n0 + r + 8 < NN) {
                g_feat0[(n0 + r + 8) * 128 + cc]     = acc[nt][2];
                g_feat0[(n0 + r + 8) * 128 + cc + 1] = acc[nt][3];
                *(__nv_bfloat162*)&g_f0h[(n0 + r + 8) * 128 + cc] =
                    __float22bfloat162_rn(make_float2(acc[nt][2], acc[nt][3]));
            }
        }
    }
    __syncthreads();

    #pragma unroll
    for (int rep = 0; rep < 2; rep++) {
        int i = tid + rep * 256;
        int r = i >> 3, hh = i & 7;
        float se = 0.f, st = 0.f;
        #pragma unroll
        for (int d = 0; d < 16; d++) {
            float f = sf[r * 132 + hh * 16 + d];
            se += f * ah[hh * 16 + d];
            st += f * at[hh * 16 + d];
        }
        if (n0 + r < NN) {
            g_eh[(n0 + r) * 8 + hh] = se;
            g_et[(n0 + r) * 8 + hh] = st;
        }
    }
}

// ---------------- K2: er per relation ---------------------------------------
__global__ void k_rel(const float* __restrict__ rel,
                      const float* __restrict__ Wrel,
                      const float* __restrict__ ar)
{
    __shared__ float srow[128];
    const int r = blockIdx.x, k = threadIdx.x;
    srow[k] = rel[r * 128 + k];
    __syncthreads();
    float acc = 0.f;
    for (int j = 0; j < 128; j++) acc += srow[j] * Wrel[j * 128 + k];
    float v = acc * ar[k];
    #pragma unroll
    for (int o = 8; o; o >>= 1) v += __shfl_xor_sync(0xffffffffu, v, o);
    if ((k & 15) == 0) g_er[r * 8 + (k >> 4)] = v;
}

// ---------------- CSR build -------------------------------------------------
__global__ void k_zero() {
    int i = blockIdx.x * blockDim.x + threadIdx.x;
    if (i < NN) g_deg[i] = 0;
}

__global__ void k_hist(const int* __restrict__ dst) {
    int e = blockIdx.x * blockDim.x + threadIdx.x;
    if (e < EE) atomicAdd(&g_deg[dst[e]], 1);
}

__global__ void __launch_bounds__(SCAN_B) k_scanA() {
    __shared__ int red[SCAN_B / 32];
    const int t = threadIdx.x;
    const int i = blockIdx.x * SCAN_B + t;
    int v = (i < NN) ? g_deg[i] : 0;
    int s = v;
    #pragma unroll
    for (int o = 16; o; o >>= 1) s += __shfl_xor_sync(0xffffffffu, s, o);
    if ((t & 31) == 0) red[t >> 5] = s;
    __syncthreads();
    if (t < 32) {
        int x = (t < SCAN_B / 32) ? red[t] : 0;
        #pragma unroll
        for (int o = 16; o; o >>= 1) x += __shfl_xor_sync(0xffffffffu, x, o);
        if (t == 0) g_part[blockIdx.x] = x;
    }
}

__global__ void __launch_bounds__(512) k_scanB() {
    __shared__ int sp[512];
    const int t = threadIdx.x;
    int v = (t < NBLK) ? g_part[t] : 0;
    sp[t] = v;
    __syncthreads();
    for (int off = 1; off < 512; off <<= 1) {
        int x = (t >= off) ? sp[t - off] : 0;
        __syncthreads();
        sp[t] += x;
        __syncthreads();
    }
    if (t < NBLK) g_part[t] = sp[t] - v;   // exclusive
}

__global__ void __launch_bounds__(SCAN_B) k_scanC() {
    __shared__ int sp[SCAN_B];
    const int t = threadIdx.x;
    const int i = blockIdx.x * SCAN_B + t;
    const int base = g_part[blockIdx.x];
    int v = (i < NN) ? g_deg[i] : 0;
    sp[t] = v;
    __syncthreads();
    for (int off = 1; off < SCAN_B; off <<= 1) {
        int x = (t >= off) ? sp[t - off] : 0;
        __syncthreads();
        sp[t] += x;
        __syncthreads();
    }
    if (i < NN) {
        int excl = base + sp[t] - v;
        g_rowptr[i] = excl;
        g_cursor[i] = excl;
    }
    if (i == NN - 1) g_rowptr[NN] = EE;
}

__global__ void k_scatter(const int* __restrict__ src,
                          const int* __restrict__ dst,
                          const int* __restrict__ etp)
{
    int e = blockIdx.x * blockDim.x + threadIdx.x;
    if (e < EE) {
        int p = atomicAdd(&g_cursor[dst[e]], 1);
        g_srcs[p] = src[e];
        g_ets[p]  = etp[e];
    }
}

// ---------------- K4: edge softmax (warp per node, 2 passes) ----------------
__global__ void __launch_bounds__(256) k_soft()
{
    const int wid  = (blockIdx.x * blockDim.x + threadIdx.x) >> 5;
    const int lane = threadIdx.x & 31;
    if (wid >= NN) return;
    const int beg = g_rowptr[wid], end = g_rowptr[wid + 1];

    float etn[8];
    {
        const float4* p = (const float4*)&g_et[wid * 8];
        float4 a0 = p[0], a1 = p[1];
        etn[0]=a0.x; etn[1]=a0.y; etn[2]=a0.z; etn[3]=a0.w;
        etn[4]=a1.x; etn[5]=a1.y; etn[6]=a1.z; etn[7]=a1.w;
    }

    float mx[8];
    #pragma unroll
    for (int h = 0; h < 8; h++) mx[h] = -1e30f;

    for (int p = beg + lane; p < end; p += 32) {
        int s = g_srcs[p], t = g_ets[p];
        float eh8[8], er8[8];
        *(float4*)&eh8[0] = ((const float4*)&g_eh[s * 8])[0];
        *(float4*)&eh8[4] = ((const float4*)&g_eh[s * 8])[1];
        *(float4*)&er8[0] = ((const float4*)&g_er[t * 8])[0];
        *(float4*)&er8[4] = ((const float4*)&g_er[t * 8])[1];
        #pragma unroll
        for (int h = 0; h < 8; h++) {
            float sc = eh8[h] + etn[h] + er8[h];
            sc = sc > 0.f ? sc : SLOPE * sc;
            mx[h] = fmaxf(mx[h], sc);
        }
    }
    #pragma unroll
    for (int o = 16; o; o >>= 1)
        #pragma unroll
        for (int h = 0; h < 8; h++)
            mx[h] = fmaxf(mx[h], __shfl_xor_sync(0xffffffffu, mx[h], o));

    float sm[8];
    #pragma unroll
    for (int h = 0; h < 8; h++) sm[h] = 0.f;

    for (int p = beg + lane; p < end; p += 32) {
        int s = g_srcs[p], t = g_ets[p];
        float eh8[8], er8[8], ex[8];
        *(float4*)&eh8[0] = ((const float4*)&g_eh[s * 8])[0];
        *(float4*)&eh8[4] = ((const float4*)&g_eh[s * 8])[1];
        *(float4*)&er8[0] = ((const float4*)&g_er[t * 8])[0];
        *(float4*)&er8[4] = ((const float4*)&g_er[t * 8])[1];
        #pragma unroll
        for (int h = 0; h < 8; h++) {
            float sc = eh8[h] + etn[h] + er8[h];
            sc = sc > 0.f ? sc : SLOPE * sc;
            ex[h] = __expf(sc - mx[h]);
            sm[h] += ex[h];
        }
        float4 o0 = {ex[0], ex[1], ex[2], ex[3]};
        float4 o1 = {ex[4], ex[5], ex[6], ex[7]};
        ((float4*)&g_a[p * 8])[0] = o0;
        ((float4*)&g_a[p * 8])[1] = o1;
    }
    #pragma unroll
    for (int o = 16; o; o >>= 1)
        #pragma unroll
        for (int h = 0; h < 8; h++)
            sm[h] += __shfl_xor_sync(0xffffffffu, sm[h], o);

    if (lane == 0) {
        float inv[8];
        #pragma unroll
        for (int h = 0; h < 8; h++) inv[h] = (sm[h] > 0.f) ? (1.f / sm[h]) : 0.f;
        float4 i0 = {inv[0], inv[1], inv[2], inv[3]};
        float4 i1 = {inv[4], inv[5], inv[6], inv[7]};
        ((float4*)&g_inv[wid * 8])[0] = i0;
        ((float4*)&g_inv[wid * 8])[1] = i1;
    }
}

// ---------------- K5: one diffusion hop (warp per node, bf16 gather) --------
__global__ void __launch_bounds__(256) k_hop(int hop)
{
    const __nv_bfloat16* finb =
        (hop == 0) ? g_f0h : ((hop & 1) ? g_hA : g_hB);
    const uint2* fin = (const uint2*)finb;   // 8 bytes = 4 bf16 per lane
    __nv_bfloat16* foutb = (hop & 1) ? g_hB : g_hA;
    const bool last = (hop == HOPS - 1);

    const int wid  = (blockIdx.x * blockDim.x + threadIdx.x) >> 5;
    const int lane = threadIdx.x & 31;
    if (wid >= NN) return;
    const int beg = g_rowptr[wid], end = g_rowptr[wid + 1];
    const int h = lane >> 2;

    const float invh = g_inv[wid * 8 + h];

    float4 acc = {0.f, 0.f, 0.f, 0.f};
    int p = beg;
    for (; p + 32 <= end; p += 32) {
        int sl = g_srcs[p + lane];
        #pragma unroll 4
        for (int q = 0; q < 32; q++) {
            int s = __shfl_sync(0xffffffffu, sl, q);
            float av = __ldg(&g_a[(p + q) * 8 + h]);
            uint2 v = __ldg(&fin[s * 32 + lane]);
            float2 lo = __bfloat1622float2(*(__nv_bfloat162*)&v.x);
            float2 hi = __bfloat1622float2(*(__nv_bfloat162*)&v.y);
            acc.x += av * lo.x; acc.y += av * lo.y;
            acc.z += av * hi.x; acc.w += av * hi.y;
        }
    }
    if (p < end) {
        int cnt = end - p;
        int sl = (p + lane < end) ? g_srcs[p + lane] : 0;
        for (int q = 0; q < cnt; q++) {
            int s = __shfl_sync(0xffffffffu, sl, q);
            float av = __ldg(&g_a[(p + q) * 8 + h]);
            uint2 v = __ldg(&fin[s * 32 + lane]);
            float2 lo = __bfloat1622float2(*(__nv_bfloat162*)&v.x);
            float2 hi = __bfloat1622float2(*(__nv_bfloat162*)&v.y);
            acc.x += av * lo.x; acc.y += av * lo.y;
            acc.z += av * hi.x; acc.w += av * hi.y;
        }
    }

    const float w = (1.f - ALPHA) * invh;
    float4 f0 = ((const float4*)g_feat0)[wid * 32 + lane];
    float4 o;
    o.x = w * acc.x + ALPHA * f0.x;
    o.y = w * acc.y + ALPHA * f0.y;
    o.z = w * acc.z + ALPHA * f0.z;
    o.w = w * acc.w + ALPHA * f0.w;

    if (last) {
        ((float4*)g_fA)[wid * 32 + lane] = o;
    } else {
        __nv_bfloat162 p0 = __float22bfloat162_rn(make_float2(o.x, o.y));
        __nv_bfloat162 p1 = __float22bfloat162_rn(make_float2(o.z, o.w));
        uint2 st;
        st.x = *(unsigned*)&p0;
        st.y = *(unsigned*)&p1;
        ((uint2*)foutb)[wid * 32 + lane] = st;
    }
}

// ---------------- K6: residual + LN2 + FFN + residual (tensor core) ---------
__global__ void __launch_bounds__(256) k_ffn(
    const float* __restrict__ g2, const float* __restrict__ be2,
    const float* __restrict__ bb1, const float* __restrict__ bb2,
    float* __restrict__ out)
{
    extern __shared__ float smem_[];
    float* rst = smem_;                    // 64*132
    float* yln = smem_ + 64 * 132;         // 64*132
    float* z   = smem_ + 2 * 64 * 132;     // 64*520
    const int n0 = blockIdx.x * 64;
    const int tid = threadIdx.x;
    const int wid = tid >> 5, lane = tid & 31;
    const int group = lane >> 2, tig = lane & 3;

    for (int i = tid; i < 64 * 128; i += 256) {
        int r = i >> 7, c = i & 127;
        int gr = min(n0 + r, NN - 1);
        rst[r * 132 + c] = g_fA[gr * 128 + c] + g_h[gr * 128 + c];
    }
    __syncthreads();

    #pragma unroll
    for (int rr = 0; rr < 8; rr++) {
        int r = wid * 8 + rr;
        float s = 0.f, s2 = 0.f;
        #pragma unroll
        for (int k = 0; k < 4; k++) {
            float v = rst[r * 132 + lane + 32 * k];
            s += v; s2 += v * v;
        }
        #pragma unroll
        for (int o = 16; o; o >>= 1) {
            s  += __shfl_xor_sync(0xffffffffu, s, o);
            s2 += __shfl_xor_sync(0xffffffffu, s2, o);
        }
        float mu  = s * (1.f / 128.f);
        float inv = rsqrtf(s2 * (1.f / 128.f) - mu * mu + LNEPS);
        #pragma unroll
        for (int k = 0; k < 4; k++) {
            int c = lane + 32 * k;
            float y = (rst[r * 132 + c] - mu) * inv * g2[c] + be2[c];
            yln[r * 132 + c] = __uint_as_float(f2tf(y));
        }
    }
    __syncthreads();

    // GEMM1: z(64x512) = relu(y @ W1 + b1). warp tile 32x128
    {
        const float* Wu = g_W1r;
        const int m0 = (wid >> 2) * 32;
        const int nw = (wid & 3) * 128;
        float acc[2][16][4];
        #pragma unroll
        for (int mt = 0; mt < 2; mt++)
            #pragma unroll
            for (int nt = 0; nt < 16; nt++)
                #pragma unroll
                for (int q = 0; q < 4; q++) acc[mt][nt][q] = 0.f;

        #pragma unroll
        for (int ks = 0; ks < 16; ks++) {
            int k0 = ks * 8;
            unsigned a[2][4];
            #pragma unroll
            for (int mt = 0; mt < 2; mt++) {
                int rb = m0 + mt * 16 + group;
                a[mt][0] = __float_as_uint(yln[rb * 132 + k0 + tig]);
                a[mt][1] = __float_as_uint(yln[(rb + 8) * 132 + k0 + tig]);
                a[mt][2] = __float_as_uint(yln[rb * 132 + k0 + tig + 4]);
                a[mt][3] = __float_as_uint(yln[(rb + 8) * 132 + k0 + tig + 4]);
            }
            #pragma unroll
            for (int nt = 0; nt < 16; nt++) {
                int c = nw + nt * 8 + group;
                unsigned b0 = __float_as_uint(Wu[(k0 + tig) * 512 + c]);
                unsigned b1 = __float_as_uint(Wu[(k0 + tig + 4) * 512 + c]);
                mma_tf32(acc[0][nt], a[0][0], a[0][1], a[0][2], a[0][3], b0, b1);
                mma_tf32(acc[1][nt], a[1][0], a[1][1], a[1][2], a[1][3], b0, b1);
            }
        }
        #pragma unroll
        for (int mt = 0; mt < 2; mt++)
            #pragma unroll
            for (int nt = 0; nt < 16; nt++) {
                int r  = m0 + mt * 16 + group;
                int cc = nw + nt * 8 + 2 * tig;
                float v0 = fmaxf(acc[mt][nt][0] + bb1[cc], 0.f);
                float v1 = fmaxf(acc[mt][nt][1] + bb1[cc + 1], 0.f);
                float v2 = fmaxf(acc[mt][nt][2] + bb1[cc], 0.f);
                float v3 = fmaxf(acc[mt][nt][3] + bb1[cc + 1], 0.f);
                z[r * 520 + cc]           = __uint_as_float(f2tf(v0));
                z[r * 520 + cc + 1]       = __uint_as_float(f2tf(v1));
                z[(r + 8) * 520 + cc]     = __uint_as_float(f2tf(v2));
                z[(r + 8) * 520 + cc + 1] = __uint_as_float(f2tf(v3));
            }
    }
    __syncthreads();

    // GEMM2: out(64x128) = z @ W2 + b2 + rst. warp tile 16x64
    {
        const float* Wu = g_W2r;
        const int m0 = (wid >> 1) * 16;
        const int nw = (wid & 1) * 64;
        float acc[8][4];
        #pragma unroll
        for (int nt = 0; nt < 8; nt++)
            #pragma unroll
            for (int q = 0; q < 4; q++) acc[nt][q] = 0.f;

        #pragma unroll 8
        for (int ks = 0; ks < 64; ks++) {
            int k0 = ks * 8;
            unsigned a0 = __float_as_uint(z[(m0 + group) * 520 + k0 + tig]);
            unsigned a1 = __float_as_uint(z[(m0 + group + 8) * 520 + k0 + tig]);
            unsigned a2 = __float_as_uint(z[(m0 + group) * 520 + k0 + tig + 4]);
            unsigned a3 = __float_as_uint(z[(m0 + group + 8) * 520 + k0 + tig + 4]);
            #pragma unroll
            for (int nt = 0; nt < 8; nt++) {
                int c = nw + nt * 8 + group;
                unsigned b0 = __float_as_uint(Wu[(k0 + tig) * 128 + c]);
                unsigned b1 = __float_as_uint(Wu[(k0 + tig + 4) * 128 + c]);
                mma_tf32(acc[nt], a0, a1, a2, a3, b0, b1);
            }
        }
        #pragma unroll
        for (int nt = 0; nt < 8; nt++) {
            int r  = m0 + group;
            int cc = nw + nt * 8 + 2 * tig;
            if (n0 + r < NN) {
                out[(n0 + r) * 128 + cc]     = acc[nt][0] + bb2[cc]     + rst[r * 132 + cc];
                out[(n0 + r) * 128 + cc + 1] = acc[nt][1] + bb2[cc + 1] + rst[r * 132 + cc + 1];
            }
            if (n0 + r + 8 < NN) {
                out[(n0 + r + 8) * 128 + cc]     = acc[nt][2] + bb2[cc]     + rst[(r + 8) * 132 + cc];
                out[(n0 + r + 8) * 128 + cc + 1] = acc[nt][3] + bb2[cc + 1] + rst[(r + 8) * 132 + cc + 1];
            }
        }
    }
}

// ---------------- launch ----------------------------------------------------
extern "C" void kernel_launch(void* const* d_in, const int* in_sizes, int n_in,
                              void* d_out, int out_size)
{
    const float* ent   = (const float*)d_in[0];
    const float* rel   = (const float*)d_in[1];
    const int*   src   = (const int*)  d_in[2];
    const int*   dst   = (const int*)  d_in[3];
    const int*   etp   = (const int*)  d_in[4];
    const float* ln1g  = (const float*)d_in[5];
    const float* ln1b  = (const float*)d_in[6];
    const float* Went  = (const float*)d_in[7];
    const float* Wrel  = (const float*)d_in[8];
    const float* ah    = (const float*)d_in[9];
    const float* at    = (const float*)d_in[10];
    const float* ar    = (const float*)d_in[11];
    const float* ln2g  = (const float*)d_in[12];
    const float* ln2b  = (const float*)d_in[13];
    const float* W1    = (const float*)d_in[14];
    const float* b1    = (const float*)d_in[15];
    const float* W2    = (const float*)d_in[16];
    const float* b2    = (const float*)d_in[17];
    float* out = (float*)d_out;

    static const size_t LN1_SMEM = (2 * 64 * 132) * sizeof(float);              // 67584
    static const size_t FFN_SMEM = (2 * 64 * 132 + 64 * 520) * sizeof(float);   // 200704
    cudaFuncSetAttribute(k_ln1_feat, cudaFuncAttributeMaxDynamicSharedMemorySize, (int)LN1_SMEM);
    cudaFuncSetAttribute(k_ffn, cudaFuncAttributeMaxDynamicSharedMemorySize, (int)FFN_SMEM);

    // pre-round weights to tf32
    k_rnd3<<<(RND_TOTAL + 255) / 256, 256>>>(Went, W1, W2);

    // CSR build (parallel scan)
    k_zero<<<(NN + 255) / 256, 256>>>();
    k_hist<<<EE / 256, 256>>>(dst);
    k_scanA<<<NBLK, SCAN_B>>>();
    k_scanB<<<1, 512>>>();
    k_scanC<<<NBLK, SCAN_B>>>();
    k_scatter<<<EE / 256, 256>>>(src, dst, etp);

    // node/relation projections + attention logit pieces
    k_ln1_feat<<<(NN + 63) / 64, 256, LN1_SMEM>>>(ent, ln1g, ln1b, ah, at);
    k_rel<<<RR, 128>>>(rel, Wrel, ar);

    // edge softmax (unnormalized + inv table)
    k_soft<<<NN / 8, 256>>>();

    // diffusion (bf16 state)
    for (int hop = 0; hop < HOPS; hop++)
        k_hop<<<NN / 8, 256>>>(hop);

    // FFN + residuals
    k_ffn<<<(NN + 63) / 64, 256, FFN_SMEM>>>(ln2g, ln2b, b1, b2, out);
}

// round 11
// speedup vs baseline: 1.9017x; 1.0546x over previous
#include <cuda_runtime.h>
#include <cuda_bf16.h>
#include <cuda_fp16.h>

#define NN   100000
#define EE   1600000
#define RR   500
#define DDIM 128
#define HH   8
#define DHH  16
#define DFFN 512
#define HOPS 5
#define ALPHA 0.15f
#define SLOPE 0.2f
#define LNEPS 1e-5f

#define SCAN_B 256
#define NBLK ((NN + SCAN_B - 1) / SCAN_B)   // 391

// ---------------- scratch (static device globals; no allocation) -------------
__device__ float g_h[NN * DDIM];        // LN1 output
__device__ float g_feat0[NN * DDIM];    // h @ W_ent (fp32 anchor)
__device__ float g_fA[NN * DDIM];       // final hop output (fp32)
__device__ __nv_bfloat16 g_f0h[NN * DDIM];  // feat0 in bf16 (hop-0 input)
__device__ __nv_bfloat16 g_hA[NN * DDIM];   // bf16 ping
__device__ __nv_bfloat16 g_hB[NN * DDIM];   // bf16 pong
__device__ float g_eh[NN * HH];
__device__ float g_et[NN * HH];
__device__ float g_er[RR * HH];
__device__ float g_a[EE * HH];          // UNnormalized exp scores, dst-sorted order
__device__ float g_inv[NN * HH];        // 1/softmax-sum per (node, head)
__device__ int   g_deg[NN];
__device__ int   g_rowptr[NN + 1];
__device__ int   g_cursor[NN];
__device__ int   g_part[512];           // scan partials
__device__ int   g_srcs[EE];            // src, sorted by dst
__device__ int   g_ets[EE];             // e_type, sorted by dst
// TF32-prerounded weights
__device__ float g_Wentr[DDIM * DDIM];
__device__ float g_W1r[DDIM * DFFN];
__device__ float g_W2r[DFFN * DDIM];

// ---------------- mma helpers ------------------------------------------------
__device__ __forceinline__ unsigned f2tf(float f) {
    unsigned u;
    asm("cvt.rna.tf32.f32 %0, %1;" : "=r"(u) : "f"(f));
    return u;
}

__device__ __forceinline__ void mma_tf32(float c[4],
    unsigned a0, unsigned a1, unsigned a2, unsigned a3,
    unsigned b0, unsigned b1)
{
    asm volatile(
        "mma.sync.aligned.m16n8k8.row.col.f32.tf32.tf32.f32 "
        "{%0,%1,%2,%3}, {%4,%5,%6,%7}, {%8,%9}, {%0,%1,%2,%3};"
        : "+f"(c[0]), "+f"(c[1]), "+f"(c[2]), "+f"(c[3])
        : "r"(a0), "r"(a1), "r"(a2), "r"(a3), "r"(b0), "r"(b1));
}

// ---------------- K0: preround all weights to tf32 ---------------------------
#define RND_TOTAL (DDIM * DDIM + DDIM * DFFN + DFFN * DDIM)  // 147456
__global__ void k_rnd3(const float* __restrict__ Went,
                       const float* __restrict__ W1,
                       const float* __restrict__ W2)
{
    int i = blockIdx.x * blockDim.x + threadIdx.x;
    if (i < DDIM * DDIM) {
        g_Wentr[i] = __uint_as_float(f2tf(Went[i]));
    } else if (i < DDIM * DDIM + DDIM * DFFN) {
        int j = i - DDIM * DDIM;
        g_W1r[j] = __uint_as_float(f2tf(W1[j]));
    } else if (i < RND_TOTAL) {
        int j = i - DDIM * DDIM - DDIM * DFFN;
        g_W2r[j] = __uint_as_float(f2tf(W2[j]));
    }
}

// ---------------- K1: LN1 + feat = h@W_ent + eh/et (tensor core) -------------
__global__ void __launch_bounds__(256) k_ln1_feat(
    const float* __restrict__ ent, const float* __restrict__ g1,
    const float* __restrict__ b1,
    const float* __restrict__ ah, const float* __restrict__ at)
{
    extern __shared__ float smem_[];
    float* sh = smem_;               // 64*132 LN output
    float* sf = smem_ + 64 * 132;    // 64*132 feat tile
    const int n0 = blockIdx.x * 64;
    const int tid = threadIdx.x;
    const int wid = tid >> 5, lane = tid & 31;
    const int group = lane >> 2, tig = lane & 3;

    for (int i = tid; i < 64 * 128; i += 256) {
        int r = i >> 7, c = i & 127;
        int gr = min(n0 + r, NN - 1);
        sh[r * 132 + c] = ent[gr * 128 + c];
    }
    __syncthreads();

    #pragma unroll
    for (int rr = 0; rr < 8; rr++) {
        int r = wid * 8 + rr;
        float s = 0.f, s2 = 0.f;
        #pragma unroll
        for (int k = 0; k < 4; k++) {
            float v = sh[r * 132 + lane + 32 * k];
            s += v; s2 += v * v;
        }
        #pragma unroll
        for (int o = 16; o; o >>= 1) {
            s  += __shfl_xor_sync(0xffffffffu, s, o);
            s2 += __shfl_xor_sync(0xffffffffu, s2, o);
        }
        float mu  = s * (1.f / 128.f);
        float inv = rsqrtf(s2 * (1.f / 128.f) - mu * mu + LNEPS);
        #pragma unroll
        for (int k = 0; k < 4; k++) {
            int c = lane + 32 * k;
            sh[r * 132 + c] = (sh[r * 132 + c] - mu) * inv * g1[c] + b1[c];
        }
    }
    __syncthreads();

    for (int i = tid; i < 64 * 128; i += 256) {
        int r = i >> 7, c = i & 127;
        if (n0 + r < NN) g_h[(n0 + r) * 128 + c] = sh[r * 132 + c];
    }

    // GEMM 64x128 = sh(64x128) @ Went(128x128). warp tile 16x64
    {
        const float* Wu = g_Wentr;
        const int m0 = (wid >> 1) * 16;
        const int nw = (wid & 1) * 64;
        float acc[8][4];
        #pragma unroll
        for (int t = 0; t < 8; t++)
            #pragma unroll
            for (int q = 0; q < 4; q++) acc[t][q] = 0.f;

        #pragma unroll
        for (int ks = 0; ks < 16; ks++) {
            int k0 = ks * 8;
            unsigned a0 = f2tf(sh[(m0 + group) * 132 + k0 + tig]);
            unsigned a1 = f2tf(sh[(m0 + group + 8) * 132 + k0 + tig]);
            unsigned a2 = f2tf(sh[(m0 + group) * 132 + k0 + tig + 4]);
            unsigned a3 = f2tf(sh[(m0 + group + 8) * 132 + k0 + tig + 4]);
            #pragma unroll
            for (int nt = 0; nt < 8; nt++) {
                int c = nw + nt * 8 + group;
                unsigned b0 = __float_as_uint(Wu[(k0 + tig) * 128 + c]);
                unsigned b1 = __float_as_uint(Wu[(k0 + tig + 4) * 128 + c]);
                mma_tf32(acc[nt], a0, a1, a2, a3, b0, b1);
            }
        }
        #pragma unroll
        for (int nt = 0; nt < 8; nt++) {
            int r = m0 + group;
            int cc = nw + nt * 8 + 2 * tig;
            sf[r * 132 + cc]           = acc[nt][0];
            sf[r * 132 + cc + 1]       = acc[nt][1];
            sf[(r + 8) * 132 + cc]     = acc[nt][2];
            sf[(r + 8) * 132 + cc + 1] = acc[nt][3];
            if (n0 + r < NN) {
                g_feat0[(n0 + r) * 128 + cc]     = acc[nt][0];
                g_feat0[(n0 + r) * 128 + cc + 1] = acc[nt][1];
                *(__nv_bfloat162*)&g_f0h[(n0 + r) * 128 + cc] =
                    __float22bfloat162_rn(make_float2(acc[nt][0], acc[nt][1]));
            }
            if (n0 + r + 8 < NN) {
                g_feat0[(n0 + r + 8) * 128 + cc]     = acc[nt][2];
                g_feat0[(n0 + r + 8) * 128 + cc + 1] = acc[nt][3];
                *(__nv_bfloat162*)&g_f0h[(n0 + r + 8) * 128 + cc] =
                    __float22bfloat162_rn(make_float2(acc[nt][2], acc[nt][3]));
            }
        }
    }
    __syncthreads();

    #pragma unroll
    for (int rep = 0; rep < 2; rep++) {
        int i = tid + rep * 256;
        int r = i >> 3, hh = i & 7;
        float se = 0.f, st = 0.f;
        #pragma unroll
        for (int d = 0; d < 16; d++) {
            float f = sf[r * 132 + hh * 16 + d];
            se += f * ah[hh * 16 + d];
            st += f * at[hh * 16 + d];
        }
        if (n0 + r < NN) {
            g_eh[(n0 + r) * 8 + hh] = se;
            g_et[(n0 + r) * 8 + hh] = st;
        }
    }
}

// ---------------- K2: er per relation ---------------------------------------
__global__ void k_rel(const float* __restrict__ rel,
                      const float* __restrict__ Wrel,
                      const float* __restrict__ ar)
{
    __shared__ float srow[128];
    const int r = blockIdx.x, k = threadIdx.x;
    srow[k] = rel[r * 128 + k];
    __syncthreads();
    float acc = 0.f;
    for (int j = 0; j < 128; j++) acc += srow[j] * Wrel[j * 128 + k];
    float v = acc * ar[k];
    #pragma unroll
    for (int o = 8; o; o >>= 1) v += __shfl_xor_sync(0xffffffffu, v, o);
    if ((k & 15) == 0) g_er[r * 8 + (k >> 4)] = v;
}

// ---------------- CSR build -------------------------------------------------
__global__ void k_zero() {
    int i = blockIdx.x * blockDim.x + threadIdx.x;
    if (i < NN) g_deg[i] = 0;
}

__global__ void k_hist(const int* __restrict__ dst) {
    int e = blockIdx.x * blockDim.x + threadIdx.x;
    if (e < EE) atomicAdd(&g_deg[dst[e]], 1);
}

__global__ void __launch_bounds__(SCAN_B) k_scanA() {
    __shared__ int red[SCAN_B / 32];
    const int t = threadIdx.x;
    const int i = blockIdx.x * SCAN_B + t;
    int v = (i < NN) ? g_deg[i] : 0;
    int s = v;
    #pragma unroll
    for (int o = 16; o; o >>= 1) s += __shfl_xor_sync(0xffffffffu, s, o);
    if ((t & 31) == 0) red[t >> 5] = s;
    __syncthreads();
    if (t < 32) {
        int x = (t < SCAN_B / 32) ? red[t] : 0;
        #pragma unroll
        for (int o = 16; o; o >>= 1) x += __shfl_xor_sync(0xffffffffu, x, o);
        if (t == 0) g_part[blockIdx.x] = x;
    }
}

__global__ void __launch_bounds__(512) k_scanB() {
    __shared__ int sp[512];
    const int t = threadIdx.x;
    int v = (t < NBLK) ? g_part[t] : 0;
    sp[t] = v;
    __syncthreads();
    for (int off = 1; off < 512; off <<= 1) {
        int x = (t >= off) ? sp[t - off] : 0;
        __syncthreads();
        sp[t] += x;
        __syncthreads();
    }
    if (t < NBLK) g_part[t] = sp[t] - v;   // exclusive
}

__global__ void __launch_bounds__(SCAN_B) k_scanC() {
    __shared__ int sp[SCAN_B];
    const int t = threadIdx.x;
    const int i = blockIdx.x * SCAN_B + t;
    const int base = g_part[blockIdx.x];
    int v = (i < NN) ? g_deg[i] : 0;
    sp[t] = v;
    __syncthreads();
    for (int off = 1; off < SCAN_B; off <<= 1) {
        int x = (t >= off) ? sp[t - off] : 0;
        __syncthreads();
        sp[t] += x;
        __syncthreads();
    }
    if (i < NN) {
        int excl = base + sp[t] - v;
        g_rowptr[i] = excl;
        g_cursor[i] = excl;
    }
    if (i == NN - 1) g_rowptr[NN] = EE;
}

__global__ void k_scatter(const int* __restrict__ src,
                          const int* __restrict__ dst,
                          const int* __restrict__ etp)
{
    int e = blockIdx.x * blockDim.x + threadIdx.x;
    if (e < EE) {
        int p = atomicAdd(&g_cursor[dst[e]], 1);
        g_srcs[p] = src[e];
        g_ets[p]  = etp[e];
    }
}

// ---------------- K4: edge softmax, SINGLE pass (scores are small;
// softmax without max-shift is mathematically identical and fp-safe here) ----
__global__ void __launch_bounds__(256) k_soft()
{
    const int wid  = (blockIdx.x * blockDim.x + threadIdx.x) >> 5;
    const int lane = threadIdx.x & 31;
    if (wid >= NN) return;
    const int beg = g_rowptr[wid], end = g_rowptr[wid + 1];

    float etn[8];
    {
        const float4* p = (const float4*)&g_et[wid * 8];
        float4 a0 = p[0], a1 = p[1];
        etn[0]=a0.x; etn[1]=a0.y; etn[2]=a0.z; etn[3]=a0.w;
        etn[4]=a1.x; etn[5]=a1.y; etn[6]=a1.z; etn[7]=a1.w;
    }

    float sm[8];
    #pragma unroll
    for (int h = 0; h < 8; h++) sm[h] = 0.f;

    for (int p = beg + lane; p < end; p += 32) {
        int s = g_srcs[p], t = g_ets[p];
        float eh8[8], er8[8], ex[8];
        *(float4*)&eh8[0] = ((const float4*)&g_eh[s * 8])[0];
        *(float4*)&eh8[4] = ((const float4*)&g_eh[s * 8])[1];
        *(float4*)&er8[0] = ((const float4*)&g_er[t * 8])[0];
        *(float4*)&er8[4] = ((const float4*)&g_er[t * 8])[1];
        #pragma unroll
        for (int h = 0; h < 8; h++) {
            float sc = eh8[h] + etn[h] + er8[h];
            sc = sc > 0.f ? sc : SLOPE * sc;
            ex[h] = __expf(sc);
            sm[h] += ex[h];
        }
        float4 o0 = {ex[0], ex[1], ex[2], ex[3]};
        float4 o1 = {ex[4], ex[5], ex[6], ex[7]};
        ((float4*)&g_a[p * 8])[0] = o0;
        ((float4*)&g_a[p * 8])[1] = o1;
    }
    #pragma unroll
    for (int o = 16; o; o >>= 1)
        #pragma unroll
        for (int h = 0; h < 8; h++)
            sm[h] += __shfl_xor_sync(0xffffffffu, sm[h], o);

    if (lane == 0) {
        float inv[8];
        #pragma unroll
        for (int h = 0; h < 8; h++) inv[h] = (sm[h] > 0.f) ? (1.f / sm[h]) : 0.f;
        float4 i0 = {inv[0], inv[1], inv[2], inv[3]};
        float4 i1 = {inv[4], inv[5], inv[6], inv[7]};
        ((float4*)&g_inv[wid * 8])[0] = i0;
        ((float4*)&g_inv[wid * 8])[1] = i1;
    }
}

// ---------------- K5: one diffusion hop (warp per node, bf16 gather) --------
__global__ void __launch_bounds__(256) k_hop(int hop)
{
    const __nv_bfloat16* finb =
        (hop == 0) ? g_f0h : ((hop & 1) ? g_hA : g_hB);
    const uint2* fin = (const uint2*)finb;   // 8 bytes = 4 bf16 per lane
    __nv_bfloat16* foutb = (hop & 1) ? g_hB : g_hA;
    const bool last = (hop == HOPS - 1);

    const int wid  = (blockIdx.x * blockDim.x + threadIdx.x) >> 5;
    const int lane = threadIdx.x & 31;
    if (wid >= NN) return;
    const int beg = g_rowptr[wid], end = g_rowptr[wid + 1];
    const int h = lane >> 2;

    const float invh = g_inv[wid * 8 + h];

    float4 acc = {0.f, 0.f, 0.f, 0.f};
    for (int pb = beg; pb < end; pb += 32) {
        int sl = (pb + lane < end) ? g_srcs[pb + lane] : 0;
        int cnt = min(32, end - pb);
        #pragma unroll 8
        for (int q = 0; q < cnt; q++) {
            int s = __shfl_sync(0xffffffffu, sl, q);
            float av = __ldg(&g_a[(pb + q) * 8 + h]);
            uint2 v = __ldg(&fin[s * 32 + lane]);
            float2 lo = __bfloat1622float2(*(__nv_bfloat162*)&v.x);
            float2 hi = __bfloat1622float2(*(__nv_bfloat162*)&v.y);
            acc.x += av * lo.x; acc.y += av * lo.y;
            acc.z += av * hi.x; acc.w += av * hi.y;
        }
    }

    const float w = (1.f - ALPHA) * invh;
    float4 f0 = ((const float4*)g_feat0)[wid * 32 + lane];
    float4 o;
    o.x = w * acc.x + ALPHA * f0.x;
    o.y = w * acc.y + ALPHA * f0.y;
    o.z = w * acc.z + ALPHA * f0.z;
    o.w = w * acc.w + ALPHA * f0.w;

    if (last) {
        ((float4*)g_fA)[wid * 32 + lane] = o;
    } else {
        __nv_bfloat162 p0 = __float22bfloat162_rn(make_float2(o.x, o.y));
        __nv_bfloat162 p1 = __float22bfloat162_rn(make_float2(o.z, o.w));
        uint2 st;
        st.x = *(unsigned*)&p0;
        st.y = *(unsigned*)&p1;
        ((uint2*)foutb)[wid * 32 + lane] = st;
    }
}

// ---------------- K6: residual + LN2 + FFN + residual (tensor core) ---------
// rst lives in `out` gmem (block-local rows), z in fp16 smem.
// smem = yln f32 64*132 + z half 64*520 = 100352 B -> 2 blocks/SM.
__global__ void __launch_bounds__(256, 2) k_ffn(
    const float* __restrict__ g2, const float* __restrict__ be2,
    const float* __restrict__ bb1, const float* __restrict__ bb2,
    float* __restrict__ out)
{
    extern __shared__ float smem_[];
    float*  yln = smem_;                        // 64*132 f32
    __half* zh  = (__half*)(smem_ + 64 * 132);  // 64*520 half
    const int n0 = blockIdx.x * 64;
    const int tid = threadIdx.x;
    const int wid = tid >> 5, lane = tid & 31;
    const int group = lane >> 2, tig = lane & 3;

    // 1. rst = f + h -> out (scratch; final value written in epilogue)
    for (int i = tid; i < 64 * 128; i += 256) {
        int r = i >> 7, c = i & 127;
        int gr = n0 + r;
        if (gr < NN) out[gr * 128 + c] = g_fA[gr * 128 + c] + g_h[gr * 128 + c];
    }
    __syncthreads();

    // 2. LN2 over rst (read back from out; block-local rows, clamped reads
    //    only touch rows this block wrote)
    #pragma unroll
    for (int rr = 0; rr < 8; rr++) {
        int r = wid * 8 + rr;
        const float* row = &out[(size_t)min(n0 + r, NN - 1) * 128];
        float x[4];
        float s = 0.f, s2 = 0.f;
        #pragma unroll
        for (int k = 0; k < 4; k++) {
            x[k] = row[lane + 32 * k];
            s += x[k]; s2 += x[k] * x[k];
        }
        #pragma unroll
        for (int o = 16; o; o >>= 1) {
            s  += __shfl_xor_sync(0xffffffffu, s, o);
            s2 += __shfl_xor_sync(0xffffffffu, s2, o);
        }
        float mu  = s * (1.f / 128.f);
        float inv = rsqrtf(s2 * (1.f / 128.f) - mu * mu + LNEPS);
        #pragma unroll
        for (int k = 0; k < 4; k++) {
            int c = lane + 32 * k;
            float y = (x[k] - mu) * inv * g2[c] + be2[c];
            yln[r * 132 + c] = __uint_as_float(f2tf(y));
        }
    }
    __syncthreads();

    // 3. GEMM1: z(64x512) = relu(y @ W1 + b1), two 64-wide N phases per warp
    {
        const float* Wu = g_W1r;
        const int m0 = (wid >> 2) * 32;
        const int nwbase = (wid & 3) * 128;
        #pragma unroll
        for (int ph = 0; ph < 2; ph++) {
            const int nw = nwbase + ph * 64;
            float acc[2][8][4];
            #pragma unroll
            for (int mt = 0; mt < 2; mt++)
                #pragma unroll
                for (int nt = 0; nt < 8; nt++)
                    #pragma unroll
                    for (int q = 0; q < 4; q++) acc[mt][nt][q] = 0.f;

            #pragma unroll
            for (int ks = 0; ks < 16; ks++) {
                int k0 = ks * 8;
                unsigned a[2][4];
                #pragma unroll
                for (int mt = 0; mt < 2; mt++) {
                    int rb = m0 + mt * 16 + group;
                    a[mt][0] = __float_as_uint(yln[rb * 132 + k0 + tig]);
                    a[mt][1] = __float_as_uint(yln[(rb + 8) * 132 + k0 + tig]);
                    a[mt][2] = __float_as_uint(yln[rb * 132 + k0 + tig + 4]);
                    a[mt][3] = __float_as_uint(yln[(rb + 8) * 132 + k0 + tig + 4]);
                }
                #pragma unroll
                for (int nt = 0; nt < 8; nt++) {
                    int c = nw + nt * 8 + group;
                    unsigned b0 = __float_as_uint(Wu[(k0 + tig) * 512 + c]);
                    unsigned b1 = __float_as_uint(Wu[(k0 + tig + 4) * 512 + c]);
                    mma_tf32(acc[0][nt], a[0][0], a[0][1], a[0][2], a[0][3], b0, b1);
                    mma_tf32(acc[1][nt], a[1][0], a[1][1], a[1][2], a[1][3], b0, b1);
                }
            }
            #pragma unroll
            for (int mt = 0; mt < 2; mt++)
                #pragma unroll
                for (int nt = 0; nt < 8; nt++) {
                    int r  = m0 + mt * 16 + group;
                    int cc = nw + nt * 8 + 2 * tig;
                    float v0 = fmaxf(acc[mt][nt][0] + bb1[cc], 0.f);
                    float v1 = fmaxf(acc[mt][nt][1] + bb1[cc + 1], 0.f);
                    float v2 = fmaxf(acc[mt][nt][2] + bb1[cc], 0.f);
                    float v3 = fmaxf(acc[mt][nt][3] + bb1[cc + 1], 0.f);
                    *(__half2*)&zh[r * 520 + cc]       = __floats2half2_rn(v0, v1);
                    *(__half2*)&zh[(r + 8) * 520 + cc] = __floats2half2_rn(v2, v3);
                }
        }
    }
    __syncthreads();

    // 4. GEMM2: out = z @ W2 + b2 + rst(out). warp tile 16x64
    {
        const float* Wu = g_W2r;
        const int m0 = (wid >> 1) * 16;
        const int nw = (wid & 1) * 64;
        float acc[8][4];
        #pragma unroll
        for (int nt = 0; nt < 8; nt++)
            #pragma unroll
            for (int q = 0; q < 4; q++) acc[nt][q] = 0.f;

        #pragma unroll 8
        for (int ks = 0; ks < 64; ks++) {
            int k0 = ks * 8;
            unsigned a0 = __float_as_uint(__half2float(zh[(m0 + group) * 520 + k0 + tig]));
            unsigned a1 = __float_as_uint(__half2float(zh[(m0 + group + 8) * 520 + k0 + tig]));
            unsigned a2 = __float_as_uint(__half2float(zh[(m0 + group) * 520 + k0 + tig + 4]));
            unsigned a3 = __float_as_uint(__half2float(zh[(m0 + group + 8) * 520 + k0 + tig + 4]));
            #pragma unroll
            for (int nt = 0; nt < 8; nt++) {
                int c = nw + nt * 8 + group;
                unsigned b0 = __float_as_uint(Wu[(k0 + tig) * 128 + c]);
                unsigned b1 = __float_as_uint(Wu[(k0 + tig + 4) * 128 + c]);
                mma_tf32(acc[nt], a0, a1, a2, a3, b0, b1);
            }
        }
        #pragma unroll
        for (int nt = 0; nt < 8; nt++) {
            int r  = m0 + group;
            int cc = nw + nt * 8 + 2 * tig;
            if (n0 + r < NN) {
                size_t i0 = (size_t)(n0 + r) * 128 + cc;
                out[i0]     = acc[nt][0] + bb2[cc]     + out[i0];
                out[i0 + 1] = acc[nt][1] + bb2[cc + 1] + out[i0 + 1];
            }
            if (n0 + r + 8 < NN) {
                size_t i1 = (size_t)(n0 + r + 8) * 128 + cc;
                out[i1]     = acc[nt][2] + bb2[cc]     + out[i1];
                out[i1 + 1] = acc[nt][3] + bb2[cc + 1] + out[i1 + 1];
            }
        }
    }
}

// ---------------- launch ----------------------------------------------------
extern "C" void kernel_launch(void* const* d_in, const int* in_sizes, int n_in,
                              void* d_out, int out_size)
{
    const float* ent   = (const float*)d_in[0];
    const float* rel   = (const float*)d_in[1];
    const int*   src   = (const int*)  d_in[2];
    const int*   dst   = (const int*)  d_in[3];
    const int*   etp   = (const int*)  d_in[4];
    const float* ln1g  = (const float*)d_in[5];
    const float* ln1b  = (const float*)d_in[6];
    const float* Went  = (const float*)d_in[7];
    const float* Wrel  = (const float*)d_in[8];
    const float* ah    = (const float*)d_in[9];
    const float* at    = (const float*)d_in[10];
    const float* ar    = (const float*)d_in[11];
    const float* ln2g  = (const float*)d_in[12];
    const float* ln2b  = (const float*)d_in[13];
    const float* W1    = (const float*)d_in[14];
    const float* b1    = (const float*)d_in[15];
    const float* W2    = (const float*)d_in[16];
    const float* b2    = (const float*)d_in[17];
    float* out = (float*)d_out;

    static const size_t LN1_SMEM = (2 * 64 * 132) * sizeof(float);                    // 67584
    static const size_t FFN_SMEM = 64 * 132 * sizeof(float) + 64 * 520 * sizeof(__half); // 100352
    cudaFuncSetAttribute(k_ln1_feat, cudaFuncAttributeMaxDynamicSharedMemorySize, (int)LN1_SMEM);
    cudaFuncSetAttribute(k_ffn, cudaFuncAttributeMaxDynamicSharedMemorySize, (int)FFN_SMEM);

    // 1-3: weights, deg init, histogram
    k_rnd3<<<(RND_TOTAL + 255) / 256, 256>>>(Went, W1, W2);
    k_zero<<<(NN + 255) / 256, 256>>>();
    k_hist<<<EE / 256, 256>>>(dst);

    // 4: node projection (profiled slot next round)
    k_ln1_feat<<<(NN + 63) / 64, 256, LN1_SMEM>>>(ent, ln1g, ln1b, ah, at);
    k_rel<<<RR, 128>>>(rel, Wrel, ar);

    // CSR build (parallel scan)
    k_scanA<<<NBLK, SCAN_B>>>();
    k_scanB<<<1, 512>>>();
    k_scanC<<<NBLK, SCAN_B>>>();
    k_scatter<<<EE / 256, 256>>>(src, dst, etp);

    // edge softmax (single pass, unnormalized + inv table)
    k_soft<<<NN / 8, 256>>>();

    // diffusion (bf16 state)
    for (int hop = 0; hop < HOPS; hop++)
        k_hop<<<NN / 8, 256>>>(hop);

    // FFN + residuals
    k_ffn<<<(NN + 63) / 64, 256, FFN_SMEM>>>(ln2g, ln2b, b1, b2, out);
}

// round 12
// speedup vs baseline: 1.9708x; 1.0363x over previous
#include <cuda_runtime.h>
#include <cuda_bf16.h>
#include <cuda_fp16.h>

#define NN   100000
#define EE   1600000
#define RR   500
#define DDIM 128
#define HH   8
#define DHH  16
#define DFFN 512
#define HOPS 5
#define ALPHA 0.15f
#define SLOPE 0.2f
#define LNEPS 1e-5f

#define SCAN_B 256
#define NBLK ((NN + SCAN_B - 1) / SCAN_B)   // 391

// ---------------- scratch (static device globals; no allocation) -------------
__device__ float g_h[NN * DDIM];        // LN1 output
__device__ float g_feat0[NN * DDIM];    // h @ W_ent (fp32 anchor)
__device__ float g_fA[NN * DDIM];       // final hop output (fp32)
__device__ __nv_bfloat16 g_f0h[NN * DDIM];  // feat0 in bf16 (hop-0 input)
__device__ __nv_bfloat16 g_hA[NN * DDIM];   // bf16 ping
__device__ __nv_bfloat16 g_hB[NN * DDIM];   // bf16 pong
__device__ float g_eh[NN * HH];
__device__ float g_et[NN * HH];
__device__ float g_er[RR * HH];
__device__ float g_a[EE * HH];          // UNnormalized exp scores, dst-sorted order
__device__ float g_inv[NN * HH];        // 1/softmax-sum per (node, head)
__device__ int   g_deg[NN];
__device__ int   g_rowptr[NN + 1];
__device__ int   g_cursor[NN];
__device__ int   g_part[512];           // scan partials
__device__ int   g_srcs[EE];            // src, sorted by dst
__device__ int   g_ets[EE];             // e_type, sorted by dst
// TF32-prerounded weights
__device__ float g_Wentr[DDIM * DDIM];
__device__ float g_W1r[DDIM * DFFN];
__device__ float g_W2r[DFFN * DDIM];

// ---------------- mma helpers ------------------------------------------------
__device__ __forceinline__ unsigned f2tf(float f) {
    unsigned u;
    asm("cvt.rna.tf32.f32 %0, %1;" : "=r"(u) : "f"(f));
    return u;
}

__device__ __forceinline__ void mma_tf32(float c[4],
    unsigned a0, unsigned a1, unsigned a2, unsigned a3,
    unsigned b0, unsigned b1)
{
    asm volatile(
        "mma.sync.aligned.m16n8k8.row.col.f32.tf32.tf32.f32 "
        "{%0,%1,%2,%3}, {%4,%5,%6,%7}, {%8,%9}, {%0,%1,%2,%3};"
        : "+f"(c[0]), "+f"(c[1]), "+f"(c[2]), "+f"(c[3])
        : "r"(a0), "r"(a1), "r"(a2), "r"(a3), "r"(b0), "r"(b1));
}

// ---------------- K0: preround all weights to tf32 ---------------------------
#define RND_TOTAL (DDIM * DDIM + DDIM * DFFN + DFFN * DDIM)  // 147456
__global__ void k_rnd3(const float* __restrict__ Went,
                       const float* __restrict__ W1,
                       const float* __restrict__ W2)
{
    int i = blockIdx.x * blockDim.x + threadIdx.x;
    if (i < DDIM * DDIM) {
        g_Wentr[i] = __uint_as_float(f2tf(Went[i]));
    } else if (i < DDIM * DDIM + DDIM * DFFN) {
        int j = i - DDIM * DDIM;
        g_W1r[j] = __uint_as_float(f2tf(W1[j]));
    } else if (i < RND_TOTAL) {
        int j = i - DDIM * DDIM - DDIM * DFFN;
        g_W2r[j] = __uint_as_float(f2tf(W2[j]));
    }
}

// ---------------- K1: LN1 + feat = h@W_ent + eh/et (tensor core) -------------
// smem = 64*132 f32 only (33792 B) -> 4 CTAs/SM. eh/et computed from MMA
// fragments via tig-lane shuffles (no sf buffer, no extra pass).
__global__ void __launch_bounds__(256) k_ln1_feat(
    const float* __restrict__ ent, const float* __restrict__ g1,
    const float* __restrict__ b1,
    const float* __restrict__ ah, const float* __restrict__ at)
{
    extern __shared__ float smem_[];
    float* sh = smem_;               // 64*132 LN output
    const int n0 = blockIdx.x * 64;
    const int tid = threadIdx.x;
    const int wid = tid >> 5, lane = tid & 31;
    const int group = lane >> 2, tig = lane & 3;

    for (int i = tid; i < 64 * 128; i += 256) {
        int r = i >> 7, c = i & 127;
        int gr = min(n0 + r, NN - 1);
        sh[r * 132 + c] = ent[gr * 128 + c];
    }
    __syncthreads();

    #pragma unroll
    for (int rr = 0; rr < 8; rr++) {
        int r = wid * 8 + rr;
        float s = 0.f, s2 = 0.f;
        #pragma unroll
        for (int k = 0; k < 4; k++) {
            float v = sh[r * 132 + lane + 32 * k];
            s += v; s2 += v * v;
        }
        #pragma unroll
        for (int o = 16; o; o >>= 1) {
            s  += __shfl_xor_sync(0xffffffffu, s, o);
            s2 += __shfl_xor_sync(0xffffffffu, s2, o);
        }
        float mu  = s * (1.f / 128.f);
        float inv = rsqrtf(s2 * (1.f / 128.f) - mu * mu + LNEPS);
        #pragma unroll
        for (int k = 0; k < 4; k++) {
            int c = lane + 32 * k;
            sh[r * 132 + c] = (sh[r * 132 + c] - mu) * inv * g1[c] + b1[c];
        }
    }
    __syncthreads();

    for (int i = tid; i < 64 * 128; i += 256) {
        int r = i >> 7, c = i & 127;
        if (n0 + r < NN) g_h[(n0 + r) * 128 + c] = sh[r * 132 + c];
    }

    // GEMM 64x128 = sh(64x128) @ Went(128x128). warp tile 16x64
    const int m0 = (wid >> 1) * 16;
    const int nw = (wid & 1) * 64;
    float acc[8][4];
    {
        const float* Wu = g_Wentr;
        #pragma unroll
        for (int t = 0; t < 8; t++)
            #pragma unroll
            for (int q = 0; q < 4; q++) acc[t][q] = 0.f;

        #pragma unroll
        for (int ks = 0; ks < 16; ks++) {
            int k0 = ks * 8;
            unsigned a0 = f2tf(sh[(m0 + group) * 132 + k0 + tig]);
            unsigned a1 = f2tf(sh[(m0 + group + 8) * 132 + k0 + tig]);
            unsigned a2 = f2tf(sh[(m0 + group) * 132 + k0 + tig + 4]);
            unsigned a3 = f2tf(sh[(m0 + group + 8) * 132 + k0 + tig + 4]);
            #pragma unroll
            for (int nt = 0; nt < 8; nt++) {
                int c = nw + nt * 8 + group;
                unsigned b0 = __float_as_uint(Wu[(k0 + tig) * 128 + c]);
                unsigned b1 = __float_as_uint(Wu[(k0 + tig + 4) * 128 + c]);
                mma_tf32(acc[nt], a0, a1, a2, a3, b0, b1);
            }
        }
    }

    // epilogue 1: feat -> g_feat0 (fp32) + g_f0h (bf16)
    {
        const int r = m0 + group;
        #pragma unroll
        for (int nt = 0; nt < 8; nt++) {
            int cc = nw + nt * 8 + 2 * tig;
            if (n0 + r < NN) {
                g_feat0[(n0 + r) * 128 + cc]     = acc[nt][0];
                g_feat0[(n0 + r) * 128 + cc + 1] = acc[nt][1];
                *(__nv_bfloat162*)&g_f0h[(n0 + r) * 128 + cc] =
                    __float22bfloat162_rn(make_float2(acc[nt][0], acc[nt][1]));
            }
            if (n0 + r + 8 < NN) {
                g_feat0[(n0 + r + 8) * 128 + cc]     = acc[nt][2];
                g_feat0[(n0 + r + 8) * 128 + cc + 1] = acc[nt][3];
                *(__nv_bfloat162*)&g_f0h[(n0 + r + 8) * 128 + cc] =
                    __float22bfloat162_rn(make_float2(acc[nt][2], acc[nt][3]));
            }
        }
    }

    // epilogue 2: eh/et directly from fragments.
    // head hh (local 0..3) covers nt = 2hh, 2hh+1; reduce over tig lanes.
    {
        const int r = m0 + group;
        #pragma unroll
        for (int hh = 0; hh < 4; hh++) {
            float seA = 0.f, seB = 0.f, stA = 0.f, stB = 0.f;
            #pragma unroll
            for (int j = 0; j < 2; j++) {
                int nt = 2 * hh + j;
                int cc = nw + nt * 8 + 2 * tig;
                float ah0 = __ldg(&ah[cc]),     ah1 = __ldg(&ah[cc + 1]);
                float at0 = __ldg(&at[cc]),     at1 = __ldg(&at[cc + 1]);
                seA += acc[nt][0] * ah0 + acc[nt][1] * ah1;
                seB += acc[nt][2] * ah0 + acc[nt][3] * ah1;
                stA += acc[nt][0] * at0 + acc[nt][1] * at1;
                stB += acc[nt][2] * at0 + acc[nt][3] * at1;
            }
            // reduce over the 4 tig lanes (lane = group*4 + tig)
            #pragma unroll
            for (int o = 1; o < 4; o <<= 1) {
                seA += __shfl_xor_sync(0xffffffffu, seA, o);
                seB += __shfl_xor_sync(0xffffffffu, seB, o);
                stA += __shfl_xor_sync(0xffffffffu, stA, o);
                stB += __shfl_xor_sync(0xffffffffu, stB, o);
            }
            if (tig == 0) {
                int hg = (nw >> 4) + hh;   // global head 0..7
                if (n0 + r < NN) {
                    g_eh[(n0 + r) * 8 + hg] = seA;
                    g_et[(n0 + r) * 8 + hg] = stA;
                }
                if (n0 + r + 8 < NN) {
                    g_eh[(n0 + r + 8) * 8 + hg] = seB;
                    g_et[(n0 + r + 8) * 8 + hg] = stB;
                }
            }
        }
    }
}

// ---------------- K2: er per relation ---------------------------------------
__global__ void k_rel(const float* __restrict__ rel,
                      const float* __restrict__ Wrel,
                      const float* __restrict__ ar)
{
    __shared__ float srow[128];
    const int r = blockIdx.x, k = threadIdx.x;
    srow[k] = rel[r * 128 + k];
    __syncthreads();
    float acc = 0.f;
    for (int j = 0; j < 128; j++) acc += srow[j] * Wrel[j * 128 + k];
    float v = acc * ar[k];
    #pragma unroll
    for (int o = 8; o; o >>= 1) v += __shfl_xor_sync(0xffffffffu, v, o);
    if ((k & 15) == 0) g_er[r * 8 + (k >> 4)] = v;
}

// ---------------- CSR build -------------------------------------------------
__global__ void k_zero() {
    int i = blockIdx.x * blockDim.x + threadIdx.x;
    if (i < NN) g_deg[i] = 0;
}

__global__ void k_hist(const int* __restrict__ dst) {
    int e = blockIdx.x * blockDim.x + threadIdx.x;
    if (e < EE) atomicAdd(&g_deg[dst[e]], 1);
}

__global__ void __launch_bounds__(SCAN_B) k_scanA() {
    __shared__ int red[SCAN_B / 32];
    const int t = threadIdx.x;
    const int i = blockIdx.x * SCAN_B + t;
    int v = (i < NN) ? g_deg[i] : 0;
    int s = v;
    #pragma unroll
    for (int o = 16; o; o >>= 1) s += __shfl_xor_sync(0xffffffffu, s, o);
    if ((t & 31) == 0) red[t >> 5] = s;
    __syncthreads();
    if (t < 32) {
        int x = (t < SCAN_B / 32) ? red[t] : 0;
        #pragma unroll
        for (int o = 16; o; o >>= 1) x += __shfl_xor_sync(0xffffffffu, x, o);
        if (t == 0) g_part[blockIdx.x] = x;
    }
}

__global__ void __launch_bounds__(512) k_scanB() {
    __shared__ int sp[512];
    const int t = threadIdx.x;
    int v = (t < NBLK) ? g_part[t] : 0;
    sp[t] = v;
    __syncthreads();
    for (int off = 1; off < 512; off <<= 1) {
        int x = (t >= off) ? sp[t - off] : 0;
        __syncthreads();
        sp[t] += x;
        __syncthreads();
    }
    if (t < NBLK) g_part[t] = sp[t] - v;   // exclusive
}

__global__ void __launch_bounds__(SCAN_B) k_scanC() {
    __shared__ int sp[SCAN_B];
    const int t = threadIdx.x;
    const int i = blockIdx.x * SCAN_B + t;
    const int base = g_part[blockIdx.x];
    int v = (i < NN) ? g_deg[i] : 0;
    sp[t] = v;
    __syncthreads();
    for (int off = 1; off < SCAN_B; off <<= 1) {
        int x = (t >= off) ? sp[t - off] : 0;
        __syncthreads();
        sp[t] += x;
        __syncthreads();
    }
    if (i < NN) {
        int excl = base + sp[t] - v;
        g_rowptr[i] = excl;
        g_cursor[i] = excl;
    }
    if (i == NN - 1) g_rowptr[NN] = EE;
}

__global__ void k_scatter(const int* __restrict__ src,
                          const int* __restrict__ dst,
                          const int* __restrict__ etp)
{
    int e = blockIdx.x * blockDim.x + threadIdx.x;
    if (e < EE) {
        int p = atomicAdd(&g_cursor[dst[e]], 1);
        g_srcs[p] = src[e];
        g_ets[p]  = etp[e];
    }
}

// ---------------- K4: edge softmax, SINGLE pass (scores are small;
// softmax without max-shift is mathematically identical and fp-safe here) ----
__global__ void __launch_bounds__(256) k_soft()
{
    const int wid  = (blockIdx.x * blockDim.x + threadIdx.x) >> 5;
    const int lane = threadIdx.x & 31;
    if (wid >= NN) return;
    const int beg = g_rowptr[wid], end = g_rowptr[wid + 1];

    float etn[8];
    {
        const float4* p = (const float4*)&g_et[wid * 8];
        float4 a0 = p[0], a1 = p[1];
        etn[0]=a0.x; etn[1]=a0.y; etn[2]=a0.z; etn[3]=a0.w;
        etn[4]=a1.x; etn[5]=a1.y; etn[6]=a1.z; etn[7]=a1.w;
    }

    float sm[8];
    #pragma unroll
    for (int h = 0; h < 8; h++) sm[h] = 0.f;

    for (int p = beg + lane; p < end; p += 32) {
        int s = g_srcs[p], t = g_ets[p];
        float eh8[8], er8[8], ex[8];
        *(float4*)&eh8[0] = ((const float4*)&g_eh[s * 8])[0];
        *(float4*)&eh8[4] = ((const float4*)&g_eh[s * 8])[1];
        *(float4*)&er8[0] = ((const float4*)&g_er[t * 8])[0];
        *(float4*)&er8[4] = ((const float4*)&g_er[t * 8])[1];
        #pragma unroll
        for (int h = 0; h < 8; h++) {
            float sc = eh8[h] + etn[h] + er8[h];
            sc = sc > 0.f ? sc : SLOPE * sc;
            ex[h] = __expf(sc);
            sm[h] += ex[h];
        }
        float4 o0 = {ex[0], ex[1], ex[2], ex[3]};
        float4 o1 = {ex[4], ex[5], ex[6], ex[7]};
        ((float4*)&g_a[p * 8])[0] = o0;
        ((float4*)&g_a[p * 8])[1] = o1;
    }
    #pragma unroll
    for (int o = 16; o; o >>= 1)
        #pragma unroll
        for (int h = 0; h < 8; h++)
            sm[h] += __shfl_xor_sync(0xffffffffu, sm[h], o);

    if (lane == 0) {
        float inv[8];
        #pragma unroll
        for (int h = 0; h < 8; h++) inv[h] = (sm[h] > 0.f) ? (1.f / sm[h]) : 0.f;
        float4 i0 = {inv[0], inv[1], inv[2], inv[3]};
        float4 i1 = {inv[4], inv[5], inv[6], inv[7]};
        ((float4*)&g_inv[wid * 8])[0] = i0;
        ((float4*)&g_inv[wid * 8])[1] = i1;
    }
}

// ---------------- K5: one diffusion hop (warp per node, bf16 gather) --------
__global__ void __launch_bounds__(256) k_hop(int hop)
{
    const __nv_bfloat16* finb =
        (hop == 0) ? g_f0h : ((hop & 1) ? g_hA : g_hB);
    const uint2* fin = (const uint2*)finb;   // 8 bytes = 4 bf16 per lane
    __nv_bfloat16* foutb = (hop & 1) ? g_hB : g_hA;
    const bool last = (hop == HOPS - 1);

    const int wid  = (blockIdx.x * blockDim.x + threadIdx.x) >> 5;
    const int lane = threadIdx.x & 31;
    if (wid >= NN) return;
    const int beg = g_rowptr[wid], end = g_rowptr[wid + 1];
    const int h = lane >> 2;

    const float invh = g_inv[wid * 8 + h];

    float4 acc = {0.f, 0.f, 0.f, 0.f};
    for (int pb = beg; pb < end; pb += 32) {
        int sl = (pb + lane < end) ? g_srcs[pb + lane] : 0;
        int cnt = min(32, end - pb);
        #pragma unroll 8
        for (int q = 0; q < cnt; q++) {
            int s = __shfl_sync(0xffffffffu, sl, q);
            float av = __ldg(&g_a[(pb + q) * 8 + h]);
            uint2 v = __ldg(&fin[s * 32 + lane]);
            float2 lo = __bfloat1622float2(*(__nv_bfloat162*)&v.x);
            float2 hi = __bfloat1622float2(*(__nv_bfloat162*)&v.y);
            acc.x += av * lo.x; acc.y += av * lo.y;
            acc.z += av * hi.x; acc.w += av * hi.y;
        }
    }

    const float w = (1.f - ALPHA) * invh;
    float4 f0 = ((const float4*)g_feat0)[wid * 32 + lane];
    float4 o;
    o.x = w * acc.x + ALPHA * f0.x;
    o.y = w * acc.y + ALPHA * f0.y;
    o.z = w * acc.z + ALPHA * f0.z;
    o.w = w * acc.w + ALPHA * f0.w;

    if (last) {
        ((float4*)g_fA)[wid * 32 + lane] = o;
    } else {
        __nv_bfloat162 p0 = __float22bfloat162_rn(make_float2(o.x, o.y));
        __nv_bfloat162 p1 = __float22bfloat162_rn(make_float2(o.z, o.w));
        uint2 st;
        st.x = *(unsigned*)&p0;
        st.y = *(unsigned*)&p1;
        ((uint2*)foutb)[wid * 32 + lane] = st;
    }
}

// ---------------- K6: residual + LN2 + FFN + residual (tensor core) ---------
// rst lives in `out` gmem (block-local rows), z in fp16 smem.
// smem = yln f32 64*132 + z half 64*520 = 100352 B -> 2 blocks/SM.
__global__ void __launch_bounds__(256, 2) k_ffn(
    const float* __restrict__ g2, const float* __restrict__ be2,
    const float* __restrict__ bb1, const float* __restrict__ bb2,
    float* __restrict__ out)
{
    extern __shared__ float smem_[];
    float*  yln = smem_;                        // 64*132 f32
    __half* zh  = (__half*)(smem_ + 64 * 132);  // 64*520 half
    const int n0 = blockIdx.x * 64;
    const int tid = threadIdx.x;
    const int wid = tid >> 5, lane = tid & 31;
    const int group = lane >> 2, tig = lane & 3;

    // 1. rst = f + h -> out (scratch; final value written in epilogue)
    for (int i = tid; i < 64 * 128; i += 256) {
        int r = i >> 7, c = i & 127;
        int gr = n0 + r;
        if (gr < NN) out[gr * 128 + c] = g_fA[gr * 128 + c] + g_h[gr * 128 + c];
    }
    __syncthreads();

    // 2. LN2 over rst (read back from out; block-local rows, clamped reads
    //    only touch rows this block wrote)
    #pragma unroll
    for (int rr = 0; rr < 8; rr++) {
        int r = wid * 8 + rr;
        const float* row = &out[(size_t)min(n0 + r, NN - 1) * 128];
        float x[4];
        float s = 0.f, s2 = 0.f;
        #pragma unroll
        for (int k = 0; k < 4; k++) {
            x[k] = row[lane + 32 * k];
            s += x[k]; s2 += x[k] * x[k];
        }
        #pragma unroll
        for (int o = 16; o; o >>= 1) {
            s  += __shfl_xor_sync(0xffffffffu, s, o);
            s2 += __shfl_xor_sync(0xffffffffu, s2, o);
        }
        float mu  = s * (1.f / 128.f);
        float inv = rsqrtf(s2 * (1.f / 128.f) - mu * mu + LNEPS);
        #pragma unroll
        for (int k = 0; k < 4; k++) {
            int c = lane + 32 * k;
            float y = (x[k] - mu) * inv * g2[c] + be2[c];
            yln[r * 132 + c] = __uint_as_float(f2tf(y));
        }
    }
    __syncthreads();

    // 3. GEMM1: z(64x512) = relu(y @ W1 + b1), two 64-wide N phases per warp
    {
        const float* Wu = g_W1r;
        const int m0 = (wid >> 2) * 32;
        const int nwbase = (wid & 3) * 128;
        #pragma unroll
        for (int ph = 0; ph < 2; ph++) {
            const int nw = nwbase + ph * 64;
            float acc[2][8][4];
            #pragma unroll
            for (int mt = 0; mt < 2; mt++)
                #pragma unroll
                for (int nt = 0; nt < 8; nt++)
                    #pragma unroll
                    for (int q = 0; q < 4; q++) acc[mt][nt][q] = 0.f;

            #pragma unroll
            for (int ks = 0; ks < 16; ks++) {
                int k0 = ks * 8;
                unsigned a[2][4];
                #pragma unroll
                for (int mt = 0; mt < 2; mt++) {
                    int rb = m0 + mt * 16 + group;
                    a[mt][0] = __float_as_uint(yln[rb * 132 + k0 + tig]);
                    a[mt][1] = __float_as_uint(yln[(rb + 8) * 132 + k0 + tig]);
                    a[mt][2] = __float_as_uint(yln[rb * 132 + k0 + tig + 4]);
                    a[mt][3] = __float_as_uint(yln[(rb + 8) * 132 + k0 + tig + 4]);
                }
                #pragma unroll
                for (int nt = 0; nt < 8; nt++) {
                    int c = nw + nt * 8 + group;
                    unsigned b0 = __float_as_uint(Wu[(k0 + tig) * 512 + c]);
                    unsigned b1 = __float_as_uint(Wu[(k0 + tig + 4) * 512 + c]);
                    mma_tf32(acc[0][nt], a[0][0], a[0][1], a[0][2], a[0][3], b0, b1);
                    mma_tf32(acc[1][nt], a[1][0], a[1][1], a[1][2], a[1][3], b0, b1);
                }
            }
            #pragma unroll
            for (int mt = 0; mt < 2; mt++)
                #pragma unroll
                for (int nt = 0; nt < 8; nt++) {
                    int r  = m0 + mt * 16 + group;
                    int cc = nw + nt * 8 + 2 * tig;
                    float v0 = fmaxf(acc[mt][nt][0] + bb1[cc], 0.f);
                    float v1 = fmaxf(acc[mt][nt][1] + bb1[cc + 1], 0.f);
                    float v2 = fmaxf(acc[mt][nt][2] + bb1[cc], 0.f);
                    float v3 = fmaxf(acc[mt][nt][3] + bb1[cc + 1], 0.f);
                    *(__half2*)&zh[r * 520 + cc]       = __floats2half2_rn(v0, v1);
                    *(__half2*)&zh[(r + 8) * 520 + cc] = __floats2half2_rn(v2, v3);
                }
        }
    }
    __syncthreads();

    // 4. GEMM2: out = z @ W2 + b2 + rst(out). warp tile 16x64
    {
        const float* Wu = g_W2r;
        const int m0 = (wid >> 1) * 16;
        const int nw = (wid & 1) * 64;
        float acc[8][4];
        #pragma unroll
        for (int nt = 0; nt < 8; nt++)
            #pragma unroll
            for (int q = 0; q < 4; q++) acc[nt][q] = 0.f;

        #pragma unroll 8
        for (int ks = 0; ks < 64; ks++) {
            int k0 = ks * 8;
            unsigned a0 = __float_as_uint(__half2float(zh[(m0 + group) * 520 + k0 + tig]));
            unsigned a1 = __float_as_uint(__half2float(zh[(m0 + group + 8) * 520 + k0 + tig]));
            unsigned a2 = __float_as_uint(__half2float(zh[(m0 + group) * 520 + k0 + tig + 4]));
            unsigned a3 = __float_as_uint(__half2float(zh[(m0 + group + 8) * 520 + k0 + tig + 4]));
            #pragma unroll
            for (int nt = 0; nt < 8; nt++) {
                int c = nw + nt * 8 + group;
                unsigned b0 = __float_as_uint(Wu[(k0 + tig) * 128 + c]);
                unsigned b1 = __float_as_uint(Wu[(k0 + tig + 4) * 128 + c]);
                mma_tf32(acc[nt], a0, a1, a2, a3, b0, b1);
            }
        }
        #pragma unroll
        for (int nt = 0; nt < 8; nt++) {
            int r  = m0 + group;
            int cc = nw + nt * 8 + 2 * tig;
            if (n0 + r < NN) {
                size_t i0 = (size_t)(n0 + r) * 128 + cc;
                out[i0]     = acc[nt][0] + bb2[cc]     + out[i0];
                out[i0 + 1] = acc[nt][1] + bb2[cc + 1] + out[i0 + 1];
            }
            if (n0 + r + 8 < NN) {
                size_t i1 = (size_t)(n0 + r + 8) * 128 + cc;
                out[i1]     = acc[nt][2] + bb2[cc]     + out[i1];
                out[i1 + 1] = acc[nt][3] + bb2[cc + 1] + out[i1 + 1];
            }
        }
    }
}

// ---------------- launch ----------------------------------------------------
extern "C" void kernel_launch(void* const* d_in, const int* in_sizes, int n_in,
                              void* d_out, int out_size)
{
    const float* ent   = (const float*)d_in[0];
    const float* rel   = (const float*)d_in[1];
    const int*   src   = (const int*)  d_in[2];
    const int*   dst   = (const int*)  d_in[3];
    const int*   etp   = (const int*)  d_in[4];
    const float* ln1g  = (const float*)d_in[5];
    const float* ln1b  = (const float*)d_in[6];
    const float* Went  = (const float*)d_in[7];
    const float* Wrel  = (const float*)d_in[8];
    const float* ah    = (const float*)d_in[9];
    const float* at    = (const float*)d_in[10];
    const float* ar    = (const float*)d_in[11];
    const float* ln2g  = (const float*)d_in[12];
    const float* ln2b  = (const float*)d_in[13];
    const float* W1    = (const float*)d_in[14];
    const float* b1    = (const float*)d_in[15];
    const float* W2    = (const float*)d_in[16];
    const float* b2    = (const float*)d_in[17];
    float* out = (float*)d_out;

    static const size_t LN1_SMEM = (64 * 132) * sizeof(float);                        // 33792
    static const size_t FFN_SMEM = 64 * 132 * sizeof(float) + 64 * 520 * sizeof(__half); // 100352
    cudaFuncSetAttribute(k_ln1_feat, cudaFuncAttributeMaxDynamicSharedMemorySize, (int)LN1_SMEM);
    cudaFuncSetAttribute(k_ffn, cudaFuncAttributeMaxDynamicSharedMemorySize, (int)FFN_SMEM);

    // 1-3: weights, deg init, histogram
    k_rnd3<<<(RND_TOTAL + 255) / 256, 256>>>(Went, W1, W2);
    k_zero<<<(NN + 255) / 256, 256>>>();
    k_hist<<<EE / 256, 256>>>(dst);

    // 4: node projection (profiled slot)
    k_ln1_feat<<<(NN + 63) / 64, 256, LN1_SMEM>>>(ent, ln1g, ln1b, ah, at);
    k_rel<<<RR, 128>>>(rel, Wrel, ar);

    // CSR build (parallel scan)
    k_scanA<<<NBLK, SCAN_B>>>();
    k_scanB<<<1, 512>>>();
    k_scanC<<<NBLK, SCAN_B>>>();
    k_scatter<<<EE / 256, 256>>>(src, dst, etp);

    // edge softmax (single pass, unnormalized + inv table)
    k_soft<<<NN / 8, 256>>>();

    // diffusion (bf16 state)
    for (int hop = 0; hop < HOPS; hop++)
        k_hop<<<NN / 8, 256>>>(hop);

    // FFN + residuals
    k_ffn<<<(NN + 63) / 64, 256, FFN_SMEM>>>(ln2g, ln2b, b1, b2, out);
}

// round 13
// speedup vs baseline: 2.2894x; 1.1617x over previous
#include <cuda_runtime.h>
#include <cuda_bf16.h>
#include <cuda_fp16.h>

#define NN   100000
#define EE   1600000
#define RR   500
#define DDIM 128
#define HH   8
#define DHH  16
#define DFFN 512
#define HOPS 5
#define ALPHA 0.15f
#define SLOPE 0.2f
#define LNEPS 1e-5f

#define SCAN_B 256
#define NBLK ((NN + SCAN_B - 1) / SCAN_B)   // 391

// ---------------- scratch (static device globals; no allocation) -------------
__device__ float g_h[NN * DDIM];        // LN1 output
__device__ float g_feat0[NN * DDIM];    // h @ W_ent (fp32 anchor)
__device__ float g_fA[NN * DDIM];       // final hop output (fp32)
__device__ __nv_bfloat16 g_f0h[NN * DDIM];  // feat0 in bf16 (hop-0 input)
__device__ __nv_bfloat16 g_hA[NN * DDIM];   // bf16 ping
__device__ __nv_bfloat16 g_hB[NN * DDIM];   // bf16 pong
__device__ float g_eh[NN * HH];
__device__ float g_et[NN * HH];
__device__ float g_er[RR * HH];
__device__ float g_a[EE * HH];          // UNnormalized exp scores, dst-sorted order
__device__ float g_inv[NN * HH];        // 1/softmax-sum per (node, head)
__device__ int   g_deg[NN];
__device__ int   g_rowptr[NN + 1];
__device__ int   g_cursor[NN];
__device__ int   g_part[512];           // scan partials
__device__ int   g_srcs[EE];            // src, sorted by dst
__device__ int   g_ets[EE];             // e_type, sorted by dst
// fp16 weights, k-pair packed: Wp[k/2][c] = {W[2k'][c], W[2k'+1][c]}
__device__ unsigned g_Wenth[(DDIM / 2) * DDIM];   // 8192
__device__ unsigned g_W1h[(DDIM / 2) * DFFN];     // 32768
__device__ unsigned g_W2h[(DFFN / 2) * DDIM];     // 32768

// ---------------- mma helper (fp16 m16n8k16, fp32 accum) ---------------------
__device__ __forceinline__ void mma_f16(float c[4],
    unsigned a0, unsigned a1, unsigned a2, unsigned a3,
    unsigned b0, unsigned b1)
{
    asm volatile(
        "mma.sync.aligned.m16n8k16.row.col.f32.f16.f16.f32 "
        "{%0,%1,%2,%3}, {%4,%5,%6,%7}, {%8,%9}, {%0,%1,%2,%3};"
        : "+f"(c[0]), "+f"(c[1]), "+f"(c[2]), "+f"(c[3])
        : "r"(a0), "r"(a1), "r"(a2), "r"(a3), "r"(b0), "r"(b1));
}

__device__ __forceinline__ unsigned packh2(float lo, float hi) {
    __half2 h = __floats2half2_rn(lo, hi);
    return *(unsigned*)&h;
}

// ---------------- K0: convert + k-pair-pack all weights to fp16 --------------
#define CVT_W0 ((DDIM / 2) * DDIM)                 // 8192
#define CVT_W1 ((DDIM / 2) * DFFN)                 // 32768
#define CVT_W2 ((DFFN / 2) * DDIM)                 // 32768
#define CVT_TOTAL (CVT_W0 + CVT_W1 + CVT_W2)       // 73728
__global__ void k_cvt(const float* __restrict__ Went,
                      const float* __restrict__ W1,
                      const float* __restrict__ W2)
{
    int i = blockIdx.x * blockDim.x + threadIdx.x;
    if (i < CVT_W0) {
        int k2 = i >> 7, c = i & 127;
        g_Wenth[i] = packh2(Went[(2 * k2) * 128 + c], Went[(2 * k2 + 1) * 128 + c]);
    } else if (i < CVT_W0 + CVT_W1) {
        int j = i - CVT_W0;
        int k2 = j >> 9, c = j & 511;
        g_W1h[j] = packh2(W1[(2 * k2) * 512 + c], W1[(2 * k2 + 1) * 512 + c]);
    } else if (i < CVT_TOTAL) {
        int j = i - CVT_W0 - CVT_W1;
        int k2 = j >> 7, c = j & 127;
        g_W2h[j] = packh2(W2[(2 * k2) * 128 + c], W2[(2 * k2 + 1) * 128 + c]);
    }
}

// ---------------- K1: LN1 + feat = h@W_ent + eh/et (fp16 tensor core) --------
// smem: sh fp32 64*132 (LN scratch) + yh half 64*132 = 50688 B -> 4 CTAs/SM.
__global__ void __launch_bounds__(256) k_ln1_feat(
    const float* __restrict__ ent, const float* __restrict__ g1,
    const float* __restrict__ b1,
    const float* __restrict__ ah, const float* __restrict__ at)
{
    extern __shared__ float smem_[];
    float*  sh = smem_;                       // 64*132 f32 raw ent
    __half* yh = (__half*)(smem_ + 64 * 132); // 64*132 half LN output
    const int n0 = blockIdx.x * 64;
    const int tid = threadIdx.x;
    const int wid = tid >> 5, lane = tid & 31;
    const int group = lane >> 2, tig = lane & 3;

    for (int i = tid; i < 64 * 128; i += 256) {
        int r = i >> 7, c = i & 127;
        int gr = min(n0 + r, NN - 1);
        sh[r * 132 + c] = ent[gr * 128 + c];
    }
    __syncthreads();

    // LN: read sh, write fp32 y -> g_h and half y -> yh
    #pragma unroll
    for (int rr = 0; rr < 8; rr++) {
        int r = wid * 8 + rr;
        float s = 0.f, s2 = 0.f;
        float x[4];
        #pragma unroll
        for (int k = 0; k < 4; k++) {
            x[k] = sh[r * 132 + lane + 32 * k];
            s += x[k]; s2 += x[k] * x[k];
        }
        #pragma unroll
        for (int o = 16; o; o >>= 1) {
            s  += __shfl_xor_sync(0xffffffffu, s, o);
            s2 += __shfl_xor_sync(0xffffffffu, s2, o);
        }
        float mu  = s * (1.f / 128.f);
        float inv = rsqrtf(s2 * (1.f / 128.f) - mu * mu + LNEPS);
        #pragma unroll
        for (int k = 0; k < 4; k++) {
            int c = lane + 32 * k;
            float y = (x[k] - mu) * inv * g1[c] + b1[c];
            yh[r * 132 + c] = __float2half(y);
            if (n0 + r < NN) g_h[(n0 + r) * 128 + c] = y;
        }
    }
    __syncthreads();

    // GEMM 64x128 = y(64x128) @ Went(128x128), fp16 k16. warp tile 16x64
    const int m0 = (wid >> 1) * 16;
    const int nw = (wid & 1) * 64;
    float acc[8][4];
    {
        #pragma unroll
        for (int t = 0; t < 8; t++)
            #pragma unroll
            for (int q = 0; q < 4; q++) acc[t][q] = 0.f;

        #pragma unroll
        for (int ks = 0; ks < 8; ks++) {
            int k0 = ks * 16, kh = ks * 8;
            unsigned a0 = *(unsigned*)&yh[(m0 + group) * 132 + k0 + 2 * tig];
            unsigned a1 = *(unsigned*)&yh[(m0 + group + 8) * 132 + k0 + 2 * tig];
            unsigned a2 = *(unsigned*)&yh[(m0 + group) * 132 + k0 + 2 * tig + 8];
            unsigned a3 = *(unsigned*)&yh[(m0 + group + 8) * 132 + k0 + 2 * tig + 8];
            #pragma unroll
            for (int nt = 0; nt < 8; nt++) {
                int c = nw + nt * 8 + group;
                unsigned b0 = g_Wenth[(kh + tig) * 128 + c];
                unsigned b1 = g_Wenth[(kh + tig + 4) * 128 + c];
                mma_f16(acc[nt], a0, a1, a2, a3, b0, b1);
            }
        }
    }

    // epilogue 1: feat -> g_feat0 (fp32) + g_f0h (bf16)
    {
        const int r = m0 + group;
        #pragma unroll
        for (int nt = 0; nt < 8; nt++) {
            int cc = nw + nt * 8 + 2 * tig;
            if (n0 + r < NN) {
                g_feat0[(n0 + r) * 128 + cc]     = acc[nt][0];
                g_feat0[(n0 + r) * 128 + cc + 1] = acc[nt][1];
                *(__nv_bfloat162*)&g_f0h[(n0 + r) * 128 + cc] =
                    __float22bfloat162_rn(make_float2(acc[nt][0], acc[nt][1]));
            }
            if (n0 + r + 8 < NN) {
                g_feat0[(n0 + r + 8) * 128 + cc]     = acc[nt][2];
                g_feat0[(n0 + r + 8) * 128 + cc + 1] = acc[nt][3];
                *(__nv_bfloat162*)&g_f0h[(n0 + r + 8) * 128 + cc] =
                    __float22bfloat162_rn(make_float2(acc[nt][2], acc[nt][3]));
            }
        }
    }

    // epilogue 2: eh/et directly from fragments (tig-lane reduce)
    {
        const int r = m0 + group;
        #pragma unroll
        for (int hh = 0; hh < 4; hh++) {
            float seA = 0.f, seB = 0.f, stA = 0.f, stB = 0.f;
            #pragma unroll
            for (int j = 0; j < 2; j++) {
                int nt = 2 * hh + j;
                int cc = nw + nt * 8 + 2 * tig;
                float ah0 = __ldg(&ah[cc]),     ah1 = __ldg(&ah[cc + 1]);
                float at0 = __ldg(&at[cc]),     at1 = __ldg(&at[cc + 1]);
                seA += acc[nt][0] * ah0 + acc[nt][1] * ah1;
                seB += acc[nt][2] * ah0 + acc[nt][3] * ah1;
                stA += acc[nt][0] * at0 + acc[nt][1] * at1;
                stB += acc[nt][2] * at0 + acc[nt][3] * at1;
            }
            #pragma unroll
            for (int o = 1; o < 4; o <<= 1) {
                seA += __shfl_xor_sync(0xffffffffu, seA, o);
                seB += __shfl_xor_sync(0xffffffffu, seB, o);
                stA += __shfl_xor_sync(0xffffffffu, stA, o);
                stB += __shfl_xor_sync(0xffffffffu, stB, o);
            }
            if (tig == 0) {
                int hg = (nw >> 4) + hh;
                if (n0 + r < NN) {
                    g_eh[(n0 + r) * 8 + hg] = seA;
                    g_et[(n0 + r) * 8 + hg] = stA;
                }
                if (n0 + r + 8 < NN) {
                    g_eh[(n0 + r + 8) * 8 + hg] = seB;
                    g_et[(n0 + r + 8) * 8 + hg] = stB;
                }
            }
        }
    }
}

// ---------------- K2: er per relation ---------------------------------------
__global__ void k_rel(const float* __restrict__ rel,
                      const float* __restrict__ Wrel,
                      const float* __restrict__ ar)
{
    __shared__ float srow[128];
    const int r = blockIdx.x, k = threadIdx.x;
    srow[k] = rel[r * 128 + k];
    __syncthreads();
    float acc = 0.f;
    for (int j = 0; j < 128; j++) acc += srow[j] * Wrel[j * 128 + k];
    float v = acc * ar[k];
    #pragma unroll
    for (int o = 8; o; o >>= 1) v += __shfl_xor_sync(0xffffffffu, v, o);
    if ((k & 15) == 0) g_er[r * 8 + (k >> 4)] = v;
}

// ---------------- CSR build -------------------------------------------------
__global__ void k_zero() {
    int i = blockIdx.x * blockDim.x + threadIdx.x;
    if (i < NN) g_deg[i] = 0;
}

__global__ void k_hist(const int* __restrict__ dst) {
    int e = blockIdx.x * blockDim.x + threadIdx.x;
    if (e < EE) atomicAdd(&g_deg[dst[e]], 1);
}

__global__ void __launch_bounds__(SCAN_B) k_scanA() {
    __shared__ int red[SCAN_B / 32];
    const int t = threadIdx.x;
    const int i = blockIdx.x * SCAN_B + t;
    int v = (i < NN) ? g_deg[i] : 0;
    int s = v;
    #pragma unroll
    for (int o = 16; o; o >>= 1) s += __shfl_xor_sync(0xffffffffu, s, o);
    if ((t & 31) == 0) red[t >> 5] = s;
    __syncthreads();
    if (t < 32) {
        int x = (t < SCAN_B / 32) ? red[t] : 0;
        #pragma unroll
        for (int o = 16; o; o >>= 1) x += __shfl_xor_sync(0xffffffffu, x, o);
        if (t == 0) g_part[blockIdx.x] = x;
    }
}

__global__ void __launch_bounds__(512) k_scanB() {
    __shared__ int sp[512];
    const int t = threadIdx.x;
    int v = (t < NBLK) ? g_part[t] : 0;
    sp[t] = v;
    __syncthreads();
    for (int off = 1; off < 512; off <<= 1) {
        int x = (t >= off) ? sp[t - off] : 0;
        __syncthreads();
        sp[t] += x;
        __syncthreads();
    }
    if (t < NBLK) g_part[t] = sp[t] - v;   // exclusive
}

__global__ void __launch_bounds__(SCAN_B) k_scanC() {
    __shared__ int sp[SCAN_B];
    const int t = threadIdx.x;
    const int i = blockIdx.x * SCAN_B + t;
    const int base = g_part[blockIdx.x];
    int v = (i < NN) ? g_deg[i] : 0;
    sp[t] = v;
    __syncthreads();
    for (int off = 1; off < SCAN_B; off <<= 1) {
        int x = (t >= off) ? sp[t - off] : 0;
        __syncthreads();
        sp[t] += x;
        __syncthreads();
    }
    if (i < NN) {
        int excl = base + sp[t] - v;
        g_rowptr[i] = excl;
        g_cursor[i] = excl;
    }
    if (i == NN - 1) g_rowptr[NN] = EE;
}

__global__ void k_scatter(const int* __restrict__ src,
                          const int* __restrict__ dst,
                          const int* __restrict__ etp)
{
    int e = blockIdx.x * blockDim.x + threadIdx.x;
    if (e < EE) {
        int p = atomicAdd(&g_cursor[dst[e]], 1);
        g_srcs[p] = src[e];
        g_ets[p]  = etp[e];
    }
}

// ---------------- K4: edge softmax, SINGLE pass ------------------------------
__global__ void __launch_bounds__(256) k_soft()
{
    const int wid  = (blockIdx.x * blockDim.x + threadIdx.x) >> 5;
    const int lane = threadIdx.x & 31;
    if (wid >= NN) return;
    const int beg = g_rowptr[wid], end = g_rowptr[wid + 1];

    float etn[8];
    {
        const float4* p = (const float4*)&g_et[wid * 8];
        float4 a0 = p[0], a1 = p[1];
        etn[0]=a0.x; etn[1]=a0.y; etn[2]=a0.z; etn[3]=a0.w;
        etn[4]=a1.x; etn[5]=a1.y; etn[6]=a1.z; etn[7]=a1.w;
    }

    float sm[8];
    #pragma unroll
    for (int h = 0; h < 8; h++) sm[h] = 0.f;

    for (int p = beg + lane; p < end; p += 32) {
        int s = g_srcs[p], t = g_ets[p];
        float eh8[8], er8[8], ex[8];
        *(float4*)&eh8[0] = ((const float4*)&g_eh[s * 8])[0];
        *(float4*)&eh8[4] = ((const float4*)&g_eh[s * 8])[1];
        *(float4*)&er8[0] = ((const float4*)&g_er[t * 8])[0];
        *(float4*)&er8[4] = ((const float4*)&g_er[t * 8])[1];
        #pragma unroll
        for (int h = 0; h < 8; h++) {
            float sc = eh8[h] + etn[h] + er8[h];
            sc = sc > 0.f ? sc : SLOPE * sc;
            ex[h] = __expf(sc);
            sm[h] += ex[h];
        }
        float4 o0 = {ex[0], ex[1], ex[2], ex[3]};
        float4 o1 = {ex[4], ex[5], ex[6], ex[7]};
        ((float4*)&g_a[p * 8])[0] = o0;
        ((float4*)&g_a[p * 8])[1] = o1;
    }
    #pragma unroll
    for (int o = 16; o; o >>= 1)
        #pragma unroll
        for (int h = 0; h < 8; h++)
            sm[h] += __shfl_xor_sync(0xffffffffu, sm[h], o);

    if (lane == 0) {
        float inv[8];
        #pragma unroll
        for (int h = 0; h < 8; h++) inv[h] = (sm[h] > 0.f) ? (1.f / sm[h]) : 0.f;
        float4 i0 = {inv[0], inv[1], inv[2], inv[3]};
        float4 i1 = {inv[4], inv[5], inv[6], inv[7]};
        ((float4*)&g_inv[wid * 8])[0] = i0;
        ((float4*)&g_inv[wid * 8])[1] = i1;
    }
}

// ---------------- K5: one diffusion hop (warp per node, bf16 gather) --------
__global__ void __launch_bounds__(256) k_hop(int hop)
{
    const __nv_bfloat16* finb =
        (hop == 0) ? g_f0h : ((hop & 1) ? g_hA : g_hB);
    const uint2* fin = (const uint2*)finb;   // 8 bytes = 4 bf16 per lane
    __nv_bfloat16* foutb = (hop & 1) ? g_hB : g_hA;
    const bool last = (hop == HOPS - 1);

    const int wid  = (blockIdx.x * blockDim.x + threadIdx.x) >> 5;
    const int lane = threadIdx.x & 31;
    if (wid >= NN) return;
    const int beg = g_rowptr[wid], end = g_rowptr[wid + 1];
    const int h = lane >> 2;

    const float invh = g_inv[wid * 8 + h];

    float4 acc = {0.f, 0.f, 0.f, 0.f};
    for (int pb = beg; pb < end; pb += 32) {
        int sl = (pb + lane < end) ? g_srcs[pb + lane] : 0;
        int cnt = min(32, end - pb);
        #pragma unroll 8
        for (int q = 0; q < cnt; q++) {
            int s = __shfl_sync(0xffffffffu, sl, q);
            float av = __ldg(&g_a[(pb + q) * 8 + h]);
            uint2 v = __ldg(&fin[s * 32 + lane]);
            float2 lo = __bfloat1622float2(*(__nv_bfloat162*)&v.x);
            float2 hi = __bfloat1622float2(*(__nv_bfloat162*)&v.y);
            acc.x += av * lo.x; acc.y += av * lo.y;
            acc.z += av * hi.x; acc.w += av * hi.y;
        }
    }

    const float w = (1.f - ALPHA) * invh;
    float4 f0 = ((const float4*)g_feat0)[wid * 32 + lane];
    float4 o;
    o.x = w * acc.x + ALPHA * f0.x;
    o.y = w * acc.y + ALPHA * f0.y;
    o.z = w * acc.z + ALPHA * f0.z;
    o.w = w * acc.w + ALPHA * f0.w;

    if (last) {
        ((float4*)g_fA)[wid * 32 + lane] = o;
    } else {
        __nv_bfloat162 p0 = __float22bfloat162_rn(make_float2(o.x, o.y));
        __nv_bfloat162 p1 = __float22bfloat162_rn(make_float2(o.z, o.w));
        uint2 st;
        st.x = *(unsigned*)&p0;
        st.y = *(unsigned*)&p1;
        ((uint2*)foutb)[wid * 32 + lane] = st;
    }
}

// ---------------- K6: residual + LN2 + FFN + residual (fp16 tensor core) ----
// rst in `out` gmem (block-local rows); yh half + zh half in smem.
// smem = 64*132*2 + 64*520*2 = 83456 B -> 2 blocks/SM.
__global__ void __launch_bounds__(256, 2) k_ffn(
    const float* __restrict__ g2, const float* __restrict__ be2,
    const float* __restrict__ bb1, const float* __restrict__ bb2,
    float* __restrict__ out)
{
    extern __shared__ float smem_[];
    __half* yh = (__half*)smem_;                 // 64*132 half
    __half* zh = yh + 64 * 132;                  // 64*520 half
    const int n0 = blockIdx.x * 64;
    const int tid = threadIdx.x;
    const int wid = tid >> 5, lane = tid & 31;
    const int group = lane >> 2, tig = lane & 3;

    // 1. rst = f + h -> out (scratch; final value re-added in epilogue)
    for (int i = tid; i < 64 * 128; i += 256) {
        int r = i >> 7, c = i & 127;
        int gr = n0 + r;
        if (gr < NN) out[gr * 128 + c] = g_fA[gr * 128 + c] + g_h[gr * 128 + c];
    }
    __syncthreads();

    // 2. LN2 over rst -> yh (half)
    #pragma unroll
    for (int rr = 0; rr < 8; rr++) {
        int r = wid * 8 + rr;
        const float* row = &out[(size_t)min(n0 + r, NN - 1) * 128];
        float x[4];
        float s = 0.f, s2 = 0.f;
        #pragma unroll
        for (int k = 0; k < 4; k++) {
            x[k] = row[lane + 32 * k];
            s += x[k]; s2 += x[k] * x[k];
        }
        #pragma unroll
        for (int o = 16; o; o >>= 1) {
            s  += __shfl_xor_sync(0xffffffffu, s, o);
            s2 += __shfl_xor_sync(0xffffffffu, s2, o);
        }
        float mu  = s * (1.f / 128.f);
        float inv = rsqrtf(s2 * (1.f / 128.f) - mu * mu + LNEPS);
        #pragma unroll
        for (int k = 0; k < 4; k++) {
            int c = lane + 32 * k;
            float y = (x[k] - mu) * inv * g2[c] + be2[c];
            yh[r * 132 + c] = __float2half(y);
        }
    }
    __syncthreads();

    // 3. GEMM1: z(64x512) = relu(y @ W1 + b1), fp16 k16, two 64-wide N phases
    {
        const int m0 = (wid >> 2) * 32;
        const int nwbase = (wid & 3) * 128;
        #pragma unroll
        for (int ph = 0; ph < 2; ph++) {
            const int nw = nwbase + ph * 64;
            float acc[2][8][4];
            #pragma unroll
            for (int mt = 0; mt < 2; mt++)
                #pragma unroll
                for (int nt = 0; nt < 8; nt++)
                    #pragma unroll
                    for (int q = 0; q < 4; q++) acc[mt][nt][q] = 0.f;

            #pragma unroll
            for (int ks = 0; ks < 8; ks++) {
                int k0 = ks * 16, kh = ks * 8;
                unsigned a[2][4];
                #pragma unroll
                for (int mt = 0; mt < 2; mt++) {
                    int rb = m0 + mt * 16 + group;
                    a[mt][0] = *(unsigned*)&yh[rb * 132 + k0 + 2 * tig];
                    a[mt][1] = *(unsigned*)&yh[(rb + 8) * 132 + k0 + 2 * tig];
                    a[mt][2] = *(unsigned*)&yh[rb * 132 + k0 + 2 * tig + 8];
                    a[mt][3] = *(unsigned*)&yh[(rb + 8) * 132 + k0 + 2 * tig + 8];
                }
                #pragma unroll
                for (int nt = 0; nt < 8; nt++) {
                    int c = nw + nt * 8 + group;
                    unsigned b0 = g_W1h[(kh + tig) * 512 + c];
                    unsigned b1 = g_W1h[(kh + tig + 4) * 512 + c];
                    mma_f16(acc[0][nt], a[0][0], a[0][1], a[0][2], a[0][3], b0, b1);
                    mma_f16(acc[1][nt], a[1][0], a[1][1], a[1][2], a[1][3], b0, b1);
                }
            }
            #pragma unroll
            for (int mt = 0; mt < 2; mt++)
                #pragma unroll
                for (int nt = 0; nt < 8; nt++) {
                    int r  = m0 + mt * 16 + group;
                    int cc = nw + nt * 8 + 2 * tig;
                    float v0 = fmaxf(acc[mt][nt][0] + bb1[cc], 0.f);
                    float v1 = fmaxf(acc[mt][nt][1] + bb1[cc + 1], 0.f);
                    float v2 = fmaxf(acc[mt][nt][2] + bb1[cc], 0.f);
                    float v3 = fmaxf(acc[mt][nt][3] + bb1[cc + 1], 0.f);
                    *(__half2*)&zh[r * 520 + cc]       = __floats2half2_rn(v0, v1);
                    *(__half2*)&zh[(r + 8) * 520 + cc] = __floats2half2_rn(v2, v3);
                }
        }
    }
    __syncthreads();

    // 4. GEMM2: out = z @ W2 + b2 + rst(out), fp16 k16. warp tile 16x64
    {
        const int m0 = (wid >> 1) * 16;
        const int nw = (wid & 1) * 64;
        float acc[8][4];
        #pragma unroll
        for (int nt = 0; nt < 8; nt++)
            #pragma unroll
            for (int q = 0; q < 4; q++) acc[nt][q] = 0.f;

        #pragma unroll 8
        for (int ks = 0; ks < 32; ks++) {
            int k0 = ks * 16, kh = ks * 8;
            unsigned a0 = *(unsigned*)&zh[(m0 + group) * 520 + k0 + 2 * tig];
            unsigned a1 = *(unsigned*)&zh[(m0 + group + 8) * 520 + k0 + 2 * tig];
            unsigned a2 = *(unsigned*)&zh[(m0 + group) * 520 + k0 + 2 * tig + 8];
            unsigned a3 = *(unsigned*)&zh[(m0 + group + 8) * 520 + k0 + 2 * tig + 8];
            #pragma unroll
            for (int nt = 0; nt < 8; nt++) {
                int c = nw + nt * 8 + group;
                unsigned b0 = g_W2h[(kh + tig) * 128 + c];
                unsigned b1 = g_W2h[(kh + tig + 4) * 128 + c];
                mma_f16(acc[nt], a0, a1, a2, a3, b0, b1);
            }
        }
        #pragma unroll
        for (int nt = 0; nt < 8; nt++) {
            int r  = m0 + group;
            int cc = nw + nt * 8 + 2 * tig;
            if (n0 + r < NN) {
                size_t i0 = (size_t)(n0 + r) * 128 + cc;
                out[i0]     = acc[nt][0] + bb2[cc]     + out[i0];
                out[i0 + 1] = acc[nt][1] + bb2[cc + 1] + out[i0 + 1];
            }
            if (n0 + r + 8 < NN) {
                size_t i1 = (size_t)(n0 + r + 8) * 128 + cc;
                out[i1]     = acc[nt][2] + bb2[cc]     + out[i1];
                out[i1 + 1] = acc[nt][3] + bb2[cc + 1] + out[i1 + 1];
            }
        }
    }
}

// ---------------- launch ----------------------------------------------------
extern "C" void kernel_launch(void* const* d_in, const int* in_sizes, int n_in,
                              void* d_out, int out_size)
{
    const float* ent   = (const float*)d_in[0];
    const float* rel   = (const float*)d_in[1];
    const int*   src   = (const int*)  d_in[2];
    const int*   dst   = (const int*)  d_in[3];
    const int*   etp   = (const int*)  d_in[4];
    const float* ln1g  = (const float*)d_in[5];
    const float* ln1b  = (const float*)d_in[6];
    const float* Went  = (const float*)d_in[7];
    const float* Wrel  = (const float*)d_in[8];
    const float* ah    = (const float*)d_in[9];
    const float* at    = (const float*)d_in[10];
    const float* ar    = (const float*)d_in[11];
    const float* ln2g  = (const float*)d_in[12];
    const float* ln2b  = (const float*)d_in[13];
    const float* W1    = (const float*)d_in[14];
    const float* b1    = (const float*)d_in[15];
    const float* W2    = (const float*)d_in[16];
    const float* b2    = (const float*)d_in[17];
    float* out = (float*)d_out;

    static const size_t LN1_SMEM = 64 * 132 * sizeof(float) + 64 * 132 * sizeof(__half); // 50688
    static const size_t FFN_SMEM = (64 * 132 + 64 * 520) * sizeof(__half);               // 83456
    cudaFuncSetAttribute(k_ln1_feat, cudaFuncAttributeMaxDynamicSharedMemorySize, (int)LN1_SMEM);
    cudaFuncSetAttribute(k_ffn, cudaFuncAttributeMaxDynamicSharedMemorySize, (int)FFN_SMEM);

    // 1-3: weights, deg init, histogram
    k_cvt<<<(CVT_TOTAL + 255) / 256, 256>>>(Went, W1, W2);
    k_zero<<<(NN + 255) / 256, 256>>>();
    k_hist<<<EE / 256, 256>>>(dst);

    // 4: node projection (profiled slot)
    k_ln1_feat<<<(NN + 63) / 64, 256, LN1_SMEM>>>(ent, ln1g, ln1b, ah, at);
    k_rel<<<RR, 128>>>(rel, Wrel, ar);

    // CSR build (parallel scan)
    k_scanA<<<NBLK, SCAN_B>>>();
    k_scanB<<<1, 512>>>();
    k_scanC<<<NBLK, SCAN_B>>>();
    k_scatter<<<EE / 256, 256>>>(src, dst, etp);

    // edge softmax (single pass, unnormalized + inv table)
    k_soft<<<NN / 8, 256>>>();

    // diffusion (bf16 state)
    for (int hop = 0; hop < HOPS; hop++)
        k_hop<<<NN / 8, 256>>>(hop);

    // FFN + residuals
    k_ffn<<<(NN + 63) / 64, 256, FFN_SMEM>>>(ln2g, ln2b, b1, b2, out);
}

// round 14
// speedup vs baseline: 2.3573x; 1.0296x over previous
#include <cuda_runtime.h>
#include <cuda_bf16.h>
#include <cuda_fp16.h>

#define NN   100000
#define EE   1600000
#define RR   500
#define DDIM 128
#define HH   8
#define DHH  16
#define DFFN 512
#define HOPS 5
#define ALPHA 0.15f
#define SLOPE 0.2f
#define LNEPS 1e-5f

#define SCAN_B 256
#define NBLK ((NN + SCAN_B - 1) / SCAN_B)   // 391

// ---------------- scratch (static device globals; no allocation) -------------
__device__ float g_h[NN * DDIM];        // LN1 output
__device__ float g_feat0[NN * DDIM];    // h @ W_ent (fp32 anchor)
__device__ float g_fA[NN * DDIM];       // final hop output (fp32)
__device__ __nv_bfloat16 g_f0h[NN * DDIM];  // feat0 in bf16 (hop-0 input)
__device__ __nv_bfloat16 g_hA[NN * DDIM];   // bf16 ping
__device__ __nv_bfloat16 g_hB[NN * DDIM];   // bf16 pong
__device__ float g_eh[NN * HH];
__device__ float g_et[NN * HH];
__device__ float g_er[RR * HH];
__device__ float g_a[EE * HH];          // UNnormalized exp scores, dst-sorted order
__device__ float g_inv[NN * HH];        // 1/softmax-sum per (node, head)
__device__ int   g_deg[NN];
__device__ int   g_rowptr[NN + 1];
__device__ int   g_cursor[NN];
__device__ int   g_part[512];           // scan partials
__device__ int   g_srcs[EE];            // src, sorted by dst
__device__ int   g_ets[EE];             // e_type, sorted by dst
// fp16 weights, k-pair packed: Wp[k/2][c] = {W[2k'][c], W[2k'+1][c]}
__device__ unsigned g_Wenth[(DDIM / 2) * DDIM];   // 8192
__device__ unsigned g_W1h[(DDIM / 2) * DFFN];     // 32768
__device__ unsigned g_W2h[(DFFN / 2) * DDIM];     // 32768

// ---------------- mma helper (fp16 m16n8k16, fp32 accum) ---------------------
__device__ __forceinline__ void mma_f16(float c[4],
    unsigned a0, unsigned a1, unsigned a2, unsigned a3,
    unsigned b0, unsigned b1)
{
    asm volatile(
        "mma.sync.aligned.m16n8k16.row.col.f32.f16.f16.f32 "
        "{%0,%1,%2,%3}, {%4,%5,%6,%7}, {%8,%9}, {%0,%1,%2,%3};"
        : "+f"(c[0]), "+f"(c[1]), "+f"(c[2]), "+f"(c[3])
        : "r"(a0), "r"(a1), "r"(a2), "r"(a3), "r"(b0), "r"(b1));
}

__device__ __forceinline__ unsigned packh2(float lo, float hi) {
    __half2 h = __floats2half2_rn(lo, hi);
    return *(unsigned*)&h;
}

// ---------------- K0: convert + k-pair-pack all weights to fp16 --------------
#define CVT_W0 ((DDIM / 2) * DDIM)                 // 8192
#define CVT_W1 ((DDIM / 2) * DFFN)                 // 32768
#define CVT_W2 ((DFFN / 2) * DDIM)                 // 32768
#define CVT_TOTAL (CVT_W0 + CVT_W1 + CVT_W2)       // 73728
__global__ void k_cvt(const float* __restrict__ Went,
                      const float* __restrict__ W1,
                      const float* __restrict__ W2)
{
    int i = blockIdx.x * blockDim.x + threadIdx.x;
    if (i < CVT_W0) {
        int k2 = i >> 7, c = i & 127;
        g_Wenth[i] = packh2(Went[(2 * k2) * 128 + c], Went[(2 * k2 + 1) * 128 + c]);
    } else if (i < CVT_W0 + CVT_W1) {
        int j = i - CVT_W0;
        int k2 = j >> 9, c = j & 511;
        g_W1h[j] = packh2(W1[(2 * k2) * 512 + c], W1[(2 * k2 + 1) * 512 + c]);
    } else if (i < CVT_TOTAL) {
        int j = i - CVT_W0 - CVT_W1;
        int k2 = j >> 7, c = j & 127;
        g_W2h[j] = packh2(W2[(2 * k2) * 128 + c], W2[(2 * k2 + 1) * 128 + c]);
    }
}

// ---------------- K1: LN1 (gmem-direct) + feat GEMM + eh/et ------------------
// smem: yh half 64*132 = 16896 B only -> 5 CTAs/SM (reg-limited).
__global__ void __launch_bounds__(256) k_ln1_feat(
    const float* __restrict__ ent, const float* __restrict__ g1,
    const float* __restrict__ b1,
    const float* __restrict__ ah, const float* __restrict__ at)
{
    extern __shared__ float smem_[];
    __half* yh = (__half*)smem_;              // 64*132 half LN output
    const int n0 = blockIdx.x * 64;
    const int tid = threadIdx.x;
    const int wid = tid >> 5, lane = tid & 31;
    const int group = lane >> 2, tig = lane & 3;

    // LN: each warp owns rows wid*8..wid*8+7, reads ent directly (coalesced)
    #pragma unroll
    for (int rr = 0; rr < 8; rr++) {
        int r = wid * 8 + rr;
        int gr = min(n0 + r, NN - 1);
        float x[4];
        float s = 0.f, s2 = 0.f;
        #pragma unroll
        for (int k = 0; k < 4; k++) {
            x[k] = __ldg(&ent[gr * 128 + lane + 32 * k]);
            s += x[k]; s2 += x[k] * x[k];
        }
        #pragma unroll
        for (int o = 16; o; o >>= 1) {
            s  += __shfl_xor_sync(0xffffffffu, s, o);
            s2 += __shfl_xor_sync(0xffffffffu, s2, o);
        }
        float mu  = s * (1.f / 128.f);
        float inv = rsqrtf(s2 * (1.f / 128.f) - mu * mu + LNEPS);
        #pragma unroll
        for (int k = 0; k < 4; k++) {
            int c = lane + 32 * k;
            float y = (x[k] - mu) * inv * g1[c] + b1[c];
            yh[r * 132 + c] = __float2half(y);
            if (n0 + r < NN) g_h[(n0 + r) * 128 + c] = y;
        }
    }
    __syncthreads();

    // GEMM 64x128 = y(64x128) @ Went(128x128), fp16 k16. warp tile 16x64
    const int m0 = (wid >> 1) * 16;
    const int nw = (wid & 1) * 64;
    float acc[8][4];
    {
        #pragma unroll
        for (int t = 0; t < 8; t++)
            #pragma unroll
            for (int q = 0; q < 4; q++) acc[t][q] = 0.f;

        #pragma unroll
        for (int ks = 0; ks < 8; ks++) {
            int k0 = ks * 16, kh = ks * 8;
            unsigned a0 = *(unsigned*)&yh[(m0 + group) * 132 + k0 + 2 * tig];
            unsigned a1 = *(unsigned*)&yh[(m0 + group + 8) * 132 + k0 + 2 * tig];
            unsigned a2 = *(unsigned*)&yh[(m0 + group) * 132 + k0 + 2 * tig + 8];
            unsigned a3 = *(unsigned*)&yh[(m0 + group + 8) * 132 + k0 + 2 * tig + 8];
            #pragma unroll
            for (int nt = 0; nt < 8; nt++) {
                int c = nw + nt * 8 + group;
                unsigned b0 = g_Wenth[(kh + tig) * 128 + c];
                unsigned b1 = g_Wenth[(kh + tig + 4) * 128 + c];
                mma_f16(acc[nt], a0, a1, a2, a3, b0, b1);
            }
        }
    }

    // epilogue 1: feat -> g_feat0 (fp32) + g_f0h (bf16)
    {
        const int r = m0 + group;
        #pragma unroll
        for (int nt = 0; nt < 8; nt++) {
            int cc = nw + nt * 8 + 2 * tig;
            if (n0 + r < NN) {
                g_feat0[(n0 + r) * 128 + cc]     = acc[nt][0];
                g_feat0[(n0 + r) * 128 + cc + 1] = acc[nt][1];
                *(__nv_bfloat162*)&g_f0h[(n0 + r) * 128 + cc] =
                    __float22bfloat162_rn(make_float2(acc[nt][0], acc[nt][1]));
            }
            if (n0 + r + 8 < NN) {
                g_feat0[(n0 + r + 8) * 128 + cc]     = acc[nt][2];
                g_feat0[(n0 + r + 8) * 128 + cc + 1] = acc[nt][3];
                *(__nv_bfloat162*)&g_f0h[(n0 + r + 8) * 128 + cc] =
                    __float22bfloat162_rn(make_float2(acc[nt][2], acc[nt][3]));
            }
        }
    }

    // epilogue 2: eh/et directly from fragments (tig-lane reduce)
    {
        const int r = m0 + group;
        #pragma unroll
        for (int hh = 0; hh < 4; hh++) {
            float seA = 0.f, seB = 0.f, stA = 0.f, stB = 0.f;
            #pragma unroll
            for (int j = 0; j < 2; j++) {
                int nt = 2 * hh + j;
                int cc = nw + nt * 8 + 2 * tig;
                float ah0 = __ldg(&ah[cc]),     ah1 = __ldg(&ah[cc + 1]);
                float at0 = __ldg(&at[cc]),     at1 = __ldg(&at[cc + 1]);
                seA += acc[nt][0] * ah0 + acc[nt][1] * ah1;
                seB += acc[nt][2] * ah0 + acc[nt][3] * ah1;
                stA += acc[nt][0] * at0 + acc[nt][1] * at1;
                stB += acc[nt][2] * at0 + acc[nt][3] * at1;
            }
            #pragma unroll
            for (int o = 1; o < 4; o <<= 1) {
                seA += __shfl_xor_sync(0xffffffffu, seA, o);
                seB += __shfl_xor_sync(0xffffffffu, seB, o);
                stA += __shfl_xor_sync(0xffffffffu, stA, o);
                stB += __shfl_xor_sync(0xffffffffu, stB, o);
            }
            if (tig == 0) {
                int hg = (nw >> 4) + hh;
                if (n0 + r < NN) {
                    g_eh[(n0 + r) * 8 + hg] = seA;
                    g_et[(n0 + r) * 8 + hg] = stA;
                }
                if (n0 + r + 8 < NN) {
                    g_eh[(n0 + r + 8) * 8 + hg] = seB;
                    g_et[(n0 + r + 8) * 8 + hg] = stB;
                }
            }
        }
    }
}

// ---------------- K2: er per relation ---------------------------------------
__global__ void k_rel(const float* __restrict__ rel,
                      const float* __restrict__ Wrel,
                      const float* __restrict__ ar)
{
    __shared__ float srow[128];
    const int r = blockIdx.x, k = threadIdx.x;
    srow[k] = rel[r * 128 + k];
    __syncthreads();
    float acc = 0.f;
    for (int j = 0; j < 128; j++) acc += srow[j] * Wrel[j * 128 + k];
    float v = acc * ar[k];
    #pragma unroll
    for (int o = 8; o; o >>= 1) v += __shfl_xor_sync(0xffffffffu, v, o);
    if ((k & 15) == 0) g_er[r * 8 + (k >> 4)] = v;
}

// ---------------- CSR build -------------------------------------------------
__global__ void k_zero() {
    int i = blockIdx.x * blockDim.x + threadIdx.x;
    if (i < NN) g_deg[i] = 0;
}

__global__ void k_hist(const int* __restrict__ dst) {
    int e = blockIdx.x * blockDim.x + threadIdx.x;
    if (e < EE) atomicAdd(&g_deg[dst[e]], 1);
}

__global__ void __launch_bounds__(SCAN_B) k_scanA() {
    __shared__ int red[SCAN_B / 32];
    const int t = threadIdx.x;
    const int i = blockIdx.x * SCAN_B + t;
    int v = (i < NN) ? g_deg[i] : 0;
    int s = v;
    #pragma unroll
    for (int o = 16; o; o >>= 1) s += __shfl_xor_sync(0xffffffffu, s, o);
    if ((t & 31) == 0) red[t >> 5] = s;
    __syncthreads();
    if (t < 32) {
        int x = (t < SCAN_B / 32) ? red[t] : 0;
        #pragma unroll
        for (int o = 16; o; o >>= 1) x += __shfl_xor_sync(0xffffffffu, x, o);
        if (t == 0) g_part[blockIdx.x] = x;
    }
}

__global__ void __launch_bounds__(512) k_scanB() {
    __shared__ int sp[512];
    const int t = threadIdx.x;
    int v = (t < NBLK) ? g_part[t] : 0;
    sp[t] = v;
    __syncthreads();
    for (int off = 1; off < 512; off <<= 1) {
        int x = (t >= off) ? sp[t - off] : 0;
        __syncthreads();
        sp[t] += x;
        __syncthreads();
    }
    if (t < NBLK) g_part[t] = sp[t] - v;   // exclusive
}

__global__ void __launch_bounds__(SCAN_B) k_scanC() {
    __shared__ int sp[SCAN_B];
    const int t = threadIdx.x;
    const int i = blockIdx.x * SCAN_B + t;
    const int base = g_part[blockIdx.x];
    int v = (i < NN) ? g_deg[i] : 0;
    sp[t] = v;
    __syncthreads();
    for (int off = 1; off < SCAN_B; off <<= 1) {
        int x = (t >= off) ? sp[t - off] : 0;
        __syncthreads();
        sp[t] += x;
        __syncthreads();
    }
    if (i < NN) {
        int excl = base + sp[t] - v;
        g_rowptr[i] = excl;
        g_cursor[i] = excl;
    }
    if (i == NN - 1) g_rowptr[NN] = EE;
}

__global__ void k_scatter(const int* __restrict__ src,
                          const int* __restrict__ dst,
                          const int* __restrict__ etp)
{
    int e = blockIdx.x * blockDim.x + threadIdx.x;
    if (e < EE) {
        int p = atomicAdd(&g_cursor[dst[e]], 1);
        g_srcs[p] = src[e];
        g_ets[p]  = etp[e];
    }
}

// ---------------- K4: edge softmax, SINGLE pass ------------------------------
__global__ void __launch_bounds__(256) k_soft()
{
    const int wid  = (blockIdx.x * blockDim.x + threadIdx.x) >> 5;
    const int lane = threadIdx.x & 31;
    if (wid >= NN) return;
    const int beg = g_rowptr[wid], end = g_rowptr[wid + 1];

    float etn[8];
    {
        const float4* p = (const float4*)&g_et[wid * 8];
        float4 a0 = p[0], a1 = p[1];
        etn[0]=a0.x; etn[1]=a0.y; etn[2]=a0.z; etn[3]=a0.w;
        etn[4]=a1.x; etn[5]=a1.y; etn[6]=a1.z; etn[7]=a1.w;
    }

    float sm[8];
    #pragma unroll
    for (int h = 0; h < 8; h++) sm[h] = 0.f;

    for (int p = beg + lane; p < end; p += 32) {
        int s = g_srcs[p], t = g_ets[p];
        float eh8[8], er8[8], ex[8];
        *(float4*)&eh8[0] = ((const float4*)&g_eh[s * 8])[0];
        *(float4*)&eh8[4] = ((const float4*)&g_eh[s * 8])[1];
        *(float4*)&er8[0] = ((const float4*)&g_er[t * 8])[0];
        *(float4*)&er8[4] = ((const float4*)&g_er[t * 8])[1];
        #pragma unroll
        for (int h = 0; h < 8; h++) {
            float sc = eh8[h] + etn[h] + er8[h];
            sc = sc > 0.f ? sc : SLOPE * sc;
            ex[h] = __expf(sc);
            sm[h] += ex[h];
        }
        float4 o0 = {ex[0], ex[1], ex[2], ex[3]};
        float4 o1 = {ex[4], ex[5], ex[6], ex[7]};
        ((float4*)&g_a[p * 8])[0] = o0;
        ((float4*)&g_a[p * 8])[1] = o1;
    }
    #pragma unroll
    for (int o = 16; o; o >>= 1)
        #pragma unroll
        for (int h = 0; h < 8; h++)
            sm[h] += __shfl_xor_sync(0xffffffffu, sm[h], o);

    if (lane == 0) {
        float inv[8];
        #pragma unroll
        for (int h = 0; h < 8; h++) inv[h] = (sm[h] > 0.f) ? (1.f / sm[h]) : 0.f;
        float4 i0 = {inv[0], inv[1], inv[2], inv[3]};
        float4 i1 = {inv[4], inv[5], inv[6], inv[7]};
        ((float4*)&g_inv[wid * 8])[0] = i0;
        ((float4*)&g_inv[wid * 8])[1] = i1;
    }
}

// ---------------- K5: one diffusion hop (warp per node, bf16 gather) --------
// src index via uniform L1-broadcast LDG (no shfl dependency in gather chain)
__global__ void __launch_bounds__(256) k_hop(int hop)
{
    const __nv_bfloat16* finb =
        (hop == 0) ? g_f0h : ((hop & 1) ? g_hA : g_hB);
    const uint2* fin = (const uint2*)finb;   // 8 bytes = 4 bf16 per lane
    __nv_bfloat16* foutb = (hop & 1) ? g_hB : g_hA;
    const bool last = (hop == HOPS - 1);

    const int wid  = (blockIdx.x * blockDim.x + threadIdx.x) >> 5;
    const int lane = threadIdx.x & 31;
    if (wid >= NN) return;
    const int beg = g_rowptr[wid], end = g_rowptr[wid + 1];
    const int h = lane >> 2;

    const float invh = g_inv[wid * 8 + h];

    float4 acc = {0.f, 0.f, 0.f, 0.f};
    for (int pb = beg; pb < end; pb += 32) {
        int cnt = min(32, end - pb);
        #pragma unroll 8
        for (int q = 0; q < cnt; q++) {
            int s = __ldg(&g_srcs[pb + q]);              // uniform broadcast
            float av = __ldg(&g_a[(pb + q) * 8 + h]);
            uint2 v = __ldg(&fin[s * 32 + lane]);
            float2 lo = __bfloat1622float2(*(__nv_bfloat162*)&v.x);
            float2 hi = __bfloat1622float2(*(__nv_bfloat162*)&v.y);
            acc.x += av * lo.x; acc.y += av * lo.y;
            acc.z += av * hi.x; acc.w += av * hi.y;
        }
    }

    const float w = (1.f - ALPHA) * invh;
    float4 f0 = ((const float4*)g_feat0)[wid * 32 + lane];
    float4 o;
    o.x = w * acc.x + ALPHA * f0.x;
    o.y = w * acc.y + ALPHA * f0.y;
    o.z = w * acc.z + ALPHA * f0.z;
    o.w = w * acc.w + ALPHA * f0.w;

    if (last) {
        ((float4*)g_fA)[wid * 32 + lane] = o;
    } else {
        __nv_bfloat162 p0 = __float22bfloat162_rn(make_float2(o.x, o.y));
        __nv_bfloat162 p1 = __float22bfloat162_rn(make_float2(o.z, o.w));
        uint2 st;
        st.x = *(unsigned*)&p0;
        st.y = *(unsigned*)&p1;
        ((uint2*)foutb)[wid * 32 + lane] = st;
    }
}

// ---------------- K6: residual + LN2 + FFN + residual (fp16 tensor core) ----
// rst in `out` gmem (block-local rows); yh half + zh half in smem.
// smem = 64*132*2 + 64*520*2 = 83456 B -> 2 blocks/SM.
__global__ void __launch_bounds__(256, 2) k_ffn(
    const float* __restrict__ g2, const float* __restrict__ be2,
    const float* __restrict__ bb1, const float* __restrict__ bb2,
    float* __restrict__ out)
{
    extern __shared__ float smem_[];
    __half* yh = (__half*)smem_;                 // 64*132 half
    __half* zh = yh + 64 * 132;                  // 64*520 half
    const int n0 = blockIdx.x * 64;
    const int tid = threadIdx.x;
    const int wid = tid >> 5, lane = tid & 31;
    const int group = lane >> 2, tig = lane & 3;

    // 1. rst = f + h -> out (scratch; final value re-added in epilogue)
    for (int i = tid; i < 64 * 128; i += 256) {
        int r = i >> 7, c = i & 127;
        int gr = n0 + r;
        if (gr < NN) out[gr * 128 + c] = g_fA[gr * 128 + c] + g_h[gr * 128 + c];
    }
    __syncthreads();

    // 2. LN2 over rst -> yh (half)
    #pragma unroll
    for (int rr = 0; rr < 8; rr++) {
        int r = wid * 8 + rr;
        const float* row = &out[(size_t)min(n0 + r, NN - 1) * 128];
        float x[4];
        float s = 0.f, s2 = 0.f;
        #pragma unroll
        for (int k = 0; k < 4; k++) {
            x[k] = row[lane + 32 * k];
            s += x[k]; s2 += x[k] * x[k];
        }
        #pragma unroll
        for (int o = 16; o; o >>= 1) {
            s  += __shfl_xor_sync(0xffffffffu, s, o);
            s2 += __shfl_xor_sync(0xffffffffu, s2, o);
        }
        float mu  = s * (1.f / 128.f);
        float inv = rsqrtf(s2 * (1.f / 128.f) - mu * mu + LNEPS);
        #pragma unroll
        for (int k = 0; k < 4; k++) {
            int c = lane + 32 * k;
            float y = (x[k] - mu) * inv * g2[c] + be2[c];
            yh[r * 132 + c] = __float2half(y);
        }
    }
    __syncthreads();

    // 3. GEMM1: z(64x512) = relu(y @ W1 + b1), fp16 k16, two 64-wide N phases
    {
        const int m0 = (wid >> 2) * 32;
        const int nwbase = (wid & 3) * 128;
        #pragma unroll
        for (int ph = 0; ph < 2; ph++) {
            const int nw = nwbase + ph * 64;
            float acc[2][8][4];
            #pragma unroll
            for (int mt = 0; mt < 2; mt++)
                #pragma unroll
                for (int nt = 0; nt < 8; nt++)
                    #pragma unroll
                    for (int q = 0; q < 4; q++) acc[mt][nt][q] = 0.f;

            #pragma unroll
            for (int ks = 0; ks < 8; ks++) {
                int k0 = ks * 16, kh = ks * 8;
                unsigned a[2][4];
                #pragma unroll
                for (int mt = 0; mt < 2; mt++) {
                    int rb = m0 + mt * 16 + group;
                    a[mt][0] = *(unsigned*)&yh[rb * 132 + k0 + 2 * tig];
                    a[mt][1] = *(unsigned*)&yh[(rb + 8) * 132 + k0 + 2 * tig];
                    a[mt][2] = *(unsigned*)&yh[rb * 132 + k0 + 2 * tig + 8];
                    a[mt][3] = *(unsigned*)&yh[(rb + 8) * 132 + k0 + 2 * tig + 8];
                }
                #pragma unroll
                for (int nt = 0; nt < 8; nt++) {
                    int c = nw + nt * 8 + group;
                    unsigned b0 = g_W1h[(kh + tig) * 512 + c];
                    unsigned b1 = g_W1h[(kh + tig + 4) * 512 + c];
                    mma_f16(acc[0][nt], a[0][0], a[0][1], a[0][2], a[0][3], b0, b1);
                    mma_f16(acc[1][nt], a[1][0], a[1][1], a[1][2], a[1][3], b0, b1);
                }
            }
            #pragma unroll
            for (int mt = 0; mt < 2; mt++)
                #pragma unroll
                for (int nt = 0; nt < 8; nt++) {
                    int r  = m0 + mt * 16 + group;
                    int cc = nw + nt * 8 + 2 * tig;
                    float v0 = fmaxf(acc[mt][nt][0] + bb1[cc], 0.f);
                    float v1 = fmaxf(acc[mt][nt][1] + bb1[cc + 1], 0.f);
                    float v2 = fmaxf(acc[mt][nt][2] + bb1[cc], 0.f);
                    float v3 = fmaxf(acc[mt][nt][3] + bb1[cc + 1], 0.f);
                    *(__half2*)&zh[r * 520 + cc]       = __floats2half2_rn(v0, v1);
                    *(__half2*)&zh[(r + 8) * 520 + cc] = __floats2half2_rn(v2, v3);
                }
        }
    }
    __syncthreads();

    // 4. GEMM2: out = z @ W2 + b2 + rst(out), fp16 k16. warp tile 16x64
    {
        const int m0 = (wid >> 1) * 16;
        const int nw = (wid & 1) * 64;
        float acc[8][4];
        #pragma unroll
        for (int nt = 0; nt < 8; nt++)
            #pragma unroll
            for (int q = 0; q < 4; q++) acc[nt][q] = 0.f;

        #pragma unroll 8
        for (int ks = 0; ks < 32; ks++) {
            int k0 = ks * 16, kh = ks * 8;
            unsigned a0 = *(unsigned*)&zh[(m0 + group) * 520 + k0 + 2 * tig];
            unsigned a1 = *(unsigned*)&zh[(m0 + group + 8) * 520 + k0 + 2 * tig];
            unsigned a2 = *(unsigned*)&zh[(m0 + group) * 520 + k0 + 2 * tig + 8];
            unsigned a3 = *(unsigned*)&zh[(m0 + group + 8) * 520 + k0 + 2 * tig + 8];
            #pragma unroll
            for (int nt = 0; nt < 8; nt++) {
                int c = nw + nt * 8 + group;
                unsigned b0 = g_W2h[(kh + tig) * 128 + c];
                unsigned b1 = g_W2h[(kh + tig + 4) * 128 + c];
                mma_f16(acc[nt], a0, a1, a2, a3, b0, b1);
            }
        }
        #pragma unroll
        for (int nt = 0; nt < 8; nt++) {
            int r  = m0 + group;
            int cc = nw + nt * 8 + 2 * tig;
            if (n0 + r < NN) {
                size_t i0 = (size_t)(n0 + r) * 128 + cc;
                out[i0]     = acc[nt][0] + bb2[cc]     + out[i0];
                out[i0 + 1] = acc[nt][1] + bb2[cc + 1] + out[i0 + 1];
            }
            if (n0 + r + 8 < NN) {
                size_t i1 = (size_t)(n0 + r + 8) * 128 + cc;
                out[i1]     = acc[nt][2] + bb2[cc]     + out[i1];
                out[i1 + 1] = acc[nt][3] + bb2[cc + 1] + out[i1 + 1];
            }
        }
    }
}

// ---------------- launch ----------------------------------------------------
extern "C" void kernel_launch(void* const* d_in, const int* in_sizes, int n_in,
                              void* d_out, int out_size)
{
    const float* ent   = (const float*)d_in[0];
    const float* rel   = (const float*)d_in[1];
    const int*   src   = (const int*)  d_in[2];
    const int*   dst   = (const int*)  d_in[3];
    const int*   etp   = (const int*)  d_in[4];
    const float* ln1g  = (const float*)d_in[5];
    const float* ln1b  = (const float*)d_in[6];
    const float* Went  = (const float*)d_in[7];
    const float* Wrel  = (const float*)d_in[8];
    const float* ah    = (const float*)d_in[9];
    const float* at    = (const float*)d_in[10];
    const float* ar    = (const float*)d_in[11];
    const float* ln2g  = (const float*)d_in[12];
    const float* ln2b  = (const float*)d_in[13];
    const float* W1    = (const float*)d_in[14];
    const float* b1    = (const float*)d_in[15];
    const float* W2    = (const float*)d_in[16];
    const float* b2    = (const float*)d_in[17];
    float* out = (float*)d_out;

    static const size_t LN1_SMEM = 64 * 132 * sizeof(__half);              // 16896
    static const size_t FFN_SMEM = (64 * 132 + 64 * 520) * sizeof(__half); // 83456
    cudaFuncSetAttribute(k_ln1_feat, cudaFuncAttributeMaxDynamicSharedMemorySize, (int)LN1_SMEM);
    cudaFuncSetAttribute(k_ffn, cudaFuncAttributeMaxDynamicSharedMemorySize, (int)FFN_SMEM);

    // 1-3: weights, deg init, histogram
    k_cvt<<<(CVT_TOTAL + 255) / 256, 256>>>(Went, W1, W2);
    k_zero<<<(NN + 255) / 256, 256>>>();
    k_hist<<<EE / 256, 256>>>(dst);

    // 4: node projection (profiled slot)
    k_ln1_feat<<<(NN + 63) / 64, 256, LN1_SMEM>>>(ent, ln1g, ln1b, ah, at);
    k_rel<<<RR, 128>>>(rel, Wrel, ar);

    // CSR build (parallel scan)
    k_scanA<<<NBLK, SCAN_B>>>();
    k_scanB<<<1, 512>>>();
    k_scanC<<<NBLK, SCAN_B>>>();
    k_scatter<<<EE / 256, 256>>>(src, dst, etp);

    // edge softmax (single pass, unnormalized + inv table)
    k_soft<<<NN / 8, 256>>>();

    // diffusion (bf16 state)
    for (int hop = 0; hop < HOPS; hop++)
        k_hop<<<NN / 8, 256>>>(hop);

    // FFN + residuals
    k_ffn<<<(NN + 63) / 64, 256, FFN_SMEM>>>(ln2g, ln2b, b1, b2, out);
}

// round 16
// speedup vs baseline: 2.5150x; 1.0669x over previous
#include <cuda_runtime.h>
#include <cuda_bf16.h>
#include <cuda_fp16.h>

#define NN   100000
#define EE   1600000
#define RR   500
#define DDIM 128
#define HH   8
#define DHH  16
#define DFFN 512
#define HOPS 5
#define ALPHA 0.15f
#define SLOPE 0.2f
#define LNEPS 1e-5f

#define SCAN_B 256
#define NBLK ((NN + SCAN_B - 1) / SCAN_B)   // 391

// ---------------- scratch (static device globals; no allocation) -------------
__device__ float g_h[NN * DDIM];        // LN1 output
__device__ float g_fA[NN * DDIM];       // final hop output (fp32)
__device__ __nv_bfloat16 g_f0h[NN * DDIM];  // feat0 bf16 (hop-0 input + anchor)
__device__ __nv_bfloat16 g_hA[NN * DDIM];   // bf16 ping
__device__ __nv_bfloat16 g_hB[NN * DDIM];   // bf16 pong
__device__ float g_eh[NN * HH];
__device__ float g_et[NN * HH];
__device__ float g_er[RR * HH];
__device__ __half g_a[EE * HH];         // UNnormalized exp scores (fp16)
__device__ float g_inv[NN * HH];        // 1/softmax-sum per (node, head)
__device__ int   g_deg[NN];
__device__ int   g_rowptr[NN + 1];
__device__ int   g_cursor[NN];
__device__ int   g_part[512];           // scan partials
__device__ int   g_srcs[EE];            // src, sorted by dst
__device__ int   g_ets[EE];             // e_type, sorted by dst
// fp16 weights, k-pair packed: Wp[k/2][c] = {W[2k'][c], W[2k'+1][c]}
__device__ unsigned g_Wenth[(DDIM / 2) * DDIM];   // 8192
__device__ unsigned g_W1h[(DDIM / 2) * DFFN];     // 32768
__device__ unsigned g_W2h[(DFFN / 2) * DDIM];     // 32768

// ---------------- mma helper (fp16 m16n8k16, fp32 accum) ---------------------
__device__ __forceinline__ void mma_f16(float c[4],
    unsigned a0, unsigned a1, unsigned a2, unsigned a3,
    unsigned b0, unsigned b1)
{
    asm volatile(
        "mma.sync.aligned.m16n8k16.row.col.f32.f16.f16.f32 "
        "{%0,%1,%2,%3}, {%4,%5,%6,%7}, {%8,%9}, {%0,%1,%2,%3};"
        : "+f"(c[0]), "+f"(c[1]), "+f"(c[2]), "+f"(c[3])
        : "r"(a0), "r"(a1), "r"(a2), "r"(a3), "r"(b0), "r"(b1));
}

__device__ __forceinline__ unsigned packh2(float lo, float hi) {
    __half2 h = __floats2half2_rn(lo, hi);
    return *(unsigned*)&h;
}

// ---------------- K0: convert + k-pair-pack all weights to fp16 --------------
#define CVT_W0 ((DDIM / 2) * DDIM)                 // 8192
#define CVT_W1 ((DDIM / 2) * DFFN)                 // 32768
#define CVT_W2 ((DFFN / 2) * DDIM)                 // 32768
#define CVT_TOTAL (CVT_W0 + CVT_W1 + CVT_W2)       // 73728
__global__ void k_cvt(const float* __restrict__ Went,
                      const float* __restrict__ W1,
                      const float* __restrict__ W2)
{
    int i = blockIdx.x * blockDim.x + threadIdx.x;
    if (i < CVT_W0) {
        int k2 = i >> 7, c = i & 127;
        g_Wenth[i] = packh2(Went[(2 * k2) * 128 + c], Went[(2 * k2 + 1) * 128 + c]);
    } else if (i < CVT_W0 + CVT_W1) {
        int j = i - CVT_W0;
        int k2 = j >> 9, c = j & 511;
        g_W1h[j] = packh2(W1[(2 * k2) * 512 + c], W1[(2 * k2 + 1) * 512 + c]);
    } else if (i < CVT_TOTAL) {
        int j = i - CVT_W0 - CVT_W1;
        int k2 = j >> 7, c = j & 127;
        g_W2h[j] = packh2(W2[(2 * k2) * 128 + c], W2[(2 * k2 + 1) * 128 + c]);
    }
}

// ---------------- K1: LN1 (gmem-direct) + feat GEMM + eh/et ------------------
// smem: yh half 64*132 = 16896 B. feat stored only as bf16 (g_f0h).
__global__ void __launch_bounds__(256) k_ln1_feat(
    const float* __restrict__ ent, const float* __restrict__ g1,
    const float* __restrict__ b1,
    const float* __restrict__ ah, const float* __restrict__ at)
{
    extern __shared__ float smem_[];
    __half* yh = (__half*)smem_;              // 64*132 half LN output
    const int n0 = blockIdx.x * 64;
    const int tid = threadIdx.x;
    const int wid = tid >> 5, lane = tid & 31;
    const int group = lane >> 2, tig = lane & 3;

    // LN: each warp owns rows wid*8..wid*8+7, reads ent directly (coalesced)
    #pragma unroll
    for (int rr = 0; rr < 8; rr++) {
        int r = wid * 8 + rr;
        int gr = min(n0 + r, NN - 1);
        float x[4];
        float s = 0.f, s2 = 0.f;
        #pragma unroll
        for (int k = 0; k < 4; k++) {
            x[k] = __ldg(&ent[gr * 128 + lane + 32 * k]);
            s += x[k]; s2 += x[k] * x[k];
        }
        #pragma unroll
        for (int o = 16; o; o >>= 1) {
            s  += __shfl_xor_sync(0xffffffffu, s, o);
            s2 += __shfl_xor_sync(0xffffffffu, s2, o);
        }
        float mu  = s * (1.f / 128.f);
        float inv = rsqrtf(s2 * (1.f / 128.f) - mu * mu + LNEPS);
        #pragma unroll
        for (int k = 0; k < 4; k++) {
            int c = lane + 32 * k;
            float y = (x[k] - mu) * inv * g1[c] + b1[c];
            yh[r * 132 + c] = __float2half(y);
            if (n0 + r < NN) g_h[(n0 + r) * 128 + c] = y;
        }
    }
    __syncthreads();

    // GEMM 64x128 = y(64x128) @ Went(128x128), fp16 k16. warp tile 16x64
    const int m0 = (wid >> 1) * 16;
    const int nw = (wid & 1) * 64;
    float acc[8][4];
    {
        #pragma unroll
        for (int t = 0; t < 8; t++)
            #pragma unroll
            for (int q = 0; q < 4; q++) acc[t][q] = 0.f;

        #pragma unroll
        for (int ks = 0; ks < 8; ks++) {
            int k0 = ks * 16, kh = ks * 8;
            unsigned a0 = *(unsigned*)&yh[(m0 + group) * 132 + k0 + 2 * tig];
            unsigned a1 = *(unsigned*)&yh[(m0 + group + 8) * 132 + k0 + 2 * tig];
            unsigned a2 = *(unsigned*)&yh[(m0 + group) * 132 + k0 + 2 * tig + 8];
            unsigned a3 = *(unsigned*)&yh[(m0 + group + 8) * 132 + k0 + 2 * tig + 8];
            #pragma unroll
            for (int nt = 0; nt < 8; nt++) {
                int c = nw + nt * 8 + group;
                unsigned b0 = g_Wenth[(kh + tig) * 128 + c];
                unsigned b1 = g_Wenth[(kh + tig + 4) * 128 + c];
                mma_f16(acc[nt], a0, a1, a2, a3, b0, b1);
            }
        }
    }

    // epilogue 1: feat -> g_f0h (bf16 only)
    {
        const int r = m0 + group;
        #pragma unroll
        for (int nt = 0; nt < 8; nt++) {
            int cc = nw + nt * 8 + 2 * tig;
            if (n0 + r < NN) {
                *(__nv_bfloat162*)&g_f0h[(n0 + r) * 128 + cc] =
                    __float22bfloat162_rn(make_float2(acc[nt][0], acc[nt][1]));
            }
            if (n0 + r + 8 < NN) {
                *(__nv_bfloat162*)&g_f0h[(n0 + r + 8) * 128 + cc] =
                    __float22bfloat162_rn(make_float2(acc[nt][2], acc[nt][3]));
            }
        }
    }

    // epilogue 2: eh/et directly from fragments (tig-lane reduce)
    {
        const int r = m0 + group;
        #pragma unroll
        for (int hh = 0; hh < 4; hh++) {
            float seA = 0.f, seB = 0.f, stA = 0.f, stB = 0.f;
            #pragma unroll
            for (int j = 0; j < 2; j++) {
                int nt = 2 * hh + j;
                int cc = nw + nt * 8 + 2 * tig;
                float ah0 = __ldg(&ah[cc]),     ah1 = __ldg(&ah[cc + 1]);
                float at0 = __ldg(&at[cc]),     at1 = __ldg(&at[cc + 1]);
                seA += acc[nt][0] * ah0 + acc[nt][1] * ah1;
                seB += acc[nt][2] * ah0 + acc[nt][3] * ah1;
                stA += acc[nt][0] * at0 + acc[nt][1] * at1;
                stB += acc[nt][2] * at0 + acc[nt][3] * at1;
            }
            #pragma unroll
            for (int o = 1; o < 4; o <<= 1) {
                seA += __shfl_xor_sync(0xffffffffu, seA, o);
                seB += __shfl_xor_sync(0xffffffffu, seB, o);
                stA += __shfl_xor_sync(0xffffffffu, stA, o);
                stB += __shfl_xor_sync(0xffffffffu, stB, o);
            }
            if (tig == 0) {
                int hg = (nw >> 4) + hh;
                if (n0 + r < NN) {
                    g_eh[(n0 + r) * 8 + hg] = seA;
                    g_et[(n0 + r) * 8 + hg] = stA;
                }
                if (n0 + r + 8 < NN) {
                    g_eh[(n0 + r + 8) * 8 + hg] = seB;
                    g_et[(n0 + r + 8) * 8 + hg] = stB;
                }
            }
        }
    }
}

// ---------------- K2: er per relation ---------------------------------------
__global__ void k_rel(const float* __restrict__ rel,
                      const float* __restrict__ Wrel,
                      const float* __restrict__ ar)
{
    __shared__ float srow[128];
    const int r = blockIdx.x, k = threadIdx.x;
    srow[k] = rel[r * 128 + k];
    __syncthreads();
    float acc = 0.f;
    for (int j = 0; j < 128; j++) acc += srow[j] * Wrel[j * 128 + k];
    float v = acc * ar[k];
    #pragma unroll
    for (int o = 8; o; o >>= 1) v += __shfl_xor_sync(0xffffffffu, v, o);
    if ((k & 15) == 0) g_er[r * 8 + (k >> 4)] = v;
}

// ---------------- CSR build -------------------------------------------------
__global__ void k_zero() {
    int i = blockIdx.x * blockDim.x + threadIdx.x;
    if (i < NN) g_deg[i] = 0;
}

__global__ void k_hist(const int* __restrict__ dst) {
    int e = blockIdx.x * blockDim.x + threadIdx.x;
    if (e < EE) atomicAdd(&g_deg[dst[e]], 1);
}

__global__ void __launch_bounds__(SCAN_B) k_scanA() {
    __shared__ int red[SCAN_B / 32];
    const int t = threadIdx.x;
    const int i = blockIdx.x * SCAN_B + t;
    int v = (i < NN) ? g_deg[i] : 0;
    int s = v;
    #pragma unroll
    for (int o = 16; o; o >>= 1) s += __shfl_xor_sync(0xffffffffu, s, o);
    if ((t & 31) == 0) red[t >> 5] = s;
    __syncthreads();
    if (t < 32) {
        int x = (t < SCAN_B / 32) ? red[t] : 0;
        #pragma unroll
        for (int o = 16; o; o >>= 1) x += __shfl_xor_sync(0xffffffffu, x, o);
        if (t == 0) g_part[blockIdx.x] = x;
    }
}

__global__ void __launch_bounds__(512) k_scanB() {
    __shared__ int sp[512];
    const int t = threadIdx.x;
    int v = (t < NBLK) ? g_part[t] : 0;
    sp[t] = v;
    __syncthreads();
    for (int off = 1; off < 512; off <<= 1) {
        int x = (t >= off) ? sp[t - off] : 0;
        __syncthreads();
        sp[t] += x;
        __syncthreads();
    }
    if (t < NBLK) g_part[t] = sp[t] - v;   // exclusive
}

__global__ void __launch_bounds__(SCAN_B) k_scanC() {
    __shared__ int sp[SCAN_B];
    const int t = threadIdx.x;
    const int i = blockIdx.x * SCAN_B + t;
    const int base = g_part[blockIdx.x];
    int v = (i < NN) ? g_deg[i] : 0;
    sp[t] = v;
    __syncthreads();
    for (int off = 1; off < SCAN_B; off <<= 1) {
        int x = (t >= off) ? sp[t - off] : 0;
        __syncthreads();
        sp[t] += x;
        __syncthreads();
    }
    if (i < NN) {
        int excl = base + sp[t] - v;
        g_rowptr[i] = excl;
        g_cursor[i] = excl;
    }
    if (i == NN - 1) g_rowptr[NN] = EE;
}

__global__ void k_scatter(const int* __restrict__ src,
                          const int* __restrict__ dst,
                          const int* __restrict__ etp)
{
    int e = blockIdx.x * blockDim.x + threadIdx.x;
    if (e < EE) {
        int p = atomicAdd(&g_cursor[dst[e]], 1);
        g_srcs[p] = src[e];
        g_ets[p]  = etp[e];
    }
}

// ---------------- K4: edge softmax, SINGLE pass, fp16 g_a --------------------
__global__ void __launch_bounds__(256) k_soft()
{
    const int wid  = (blockIdx.x * blockDim.x + threadIdx.x) >> 5;
    const int lane = threadIdx.x & 31;
    if (wid >= NN) return;
    const int beg = g_rowptr[wid], end = g_rowptr[wid + 1];

    float etn[8];
    {
        const float4* p = (const float4*)&g_et[wid * 8];
        float4 a0 = p[0], a1 = p[1];
        etn[0]=a0.x; etn[1]=a0.y; etn[2]=a0.z; etn[3]=a0.w;
        etn[4]=a1.x; etn[5]=a1.y; etn[6]=a1.z; etn[7]=a1.w;
    }

    float sm[8];
    #pragma unroll
    for (int h = 0; h < 8; h++) sm[h] = 0.f;

    for (int p = beg + lane; p < end; p += 32) {
        int s = g_srcs[p], t = g_ets[p];
        float eh8[8], er8[8], ex[8];
        *(float4*)&eh8[0] = ((const float4*)&g_eh[s * 8])[0];
        *(float4*)&eh8[4] = ((const float4*)&g_eh[s * 8])[1];
        *(float4*)&er8[0] = ((const float4*)&g_er[t * 8])[0];
        *(float4*)&er8[4] = ((const float4*)&g_er[t * 8])[1];
        #pragma unroll
        for (int h = 0; h < 8; h++) {
            float sc = eh8[h] + etn[h] + er8[h];
            sc = sc > 0.f ? sc : SLOPE * sc;
            ex[h] = __expf(sc);
            sm[h] += ex[h];
        }
        uint4 st;
        st.x = packh2(ex[0], ex[1]);
        st.y = packh2(ex[2], ex[3]);
        st.z = packh2(ex[4], ex[5]);
        st.w = packh2(ex[6], ex[7]);
        *(uint4*)&g_a[p * 8] = st;
    }
    #pragma unroll
    for (int o = 16; o; o >>= 1)
        #pragma unroll
        for (int h = 0; h < 8; h++)
            sm[h] += __shfl_xor_sync(0xffffffffu, sm[h], o);

    if (lane == 0) {
        float inv[8];
        #pragma unroll
        for (int h = 0; h < 8; h++) inv[h] = (sm[h] > 0.f) ? (1.f / sm[h]) : 0.f;
        float4 i0 = {inv[0], inv[1], inv[2], inv[3]};
        float4 i1 = {inv[4], inv[5], inv[6], inv[7]};
        ((float4*)&g_inv[wid * 8])[0] = i0;
        ((float4*)&g_inv[wid * 8])[1] = i1;
    }
}

// ---------------- K5: one diffusion hop (warp per node, all-bf16/fp16) ------
__global__ void __launch_bounds__(256) k_hop(int hop)
{
    const __nv_bfloat16* finb =
        (hop == 0) ? g_f0h : ((hop & 1) ? g_hA : g_hB);
    const uint2* fin = (const uint2*)finb;   // 8 bytes = 4 bf16 per lane
    __nv_bfloat16* foutb = (hop & 1) ? g_hB : g_hA;
    const bool last = (hop == HOPS - 1);

    const int wid  = (blockIdx.x * blockDim.x + threadIdx.x) >> 5;
    const int lane = threadIdx.x & 31;
    if (wid >= NN) return;
    const int beg = g_rowptr[wid], end = g_rowptr[wid + 1];
    const int h = lane >> 2;

    const float invh = g_inv[wid * 8 + h];

    float4 acc = {0.f, 0.f, 0.f, 0.f};
    for (int pb = beg; pb < end; pb += 32) {
        int cnt = min(32, end - pb);
        #pragma unroll 8
        for (int q = 0; q < cnt; q++) {
            int s = __ldg(&g_srcs[pb + q]);              // uniform broadcast
            float av = __half2float(__ldg(&g_a[(pb + q) * 8 + h]));
            uint2 v = __ldg(&fin[s * 32 + lane]);
            float2 lo = __bfloat1622float2(*(__nv_bfloat162*)&v.x);
            float2 hi = __bfloat1622float2(*(__nv_bfloat162*)&v.y);
            acc.x += av * lo.x; acc.y += av * lo.y;
            acc.z += av * hi.x; acc.w += av * hi.y;
        }
    }

    const float w = (1.f - ALPHA) * invh;
    uint2 f0v = ((const uint2*)g_f0h)[wid * 32 + lane];
    float2 f0lo = __bfloat1622float2(*(__nv_bfloat162*)&f0v.x);
    float2 f0hi = __bfloat1622float2(*(__nv_bfloat162*)&f0v.y);
    float4 o;
    o.x = w * acc.x + ALPHA * f0lo.x;
    o.y = w * acc.y + ALPHA * f0lo.y;
    o.z = w * acc.z + ALPHA * f0hi.x;
    o.w = w * acc.w + ALPHA * f0hi.y;

    if (last) {
        ((float4*)g_fA)[wid * 32 + lane] = o;
    } else {
        __nv_bfloat162 p0 = __float22bfloat162_rn(make_float2(o.x, o.y));
        __nv_bfloat162 p1 = __float22bfloat162_rn(make_float2(o.z, o.w));
        uint2 st;
        st.x = *(unsigned*)&p0;
        st.y = *(unsigned*)&p1;
        ((uint2*)foutb)[wid * 32 + lane] = st;
    }
}

// ---------------- K6: residual + LN2 + FFN + residual (fp16 tensor core) ----
// rst in `out` gmem (block-local rows); yh half + zh half in smem.
// smem = 64*132*2 + 64*520*2 = 83456 B -> 2 blocks/SM.
__global__ void __launch_bounds__(256, 2) k_ffn(
    const float* __restrict__ g2, const float* __restrict__ be2,
    const float* __restrict__ bb1, const float* __restrict__ bb2,
    float* __restrict__ out)
{
    extern __shared__ float smem_[];
    __half* yh = (__half*)smem_;                 // 64*132 half
    __half* zh = yh + 64 * 132;                  // 64*520 half
    const int n0 = blockIdx.x * 64;
    const int tid = threadIdx.x;
    const int wid = tid >> 5, lane = tid & 31;
    const int group = lane >> 2, tig = lane & 3;

    // 1. rst = f + h -> out (scratch; final value re-added in epilogue)
    for (int i = tid; i < 64 * 128; i += 256) {
        int r = i >> 7, c = i & 127;
        int gr = n0 + r;
        if (gr < NN) out[gr * 128 + c] = g_fA[gr * 128 + c] + g_h[gr * 128 + c];
    }
    __syncthreads();

    // 2. LN2 over rst -> yh (half)
    #pragma unroll
    for (int rr = 0; rr < 8; rr++) {
        int r = wid * 8 + rr;
        const float* row = &out[(size_t)min(n0 + r, NN - 1) * 128];
        float x[4];
        float s = 0.f, s2 = 0.f;
        #pragma unroll
        for (int k = 0; k < 4; k++) {
            x[k] = row[lane + 32 * k];
            s += x[k]; s2 += x[k] * x[k];
        }
        #pragma unroll
        for (int o = 16; o; o >>= 1) {
            s  += __shfl_xor_sync(0xffffffffu, s, o);
            s2 += __shfl_xor_sync(0xffffffffu, s2, o);
        }
        float mu  = s * (1.f / 128.f);
        float inv = rsqrtf(s2 * (1.f / 128.f) - mu * mu + LNEPS);
        #pragma unroll
        for (int k = 0; k < 4; k++) {
            int c = lane + 32 * k;
            float y = (x[k] - mu) * inv * g2[c] + be2[c];
            yh[r * 132 + c] = __float2half(y);
        }
    }
    __syncthreads();

    // 3. GEMM1: z(64x512) = relu(y @ W1 + b1), fp16 k16, two 64-wide N phases
    {
        const int m0 = (wid >> 2) * 32;
        const int nwbase = (wid & 3) * 128;
        #pragma unroll
        for (int ph = 0; ph < 2; ph++) {
            const int nw = nwbase + ph * 64;
            float acc[2][8][4];
            #pragma unroll
            for (int mt = 0; mt < 2; mt++)
                #pragma unroll
                for (int nt = 0; nt < 8; nt++)
                    #pragma unroll
                    for (int q = 0; q < 4; q++) acc[mt][nt][q] = 0.f;

            #pragma unroll
            for (int ks = 0; ks < 8; ks++) {
                int k0 = ks * 16, kh = ks * 8;
                unsigned a[2][4];
                #pragma unroll
                for (int mt = 0; mt < 2; mt++) {
                    int rb = m0 + mt * 16 + group;
                    a[mt][0] = *(unsigned*)&yh[rb * 132 + k0 + 2 * tig];
                    a[mt][1] = *(unsigned*)&yh[(rb + 8) * 132 + k0 + 2 * tig];
                    a[mt][2] = *(unsigned*)&yh[rb * 132 + k0 + 2 * tig + 8];
                    a[mt][3] = *(unsigned*)&yh[(rb + 8) * 132 + k0 + 2 * tig + 8];
                }
                #pragma unroll
                for (int nt = 0; nt < 8; nt++) {
                    int c = nw + nt * 8 + group;
                    unsigned b0 = g_W1h[(kh + tig) * 512 + c];
                    unsigned b1 = g_W1h[(kh + tig + 4) * 512 + c];
                    mma_f16(acc[0][nt], a[0][0], a[0][1], a[0][2], a[0][3], b0, b1);
                    mma_f16(acc[1][nt], a[1][0], a[1][1], a[1][2], a[1][3], b0, b1);
                }
            }
            #pragma unroll
            for (int mt = 0; mt < 2; mt++)
                #pragma unroll
                for (int nt = 0; nt < 8; nt++) {
                    int r  = m0 + mt * 16 + group;
                    int cc = nw + nt * 8 + 2 * tig;
                    float v0 = fmaxf(acc[mt][nt][0] + bb1[cc], 0.f);
                    float v1 = fmaxf(acc[mt][nt][1] + bb1[cc + 1], 0.f);
                    float v2 = fmaxf(acc[mt][nt][2] + bb1[cc], 0.f);
                    float v3 = fmaxf(acc[mt][nt][3] + bb1[cc + 1], 0.f);
                    *(__half2*)&zh[r * 520 + cc]       = __floats2half2_rn(v0, v1);
                    *(__half2*)&zh[(r + 8) * 520 + cc] = __floats2half2_rn(v2, v3);
                }
        }
    }
    __syncthreads();

    // 4. GEMM2: out = z @ W2 + b2 + rst(out), fp16 k16. warp tile 16x64
    {
        const int m0 = (wid >> 1) * 16;
        const int nw = (wid & 1) * 64;
        float acc[8][4];
        #pragma unroll
        for (int nt = 0; nt < 8; nt++)
            #pragma unroll
            for (int q = 0; q < 4; q++) acc[nt][q] = 0.f;

        #pragma unroll 8
        for (int ks = 0; ks < 32; ks++) {
            int k0 = ks * 16, kh = ks * 8;
            unsigned a0 = *(unsigned*)&zh[(m0 + group) * 520 + k0 + 2 * tig];
            unsigned a1 = *(unsigned*)&zh[(m0 + group + 8) * 520 + k0 + 2 * tig];
            unsigned a2 = *(unsigned*)&zh[(m0 + group) * 520 + k0 + 2 * tig + 8];
            unsigned a3 = *(unsigned*)&zh[(m0 + group + 8) * 520 + k0 + 2 * tig + 8];
            #pragma unroll
            for (int nt = 0; nt < 8; nt++) {
                int c = nw + nt * 8 + group;
                unsigned b0 = g_W2h[(kh + tig) * 128 + c];
                unsigned b1 = g_W2h[(kh + tig + 4) * 128 + c];
                mma_f16(acc[nt], a0, a1, a2, a3, b0, b1);
            }
        }
        #pragma unroll
        for (int nt = 0; nt < 8; nt++) {
            int r  = m0 + group;
            int cc = nw + nt * 8 + 2 * tig;
            if (n0 + r < NN) {
                size_t i0 = (size_t)(n0 + r) * 128 + cc;
                out[i0]     = acc[nt][0] + bb2[cc]     + out[i0];
                out[i0 + 1] = acc[nt][1] + bb2[cc + 1] + out[i0 + 1];
            }
            if (n0 + r + 8 < NN) {
                size_t i1 = (size_t)(n0 + r + 8) * 128 + cc;
                out[i1]     = acc[nt][2] + bb2[cc]     + out[i1];
                out[i1 + 1] = acc[nt][3] + bb2[cc + 1] + out[i1 + 1];
            }
        }
    }
}

// ---------------- launch ----------------------------------------------------
extern "C" void kernel_launch(void* const* d_in, const int* in_sizes, int n_in,
                              void* d_out, int out_size)
{
    const float* ent   = (const float*)d_in[0];
    const float* rel   = (const float*)d_in[1];
    const int*   src   = (const int*)  d_in[2];
    const int*   dst   = (const int*)  d_in[3];
    const int*   etp   = (const int*)  d_in[4];
    const float* ln1g  = (const float*)d_in[5];
    const float* ln1b  = (const float*)d_in[6];
    const float* Went  = (const float*)d_in[7];
    const float* Wrel  = (const float*)d_in[8];
    const float* ah    = (const float*)d_in[9];
    const float* at    = (const float*)d_in[10];
    const float* ar    = (const float*)d_in[11];
    const float* ln2g  = (const float*)d_in[12];
    const float* ln2b  = (const float*)d_in[13];
    const float* W1    = (const float*)d_in[14];
    const float* b1    = (const float*)d_in[15];
    const float* W2    = (const float*)d_in[16];
    const float* b2    = (const float*)d_in[17];
    float* out = (float*)d_out;

    static const size_t LN1_SMEM = 64 * 132 * sizeof(__half);              // 16896
    static const size_t FFN_SMEM = (64 * 132 + 64 * 520) * sizeof(__half); // 83456
    cudaFuncSetAttribute(k_ln1_feat, cudaFuncAttributeMaxDynamicSharedMemorySize, (int)LN1_SMEM);
    cudaFuncSetAttribute(k_ffn, cudaFuncAttributeMaxDynamicSharedMemorySize, (int)FFN_SMEM);

    // 1-3: weights, deg init, histogram
    k_cvt<<<(CVT_TOTAL + 255) / 256, 256>>>(Went, W1, W2);
    k_zero<<<(NN + 255) / 256, 256>>>();
    k_hist<<<EE / 256, 256>>>(dst);

    // 4: node projection (profiled slot)
    k_ln1_feat<<<(NN + 63) / 64, 256, LN1_SMEM>>>(ent, ln1g, ln1b, ah, at);
    k_rel<<<RR, 128>>>(rel, Wrel, ar);

    // CSR build (parallel scan)
    k_scanA<<<NBLK, SCAN_B>>>();
    k_scanB<<<1, 512>>>();
    k_scanC<<<NBLK, SCAN_B>>>();
    k_scatter<<<EE / 256, 256>>>(src, dst, etp);

    // edge softmax (single pass, unnormalized fp16 + inv table)
    k_soft<<<NN / 8, 256>>>();

    // diffusion (bf16 state)
    for (int hop = 0; hop < HOPS; hop++)
        k_hop<<<NN / 8, 256>>>(hop);

    // FFN + residuals
    k_ffn<<<(NN + 63) / 64, 256, FFN_SMEM>>>(ln2g, ln2b, b1, b2, out);
}